// round 10
// baseline (speedup 1.0000x reference)
#include <cuda_runtime.h>
#include <cuda_bf16.h>
#include <math.h>
#include <stdint.h>

#define N_NODES  50000
#define N_EDGES  800000
#define FEAT     90
#define H        128
#define STEPS    4
#define N_GRAPHS 100
#define M_PAD    50048   // 128 * 391
#define M_TILES  (M_PAD / 128)
#define NOUT     384

// pipeline split: tiles [0,196) | [196,391); node split at 196*128
#define TILES_A  196
#define TILES_B  (M_TILES - TILES_A)
#define SPLIT_NODE (TILES_A * 128)

typedef unsigned long long u64;

// ---------------- device scratch ----------------
__device__ float g_h  [(size_t)M_PAD * H];
__device__ float g_agg[(size_t)M_PAD * H];
__device__ float g_gx [(size_t)M_PAD * 3 * H];
__device__ float g_gh [(size_t)M_PAD * 3 * H];
__device__ float g_pool[N_GRAPHS * H];
__device__ float g_cnt [N_GRAPHS];

// CSR for gather aggregation
__device__ int g_deg[N_NODES];
__device__ int g_off[N_NODES + 1];
__device__ int g_cur[N_NODES];
__device__ int g_eid[N_EDGES];

// bf16-split, transposed weights, layout [n][k]
__device__ __nv_bfloat16 g_wcomb_h[STEPS * 3 * H * H];  // W_msg[s] @ W_ih
__device__ __nv_bfloat16 g_wcomb_l[STEPS * 3 * H * H];
__device__ __nv_bfloat16 g_whh_h[3 * H * H];
__device__ __nv_bfloat16 g_whh_l[3 * H * H];

// ---------------- PTX helpers ----------------
__device__ __forceinline__ uint32_t smem_u32(const void* p) {
    uint32_t a;
    asm("{ .reg .u64 t; cvta.to.shared.u64 t, %1; cvt.u32.u64 %0, t; }" : "=r"(a) : "l"(p));
    return a;
}

__device__ __forceinline__ void ldsm_x4(uint32_t& r0, uint32_t& r1, uint32_t& r2, uint32_t& r3,
                                        uint32_t addr) {
    asm volatile("ldmatrix.sync.aligned.m8n8.x4.shared.b16 {%0,%1,%2,%3}, [%4];"
                 : "=r"(r0), "=r"(r1), "=r"(r2), "=r"(r3) : "r"(addr));
}

__device__ __forceinline__ void mma_bf16(float* c, const uint32_t* a, const uint32_t* b) {
    asm volatile(
        "mma.sync.aligned.m16n8k16.row.col.f32.bf16.bf16.f32 "
        "{%0,%1,%2,%3}, {%4,%5,%6,%7}, {%8,%9}, {%0,%1,%2,%3};"
        : "+f"(c[0]), "+f"(c[1]), "+f"(c[2]), "+f"(c[3])
        : "r"(a[0]), "r"(a[1]), "r"(a[2]), "r"(a[3]), "r"(b[0]), "r"(b[1]));
}

// swizzled tile offset: row r (0..127), 16B-chunk c (0..15); 256B rows
__device__ __forceinline__ uint32_t swz(int r, int c) {
    return (uint32_t)r * 256 + (uint32_t)((c ^ (r & 7)) << 4);
}

__device__ __forceinline__ float sigmoidf_(float x) { return 1.f / (1.f + expf(-x)); }

// ---------------- CSR build ----------------
__global__ void hist_kernel(const int* __restrict__ ei) {
    int e = blockIdx.x * 256 + threadIdx.x;
    if (e < N_EDGES) atomicAdd(&g_deg[ei[N_EDGES + e]], 1);
}

__global__ void scan_kernel() {   // single block, 1024 threads
    const int tid = threadIdx.x, lane = tid & 31, w = tid >> 5;
    __shared__ int wsum[32];
    int total = 0;
    for (int base = 0; base < N_NODES; base += 1024) {
        int i = base + tid;
        int v = (i < N_NODES) ? g_deg[i] : 0;
        int x = v;
        #pragma unroll
        for (int d = 1; d < 32; d <<= 1) {
            int t = __shfl_up_sync(0xFFFFFFFFu, x, d);
            if (lane >= d) x += t;
        }
        if (lane == 31) wsum[w] = x;
        __syncthreads();
        if (w == 0) {
            int y = wsum[lane];
            #pragma unroll
            for (int d = 1; d < 32; d <<= 1) {
                int t = __shfl_up_sync(0xFFFFFFFFu, y, d);
                if (lane >= d) y += t;
            }
            wsum[lane] = y;
        }
        __syncthreads();
        int woff = (w == 0) ? 0 : wsum[w - 1];
        int excl = total + woff + x - v;
        if (i < N_NODES) { g_off[i] = excl; g_cur[i] = excl; }
        int chunk = wsum[31];
        __syncthreads();
        total += chunk;
    }
    if (tid == 0) g_off[N_NODES] = total;
}

__global__ void fill_kernel(const int* __restrict__ ei) {
    int e = blockIdx.x * 256 + threadIdx.x;
    if (e < N_EDGES) {
        int dst = ei[N_EDGES + e];
        int pos = atomicAdd(&g_cur[dst], 1);
        g_eid[pos] = ei[e];
    }
}

// ---------------- gather: agg[n] = sum_{e: dst=n} h[src[e]], node range --------
__global__ void gather_kernel(int node_base, int node_end) {
    const int node = node_base + ((blockIdx.x * blockDim.x + threadIdx.x) >> 5);
    if (node >= node_end) return;
    const int lane = threadIdx.x & 31;
    const int beg = g_off[node], end = g_off[node + 1];
    float4 acc = make_float4(0.f, 0.f, 0.f, 0.f);
    #pragma unroll 4
    for (int e = beg; e < end; e++) {
        int src = __ldg(&g_eid[e]);
        float4 v = *(const float4*)(g_h + (size_t)src * H + lane * 4);
        acc.x += v.x; acc.y += v.y; acc.z += v.z; acc.w += v.w;
    }
    *(float4*)(g_agg + (size_t)node * H + lane * 4) = acc;
}

// ---------------- weight prep ----------------
__global__ void prep_whh(const float* __restrict__ Whh) {
    int j = blockIdx.x * 256 + threadIdx.x;
    if (j >= 3 * H * H) return;
    int n = j >> 7, k = j & 127;
    float v = Whh[k * 384 + n];
    __nv_bfloat16 hi = __float2bfloat16(v);
    __nv_bfloat16 lo = __float2bfloat16(v - __bfloat162float(hi));
    g_whh_h[j] = hi; g_whh_l[j] = lo;
}

__global__ void prep_wcomb(const float* __restrict__ Wmsg,
                           const float* __restrict__ Wih) {
    int i = blockIdx.x * 256 + threadIdx.x;
    if (i >= STEPS * 3 * H * H) return;
    int s = i / (3 * H * H);
    int r = i % (3 * H * H);
    int k = r / 384;
    int n = r % 384;
    const float* wm = Wmsg + (s << 14) + k * H;
    float acc = 0.f;
    #pragma unroll 8
    for (int j = 0; j < H; j++) acc = fmaf(wm[j], Wih[j * 384 + n], acc);
    __nv_bfloat16 hi = __float2bfloat16(acc);
    __nv_bfloat16 lo = __float2bfloat16(acc - __bfloat162float(hi));
    size_t o = (size_t)s * 3 * H * H + (size_t)n * H + k;
    g_wcomb_h[o] = hi; g_wcomb_l[o] = lo;
}

// ---------------- mma.sync GEMM: C[rows,384] = A[rows,128] @ W[128,384] + b ----
// bf16x3: C = Ah*Bh + Ah*Bl + Al*Bh (fp32 accum). 512 thr, warp tile m32 x n32.
// tile_base: row-tile offset (for split launches).
#define SM_A_H 0
#define SM_A_L 32768
#define SM_B_H 65536
#define SM_B_L 98304
#define SM_BIAS 131072
#define GEMM_SMEM (131072 + 1536)

__global__ void __launch_bounds__(512, 1) gemm_mma(
        const float* __restrict__ A,
        const __nv_bfloat16* __restrict__ Bh, const __nv_bfloat16* __restrict__ Bl,
        const float* __restrict__ bias, float* __restrict__ C, int tile_base) {
    extern __shared__ char smem[];
    const uint32_t sbase = smem_u32(smem);
    const int tid = threadIdx.x;
    const int wid = tid >> 5;
    const int lane = tid & 31;
    const int m0 = (tile_base + blockIdx.x) * 128;

    // ---- load A tile (128x128 fp32), split to bf16 hi/lo, swizzled store ----
    {
        const float* Ab = A + (size_t)m0 * 128;
        #pragma unroll
        for (int it = 0; it < 8; it++) {
            int idx = it * 512 + tid;          // 0..4095
            int row = idx >> 5;
            int q = idx & 31;                  // float4 index; k0 = q*4
            float4 v = *(const float4*)(Ab + row * 128 + q * 4);
            __nv_bfloat16 h0 = __float2bfloat16(v.x);
            __nv_bfloat16 h1 = __float2bfloat16(v.y);
            __nv_bfloat16 h2 = __float2bfloat16(v.z);
            __nv_bfloat16 h3 = __float2bfloat16(v.w);
            __nv_bfloat16 l0 = __float2bfloat16(v.x - __bfloat162float(h0));
            __nv_bfloat16 l1 = __float2bfloat16(v.y - __bfloat162float(h1));
            __nv_bfloat16 l2 = __float2bfloat16(v.z - __bfloat162float(h2));
            __nv_bfloat16 l3 = __float2bfloat16(v.w - __bfloat162float(h3));
            uint32_t off = swz(row, q >> 1) + (q & 1) * 8;
            uint2 hw, lw;
            hw.x = (uint32_t)__bfloat16_as_ushort(h0) | ((uint32_t)__bfloat16_as_ushort(h1) << 16);
            hw.y = (uint32_t)__bfloat16_as_ushort(h2) | ((uint32_t)__bfloat16_as_ushort(h3) << 16);
            lw.x = (uint32_t)__bfloat16_as_ushort(l0) | ((uint32_t)__bfloat16_as_ushort(l1) << 16);
            lw.y = (uint32_t)__bfloat16_as_ushort(l2) | ((uint32_t)__bfloat16_as_ushort(l3) << 16);
            *(uint2*)(smem + SM_A_H + off) = hw;
            *(uint2*)(smem + SM_A_L + off) = lw;
        }
    }
    // ---- bias -> smem ----
    for (int i = tid; i < NOUT; i += 512)
        *(float*)(smem + SM_BIAS + i * 4) = bias[i];

    const int wm = (wid & 3) * 32;          // warp row offset
    const int wn = (wid >> 2) * 32;         // warp col offset within tile

    #pragma unroll
    for (int nt = 0; nt < 3; nt++) {
        __syncthreads();
        // ---- load B sub-tile 128n x 128k hi+lo, swizzled ----
        {
            const __nv_bfloat16* bh = Bh + (size_t)nt * 128 * 128;
            const __nv_bfloat16* bl = Bl + (size_t)nt * 128 * 128;
            #pragma unroll
            for (int it = 0; it < 4; it++) {
                int idx = it * 512 + tid;       // 0..2047
                int row = idx >> 4;
                int c = idx & 15;
                uint32_t off = swz(row, c);
                *(uint4*)(smem + SM_B_H + off) = *(const uint4*)(bh + row * 128 + c * 8);
                *(uint4*)(smem + SM_B_L + off) = *(const uint4*)(bl + row * 128 + c * 8);
            }
        }
        __syncthreads();

        // ---- compute: 8 k-steps, warp tile m32 x n32 ----
        float acc[2][4][4];
        #pragma unroll
        for (int mi = 0; mi < 2; mi++)
            #pragma unroll
            for (int ni = 0; ni < 4; ni++)
                #pragma unroll
                for (int j = 0; j < 4; j++) acc[mi][ni][j] = 0.f;

        #pragma unroll
        for (int ks = 0; ks < 8; ks++) {
            const int c0 = ks * 2;
            uint32_t ah[2][4], al[2][4], bh[4][2], bl[4][2];
            {
                int arow = (lane & 15);
                int ac = c0 + (lane >> 4);
                #pragma unroll
                for (int mi = 0; mi < 2; mi++) {
                    uint32_t o = swz(wm + mi * 16 + arow, ac);
                    ldsm_x4(ah[mi][0], ah[mi][1], ah[mi][2], ah[mi][3], sbase + SM_A_H + o);
                    ldsm_x4(al[mi][0], al[mi][1], al[mi][2], al[mi][3], sbase + SM_A_L + o);
                }
            }
            {
                int brow = ((lane >> 4) << 3) + (lane & 7);
                int bc = c0 + ((lane >> 3) & 1);
                #pragma unroll
                for (int nj = 0; nj < 2; nj++) {
                    uint32_t o = swz(wn + nj * 16 + brow, bc);
                    uint32_t t0, t1, t2, t3;
                    ldsm_x4(t0, t1, t2, t3, sbase + SM_B_H + o);
                    bh[nj * 2][0] = t0; bh[nj * 2][1] = t1;
                    bh[nj * 2 + 1][0] = t2; bh[nj * 2 + 1][1] = t3;
                    ldsm_x4(t0, t1, t2, t3, sbase + SM_B_L + o);
                    bl[nj * 2][0] = t0; bl[nj * 2][1] = t1;
                    bl[nj * 2 + 1][0] = t2; bl[nj * 2 + 1][1] = t3;
                }
            }
            #pragma unroll
            for (int mi = 0; mi < 2; mi++)
                #pragma unroll
                for (int ni = 0; ni < 4; ni++) {
                    mma_bf16(acc[mi][ni], ah[mi], bh[ni]);
                    mma_bf16(acc[mi][ni], ah[mi], bl[ni]);
                    mma_bf16(acc[mi][ni], al[mi], bh[ni]);
                }
        }

        // ---- epilogue ----
        {
            const int r0 = m0 + wm + (lane >> 2);
            const int cb = nt * 128 + wn + (lane & 3) * 2;
            #pragma unroll
            for (int mi = 0; mi < 2; mi++) {
                #pragma unroll
                for (int ni = 0; ni < 4; ni++) {
                    int col = cb + ni * 8;
                    float2 bb = *(const float2*)(smem + SM_BIAS + col * 4);
                    float* c0p = C + (size_t)(r0 + mi * 16) * NOUT + col;
                    float* c1p = C + (size_t)(r0 + mi * 16 + 8) * NOUT + col;
                    *(float2*)c0p = make_float2(acc[mi][ni][0] + bb.x, acc[mi][ni][1] + bb.y);
                    *(float2*)c1p = make_float2(acc[mi][ni][2] + bb.x, acc[mi][ni][3] + bb.y);
                }
            }
        }
    }
}

// ---------------- embedding: h = relu(x @ W_emb), K=90 ----------------
__global__ void embed_kernel(const float* __restrict__ x,
                             const float* __restrict__ Wemb) {
    extern __shared__ float sm[];
    float* Ws = sm;               // FEAT*H
    float* xs = sm + FEAT * H;    // 32*FEAT
    const int tid = threadIdx.x;
    for (int i = tid; i < FEAT * H; i += 128) Ws[i] = Wemb[i];
    const int n0 = blockIdx.x * 32;
    for (int i = tid; i < 32 * FEAT; i += 128) {
        int r = i / FEAT, cc = i - r * FEAT;
        int n = n0 + r;
        xs[i] = (n < N_NODES) ? x[(size_t)n * FEAT + cc] : 0.f;
    }
    __syncthreads();
    const int c = tid;
    for (int r = 0; r < 32; r++) {
        float acc = 0.f;
        const float* xr = xs + r * FEAT;
        #pragma unroll 6
        for (int k = 0; k < FEAT; k++) acc = fmaf(xr[k], Ws[k * H + c], acc);
        g_h[(size_t)(n0 + r) * H + c] = fmaxf(acc, 0.f);
    }
}

// ---------------- GRU elementwise (float4 vectorized) ------------------------
__global__ void gru_kernel() {
    const int v = blockIdx.x * blockDim.x + threadIdx.x;  // vec4 index, < M_PAD*32
    const int node = v >> 5;
    const int c4 = (v & 31) * 4;
    const size_t gb = (size_t)node * 384 + c4;
    const size_t hb = (size_t)node * 128 + c4;
    float4 xr = *(const float4*)&g_gx[gb];
    float4 xz = *(const float4*)&g_gx[gb + 128];
    float4 xn = *(const float4*)&g_gx[gb + 256];
    float4 hr = *(const float4*)&g_gh[gb];
    float4 hz = *(const float4*)&g_gh[gb + 128];
    float4 hn = *(const float4*)&g_gh[gb + 256];
    float4 hv = *(const float4*)&g_h[hb];
    float4 o;
    {
        float r = sigmoidf_(xr.x + hr.x), z = sigmoidf_(xz.x + hz.x);
        float nn = tanhf(xn.x + r * hn.x);
        o.x = (1.f - z) * nn + z * hv.x;
    }
    {
        float r = sigmoidf_(xr.y + hr.y), z = sigmoidf_(xz.y + hz.y);
        float nn = tanhf(xn.y + r * hn.y);
        o.y = (1.f - z) * nn + z * hv.y;
    }
    {
        float r = sigmoidf_(xr.z + hr.z), z = sigmoidf_(xz.z + hz.z);
        float nn = tanhf(xn.z + r * hn.z);
        o.z = (1.f - z) * nn + z * hv.z;
    }
    {
        float r = sigmoidf_(xr.w + hr.w), z = sigmoidf_(xz.w + hz.w);
        float nn = tanhf(xn.w + r * hn.w);
        o.w = (1.f - z) * nn + z * hv.w;
    }
    *(float4*)&g_h[hb] = o;
}

// ---------------- pooling: sum relu(h) per graph (batch sorted) --------------
__global__ void pool_kernel(const int* __restrict__ batch) {
    __shared__ int bs[256];
    const int tid = threadIdx.x;        // 128 threads, one column each
    const int n0 = blockIdx.x * 256;
    const int cnt = min(256, N_NODES - n0);
    for (int i = tid; i < cnt; i += 128) bs[i] = batch[n0 + i];
    __syncthreads();
    const int c = tid;
    float sum = 0.f;
    int cur = bs[0];
    int run = 0;
    for (int i = 0; i < cnt; i++) {
        int b = bs[i];
        if (b != cur) {
            atomicAdd(&g_pool[cur * H + c], sum);
            if (c == 0) atomicAdd(&g_cnt[cur], (float)run);
            sum = 0.f; run = 0; cur = b;
        }
        sum += fmaxf(g_h[(size_t)(n0 + i) * H + c], 0.f);
        run++;
    }
    atomicAdd(&g_pool[cur * H + c], sum);
    if (c == 0) atomicAdd(&g_cnt[cur], (float)run);
}

// ---------------- head: mean -> Linear+ReLU -> Linear -> softplus ------------
__global__ void head_kernel(const float* __restrict__ W1, const float* __restrict__ b1,
                            const float* __restrict__ W2, const float* __restrict__ b2,
                            float* __restrict__ out) {
    __shared__ float ps[H];
    __shared__ float hs[H];
    const int g = blockIdx.x, c = threadIdx.x;
    float cnt = fmaxf(g_cnt[g], 1.f);
    ps[c] = g_pool[g * H + c] / cnt;
    __syncthreads();
    float acc = b1[c];
    #pragma unroll 8
    for (int k = 0; k < H; k++) acc = fmaf(ps[k], W1[k * H + c], acc);
    hs[c] = fmaxf(acc, 0.f) * W2[c];
    __syncthreads();
    for (int s = 64; s > 0; s >>= 1) {
        if (c < s) hs[c] += hs[c + s];
        __syncthreads();
    }
    if (c == 0) {
        float xv = hs[0] + b2[0];
        out[g] = (xv > 0.f) ? (xv + log1pf(expf(-xv))) : log1pf(expf(xv));
    }
}

// ---------------- launch ------------------------------------------------------
extern "C" void kernel_launch(void* const* d_in, const int* in_sizes, int n_in,
                              void* d_out, int out_size) {
    const float* x     = (const float*)d_in[0];
    const int*   ei    = (const int*)d_in[1];
    const int*   batch = (const int*)d_in[2];
    const float* W_emb = (const float*)d_in[3];
    const float* W_msg = (const float*)d_in[4];
    const float* W_ih  = (const float*)d_in[5];
    const float* W_hh  = (const float*)d_in[6];
    const float* b_ih  = (const float*)d_in[7];
    const float* b_hh  = (const float*)d_in[8];
    const float* W1    = (const float*)d_in[9];
    const float* b1    = (const float*)d_in[10];
    const float* W2    = (const float*)d_in[11];
    const float* b2    = (const float*)d_in[12];
    float* out = (float*)d_out;

    float *h_p, *agg_p, *gx_p, *gh_p, *pool_p, *cnt_p;
    int* deg_p;
    cudaGetSymbolAddress((void**)&h_p,   g_h);
    cudaGetSymbolAddress((void**)&agg_p, g_agg);
    cudaGetSymbolAddress((void**)&gx_p,  g_gx);
    cudaGetSymbolAddress((void**)&gh_p,  g_gh);
    cudaGetSymbolAddress((void**)&pool_p, g_pool);
    cudaGetSymbolAddress((void**)&cnt_p,  g_cnt);
    cudaGetSymbolAddress((void**)&deg_p,  g_deg);

    __nv_bfloat16 *wcomb_h, *wcomb_l, *whh_h, *whh_l;
    cudaGetSymbolAddress((void**)&wcomb_h, g_wcomb_h);
    cudaGetSymbolAddress((void**)&wcomb_l, g_wcomb_l);
    cudaGetSymbolAddress((void**)&whh_h,   g_whh_h);
    cudaGetSymbolAddress((void**)&whh_l,   g_whh_l);

    const int embed_smem = (FEAT * H + 32 * FEAT) * 4;  // 57600 B
    cudaFuncSetAttribute(embed_kernel,
                         cudaFuncAttributeMaxDynamicSharedMemorySize, embed_smem);
    cudaFuncSetAttribute(gemm_mma,
                         cudaFuncAttributeMaxDynamicSharedMemorySize, GEMM_SMEM);

    // side streams + events for capture-safe fork/join
    cudaStream_t s2, s3;
    cudaStreamCreateWithFlags(&s2, cudaStreamNonBlocking);
    cudaStreamCreateWithFlags(&s3, cudaStreamNonBlocking);
    cudaEvent_t evF, evJ, evA, evB;
    cudaEventCreateWithFlags(&evF, cudaEventDisableTiming);
    cudaEventCreateWithFlags(&evJ, cudaEventDisableTiming);
    cudaEventCreateWithFlags(&evA, cudaEventDisableTiming);
    cudaEventCreateWithFlags(&evB, cudaEventDisableTiming);

    // ---- setup phase: CSR build (stream 0)  ||  weight prep + embed (s2) ----
    cudaEventRecord(evF, 0);
    cudaStreamWaitEvent(s2, evF, 0);
    prep_whh<<<(3 * H * H + 255) / 256, 256, 0, s2>>>(W_hh);
    prep_wcomb<<<(STEPS * 3 * H * H + 255) / 256, 256, 0, s2>>>(W_msg, W_ih);
    embed_kernel<<<M_PAD / 32, 128, embed_smem, s2>>>(x, W_emb);
    cudaEventRecord(evJ, s2);

    cudaMemsetAsync(deg_p, 0, N_NODES * sizeof(int));
    hist_kernel<<<(N_EDGES + 255) / 256, 256>>>(ei);
    scan_kernel<<<1, 1024>>>();
    fill_kernel<<<(N_EDGES + 255) / 256, 256>>>(ei);
    cudaStreamWaitEvent(0, evJ, 0);

    // ---- steps ----
    // s0: gatherA -> gxA -> [wait evB] gxB -> [wait evJ] gru
    // s2: [wait evF] gh (full)
    // s3: [wait evA] gatherB
    const int gridA = (SPLIT_NODE * 32) / 256;                       // 3136
    const int gridB = ((N_NODES - SPLIT_NODE) * 32 + 255) / 256;     // 3114
    for (int s = 0; s < STEPS; s++) {
        cudaEventRecord(evF, 0);
        cudaStreamWaitEvent(s2, evF, 0);
        gemm_mma<<<M_TILES, 512, GEMM_SMEM, s2>>>(h_p, whh_h, whh_l, b_hh, gh_p, 0);
        cudaEventRecord(evJ, s2);

        gather_kernel<<<gridA, 256>>>(0, SPLIT_NODE);
        cudaEventRecord(evA, 0);
        cudaStreamWaitEvent(s3, evA, 0);
        gather_kernel<<<gridB, 256, 0, s3>>>(SPLIT_NODE, N_NODES);
        cudaEventRecord(evB, s3);

        gemm_mma<<<TILES_A, 512, GEMM_SMEM>>>(
            agg_p, wcomb_h + (size_t)s * 3 * H * H, wcomb_l + (size_t)s * 3 * H * H,
            b_ih, gx_p, 0);
        cudaStreamWaitEvent(0, evB, 0);
        gemm_mma<<<TILES_B, 512, GEMM_SMEM>>>(
            agg_p, wcomb_h + (size_t)s * 3 * H * H, wcomb_l + (size_t)s * 3 * H * H,
            b_ih, gx_p, TILES_A);

        cudaStreamWaitEvent(0, evJ, 0);
        gru_kernel<<<(M_PAD * 32) / 256, 256>>>();
    }

    // ---- pooling + head ----
    cudaMemsetAsync(pool_p, 0, N_GRAPHS * H * sizeof(float));
    cudaMemsetAsync(cnt_p, 0, N_GRAPHS * sizeof(float));
    pool_kernel<<<(N_NODES + 255) / 256, 128>>>(batch);
    head_kernel<<<N_GRAPHS, H>>>(W1, b1, W2, b2, out);

    cudaEventDestroy(evF);
    cudaEventDestroy(evJ);
    cudaEventDestroy(evA);
    cudaEventDestroy(evB);
    cudaStreamDestroy(s2);
    cudaStreamDestroy(s3);
}

// round 11
// speedup vs baseline: 1.0385x; 1.0385x over previous
#include <cuda_runtime.h>
#include <cuda_bf16.h>
#include <math.h>
#include <stdint.h>

#define N_NODES  50000
#define N_EDGES  800000
#define FEAT     90
#define H        128
#define STEPS    4
#define N_GRAPHS 100
#define M_PAD    50048   // 128 * 391 (also divisible by 64 -> 782 tiles)
#define GEMM_TILES (M_PAD / 64)
#define NOUT     384

typedef unsigned long long u64;

// ---------------- device scratch ----------------
__device__ float g_h  [(size_t)M_PAD * H];
__device__ float g_agg[(size_t)M_PAD * H];
__device__ float g_gx [(size_t)M_PAD * 3 * H];
__device__ float g_gh [(size_t)M_PAD * 3 * H];
__device__ float g_pool[N_GRAPHS * H];
__device__ float g_cnt [N_GRAPHS];

// CSR for gather aggregation
__device__ int g_deg[N_NODES];
__device__ int g_off[N_NODES + 1];
__device__ int g_cur[N_NODES];
__device__ int g_eid[N_EDGES];

// bf16-split, transposed weights, layout [n][k]
__device__ __nv_bfloat16 g_wcomb_h[STEPS * 3 * H * H];  // W_msg[s] @ W_ih
__device__ __nv_bfloat16 g_wcomb_l[STEPS * 3 * H * H];
__device__ __nv_bfloat16 g_whh_h[3 * H * H];
__device__ __nv_bfloat16 g_whh_l[3 * H * H];

// ---------------- PTX helpers ----------------
__device__ __forceinline__ uint32_t smem_u32(const void* p) {
    uint32_t a;
    asm("{ .reg .u64 t; cvta.to.shared.u64 t, %1; cvt.u32.u64 %0, t; }" : "=r"(a) : "l"(p));
    return a;
}

__device__ __forceinline__ void ldsm_x4(uint32_t& r0, uint32_t& r1, uint32_t& r2, uint32_t& r3,
                                        uint32_t addr) {
    asm volatile("ldmatrix.sync.aligned.m8n8.x4.shared.b16 {%0,%1,%2,%3}, [%4];"
                 : "=r"(r0), "=r"(r1), "=r"(r2), "=r"(r3) : "r"(addr));
}

__device__ __forceinline__ void mma_bf16(float* c, const uint32_t* a, const uint32_t* b) {
    asm volatile(
        "mma.sync.aligned.m16n8k16.row.col.f32.bf16.bf16.f32 "
        "{%0,%1,%2,%3}, {%4,%5,%6,%7}, {%8,%9}, {%0,%1,%2,%3};"
        : "+f"(c[0]), "+f"(c[1]), "+f"(c[2]), "+f"(c[3])
        : "r"(a[0]), "r"(a[1]), "r"(a[2]), "r"(a[3]), "r"(b[0]), "r"(b[1]));
}

// swizzled tile offset: row r, 16B-chunk c (0..15); 256B rows
__device__ __forceinline__ uint32_t swz(int r, int c) {
    return (uint32_t)r * 256 + (uint32_t)((c ^ (r & 7)) << 4);
}

__device__ __forceinline__ float sigmoidf_(float x) { return 1.f / (1.f + expf(-x)); }

// ---------------- CSR build ----------------
__global__ void hist_kernel(const int* __restrict__ ei) {
    int e = blockIdx.x * 256 + threadIdx.x;
    if (e < N_EDGES) atomicAdd(&g_deg[ei[N_EDGES + e]], 1);
}

__global__ void scan_kernel() {   // single block, 1024 threads
    const int tid = threadIdx.x, lane = tid & 31, w = tid >> 5;
    __shared__ int wsum[32];
    int total = 0;
    for (int base = 0; base < N_NODES; base += 1024) {
        int i = base + tid;
        int v = (i < N_NODES) ? g_deg[i] : 0;
        int x = v;
        #pragma unroll
        for (int d = 1; d < 32; d <<= 1) {
            int t = __shfl_up_sync(0xFFFFFFFFu, x, d);
            if (lane >= d) x += t;
        }
        if (lane == 31) wsum[w] = x;
        __syncthreads();
        if (w == 0) {
            int y = wsum[lane];
            #pragma unroll
            for (int d = 1; d < 32; d <<= 1) {
                int t = __shfl_up_sync(0xFFFFFFFFu, y, d);
                if (lane >= d) y += t;
            }
            wsum[lane] = y;
        }
        __syncthreads();
        int woff = (w == 0) ? 0 : wsum[w - 1];
        int excl = total + woff + x - v;
        if (i < N_NODES) { g_off[i] = excl; g_cur[i] = excl; }
        int chunk = wsum[31];
        __syncthreads();
        total += chunk;
    }
    if (tid == 0) g_off[N_NODES] = total;
}

__global__ void fill_kernel(const int* __restrict__ ei) {
    int e = blockIdx.x * 256 + threadIdx.x;
    if (e < N_EDGES) {
        int dst = ei[N_EDGES + e];
        int pos = atomicAdd(&g_cur[dst], 1);
        g_eid[pos] = ei[e];
    }
}

// ---------------- gather: agg[n] = sum_{e: dst=n} h[src[e]] ----------------
__global__ void gather_kernel() {
    const int node = (blockIdx.x * blockDim.x + threadIdx.x) >> 5;
    if (node >= N_NODES) return;
    const int lane = threadIdx.x & 31;
    const int beg = g_off[node], end = g_off[node + 1];
    float4 acc = make_float4(0.f, 0.f, 0.f, 0.f);
    #pragma unroll 4
    for (int e = beg; e < end; e++) {
        int src = __ldg(&g_eid[e]);
        float4 v = *(const float4*)(g_h + (size_t)src * H + lane * 4);
        acc.x += v.x; acc.y += v.y; acc.z += v.z; acc.w += v.w;
    }
    *(float4*)(g_agg + (size_t)node * H + lane * 4) = acc;
}

// ---------------- weight prep ----------------
__global__ void prep_whh(const float* __restrict__ Whh) {
    int j = blockIdx.x * 256 + threadIdx.x;
    if (j >= 3 * H * H) return;
    int n = j >> 7, k = j & 127;
    float v = Whh[k * 384 + n];
    __nv_bfloat16 hi = __float2bfloat16(v);
    __nv_bfloat16 lo = __float2bfloat16(v - __bfloat162float(hi));
    g_whh_h[j] = hi; g_whh_l[j] = lo;
}

__global__ void prep_wcomb(const float* __restrict__ Wmsg,
                           const float* __restrict__ Wih) {
    int i = blockIdx.x * 256 + threadIdx.x;
    if (i >= STEPS * 3 * H * H) return;
    int s = i / (3 * H * H);
    int r = i % (3 * H * H);
    int k = r / 384;
    int n = r % 384;
    const float* wm = Wmsg + (s << 14) + k * H;
    float acc = 0.f;
    #pragma unroll 8
    for (int j = 0; j < H; j++) acc = fmaf(wm[j], Wih[j * 384 + n], acc);
    __nv_bfloat16 hi = __float2bfloat16(acc);
    __nv_bfloat16 lo = __float2bfloat16(acc - __bfloat162float(hi));
    size_t o = (size_t)s * 3 * H * H + (size_t)n * H + k;
    g_wcomb_h[o] = hi; g_wcomb_l[o] = lo;
}

// ---------------- mma.sync GEMM: C[M_PAD,384] = A[M_PAD,128] @ W[128,384] + b --
// bf16x3: C = Ah*Bh + Ah*Bl + Al*Bh (fp32 accum).
// BM=64, 256 threads (8 warps, 2x4 grid, warp tile m32 x n32), 97.5KB smem
// -> 2 CTAs/SM so one CTA's B-tile loads overlap the other's mma bursts.
#define SM_A_H 0
#define SM_A_L 16384
#define SM_B_H 32768
#define SM_B_L 65536
#define SM_BIAS 98304
#define GEMM_SMEM (98304 + 1536)

__global__ void __launch_bounds__(256, 2) gemm_mma(
        const float* __restrict__ A,
        const __nv_bfloat16* __restrict__ Bh, const __nv_bfloat16* __restrict__ Bl,
        const float* __restrict__ bias, float* __restrict__ C) {
    extern __shared__ char smem[];
    const uint32_t sbase = smem_u32(smem);
    const int tid = threadIdx.x;
    const int wid = tid >> 5;
    const int lane = tid & 31;
    const int m0 = blockIdx.x * 64;

    // ---- load A tile (64x128 fp32), split to bf16 hi/lo, swizzled store ----
    {
        const float* Ab = A + (size_t)m0 * 128;
        #pragma unroll
        for (int it = 0; it < 8; it++) {
            int idx = it * 256 + tid;          // 0..2047
            int row = idx >> 5;                // 0..63
            int q = idx & 31;                  // float4 index; k0 = q*4
            float4 v = *(const float4*)(Ab + row * 128 + q * 4);
            __nv_bfloat16 h0 = __float2bfloat16(v.x);
            __nv_bfloat16 h1 = __float2bfloat16(v.y);
            __nv_bfloat16 h2 = __float2bfloat16(v.z);
            __nv_bfloat16 h3 = __float2bfloat16(v.w);
            __nv_bfloat16 l0 = __float2bfloat16(v.x - __bfloat162float(h0));
            __nv_bfloat16 l1 = __float2bfloat16(v.y - __bfloat162float(h1));
            __nv_bfloat16 l2 = __float2bfloat16(v.z - __bfloat162float(h2));
            __nv_bfloat16 l3 = __float2bfloat16(v.w - __bfloat162float(h3));
            uint32_t off = swz(row, q >> 1) + (q & 1) * 8;
            uint2 hw, lw;
            hw.x = (uint32_t)__bfloat16_as_ushort(h0) | ((uint32_t)__bfloat16_as_ushort(h1) << 16);
            hw.y = (uint32_t)__bfloat16_as_ushort(h2) | ((uint32_t)__bfloat16_as_ushort(h3) << 16);
            lw.x = (uint32_t)__bfloat16_as_ushort(l0) | ((uint32_t)__bfloat16_as_ushort(l1) << 16);
            lw.y = (uint32_t)__bfloat16_as_ushort(l2) | ((uint32_t)__bfloat16_as_ushort(l3) << 16);
            *(uint2*)(smem + SM_A_H + off) = hw;
            *(uint2*)(smem + SM_A_L + off) = lw;
        }
    }
    // ---- bias -> smem ----
    for (int i = tid; i < NOUT; i += 256)
        *(float*)(smem + SM_BIAS + i * 4) = bias[i];

    const int wm = (wid & 1) * 32;          // warp row offset (2 rows of warps)
    const int wn = (wid >> 1) * 32;         // warp col offset (4 cols of warps)

    #pragma unroll
    for (int nt = 0; nt < 3; nt++) {
        __syncthreads();   // A/bias ready (nt=0) / previous compute done (nt>0)
        // ---- load B sub-tile 128n x 128k hi+lo, swizzled ----
        {
            const __nv_bfloat16* bh = Bh + (size_t)nt * 128 * 128;
            const __nv_bfloat16* bl = Bl + (size_t)nt * 128 * 128;
            #pragma unroll
            for (int it = 0; it < 8; it++) {
                int idx = it * 256 + tid;       // 0..2047
                int row = idx >> 4;             // 0..127
                int c = idx & 15;
                uint32_t off = swz(row, c);
                *(uint4*)(smem + SM_B_H + off) = *(const uint4*)(bh + row * 128 + c * 8);
                *(uint4*)(smem + SM_B_L + off) = *(const uint4*)(bl + row * 128 + c * 8);
            }
        }
        __syncthreads();

        // ---- compute: 8 k-steps, warp tile m32 x n32 ----
        float acc[2][4][4];
        #pragma unroll
        for (int mi = 0; mi < 2; mi++)
            #pragma unroll
            for (int ni = 0; ni < 4; ni++)
                #pragma unroll
                for (int j = 0; j < 4; j++) acc[mi][ni][j] = 0.f;

        #pragma unroll
        for (int ks = 0; ks < 8; ks++) {
            const int c0 = ks * 2;
            uint32_t ah[2][4], al[2][4], bh[4][2], bl[4][2];
            {
                int arow = (lane & 15);
                int ac = c0 + (lane >> 4);
                #pragma unroll
                for (int mi = 0; mi < 2; mi++) {
                    uint32_t o = swz(wm + mi * 16 + arow, ac);
                    ldsm_x4(ah[mi][0], ah[mi][1], ah[mi][2], ah[mi][3], sbase + SM_A_H + o);
                    ldsm_x4(al[mi][0], al[mi][1], al[mi][2], al[mi][3], sbase + SM_A_L + o);
                }
            }
            {
                int brow = ((lane >> 4) << 3) + (lane & 7);
                int bc = c0 + ((lane >> 3) & 1);
                #pragma unroll
                for (int nj = 0; nj < 2; nj++) {
                    uint32_t o = swz(wn + nj * 16 + brow, bc);
                    uint32_t t0, t1, t2, t3;
                    ldsm_x4(t0, t1, t2, t3, sbase + SM_B_H + o);
                    bh[nj * 2][0] = t0; bh[nj * 2][1] = t1;
                    bh[nj * 2 + 1][0] = t2; bh[nj * 2 + 1][1] = t3;
                    ldsm_x4(t0, t1, t2, t3, sbase + SM_B_L + o);
                    bl[nj * 2][0] = t0; bl[nj * 2][1] = t1;
                    bl[nj * 2 + 1][0] = t2; bl[nj * 2 + 1][1] = t3;
                }
            }
            #pragma unroll
            for (int mi = 0; mi < 2; mi++)
                #pragma unroll
                for (int ni = 0; ni < 4; ni++) {
                    mma_bf16(acc[mi][ni], ah[mi], bh[ni]);
                    mma_bf16(acc[mi][ni], ah[mi], bl[ni]);
                    mma_bf16(acc[mi][ni], al[mi], bh[ni]);
                }
        }

        // ---- epilogue ----
        {
            const int r0 = m0 + wm + (lane >> 2);
            const int cb = nt * 128 + wn + (lane & 3) * 2;
            #pragma unroll
            for (int mi = 0; mi < 2; mi++) {
                #pragma unroll
                for (int ni = 0; ni < 4; ni++) {
                    int col = cb + ni * 8;
                    float2 bb = *(const float2*)(smem + SM_BIAS + col * 4);
                    float* c0p = C + (size_t)(r0 + mi * 16) * NOUT + col;
                    float* c1p = C + (size_t)(r0 + mi * 16 + 8) * NOUT + col;
                    *(float2*)c0p = make_float2(acc[mi][ni][0] + bb.x, acc[mi][ni][1] + bb.y);
                    *(float2*)c1p = make_float2(acc[mi][ni][2] + bb.x, acc[mi][ni][3] + bb.y);
                }
            }
        }
    }
}

// ---------------- embedding: h = relu(x @ W_emb), K=90 ----------------
__global__ void embed_kernel(const float* __restrict__ x,
                             const float* __restrict__ Wemb) {
    extern __shared__ float sm[];
    float* Ws = sm;               // FEAT*H
    float* xs = sm + FEAT * H;    // 32*FEAT
    const int tid = threadIdx.x;
    for (int i = tid; i < FEAT * H; i += 128) Ws[i] = Wemb[i];
    const int n0 = blockIdx.x * 32;
    for (int i = tid; i < 32 * FEAT; i += 128) {
        int r = i / FEAT, cc = i - r * FEAT;
        int n = n0 + r;
        xs[i] = (n < N_NODES) ? x[(size_t)n * FEAT + cc] : 0.f;
    }
    __syncthreads();
    const int c = tid;
    for (int r = 0; r < 32; r++) {
        float acc = 0.f;
        const float* xr = xs + r * FEAT;
        #pragma unroll 6
        for (int k = 0; k < FEAT; k++) acc = fmaf(xr[k], Ws[k * H + c], acc);
        g_h[(size_t)(n0 + r) * H + c] = fmaxf(acc, 0.f);
    }
}

// ---------------- GRU elementwise (float4 vectorized) ------------------------
__global__ void gru_kernel() {
    const int v = blockIdx.x * blockDim.x + threadIdx.x;  // vec4 index, < M_PAD*32
    const int node = v >> 5;
    const int c4 = (v & 31) * 4;
    const size_t gb = (size_t)node * 384 + c4;
    const size_t hb = (size_t)node * 128 + c4;
    float4 xr = *(const float4*)&g_gx[gb];
    float4 xz = *(const float4*)&g_gx[gb + 128];
    float4 xn = *(const float4*)&g_gx[gb + 256];
    float4 hr = *(const float4*)&g_gh[gb];
    float4 hz = *(const float4*)&g_gh[gb + 128];
    float4 hn = *(const float4*)&g_gh[gb + 256];
    float4 hv = *(const float4*)&g_h[hb];
    float4 o;
    {
        float r = sigmoidf_(xr.x + hr.x), z = sigmoidf_(xz.x + hz.x);
        float nn = tanhf(xn.x + r * hn.x);
        o.x = (1.f - z) * nn + z * hv.x;
    }
    {
        float r = sigmoidf_(xr.y + hr.y), z = sigmoidf_(xz.y + hz.y);
        float nn = tanhf(xn.y + r * hn.y);
        o.y = (1.f - z) * nn + z * hv.y;
    }
    {
        float r = sigmoidf_(xr.z + hr.z), z = sigmoidf_(xz.z + hz.z);
        float nn = tanhf(xn.z + r * hn.z);
        o.z = (1.f - z) * nn + z * hv.z;
    }
    {
        float r = sigmoidf_(xr.w + hr.w), z = sigmoidf_(xz.w + hz.w);
        float nn = tanhf(xn.w + r * hn.w);
        o.w = (1.f - z) * nn + z * hv.w;
    }
    *(float4*)&g_h[hb] = o;
}

// ---------------- pooling: sum relu(h) per graph (batch sorted) --------------
__global__ void pool_kernel(const int* __restrict__ batch) {
    __shared__ int bs[256];
    const int tid = threadIdx.x;        // 128 threads, one column each
    const int n0 = blockIdx.x * 256;
    const int cnt = min(256, N_NODES - n0);
    for (int i = tid; i < cnt; i += 128) bs[i] = batch[n0 + i];
    __syncthreads();
    const int c = tid;
    float sum = 0.f;
    int cur = bs[0];
    int run = 0;
    for (int i = 0; i < cnt; i++) {
        int b = bs[i];
        if (b != cur) {
            atomicAdd(&g_pool[cur * H + c], sum);
            if (c == 0) atomicAdd(&g_cnt[cur], (float)run);
            sum = 0.f; run = 0; cur = b;
        }
        sum += fmaxf(g_h[(size_t)(n0 + i) * H + c], 0.f);
        run++;
    }
    atomicAdd(&g_pool[cur * H + c], sum);
    if (c == 0) atomicAdd(&g_cnt[cur], (float)run);
}

// ---------------- head: mean -> Linear+ReLU -> Linear -> softplus ------------
__global__ void head_kernel(const float* __restrict__ W1, const float* __restrict__ b1,
                            const float* __restrict__ W2, const float* __restrict__ b2,
                            float* __restrict__ out) {
    __shared__ float ps[H];
    __shared__ float hs[H];
    const int g = blockIdx.x, c = threadIdx.x;
    float cnt = fmaxf(g_cnt[g], 1.f);
    ps[c] = g_pool[g * H + c] / cnt;
    __syncthreads();
    float acc = b1[c];
    #pragma unroll 8
    for (int k = 0; k < H; k++) acc = fmaf(ps[k], W1[k * H + c], acc);
    hs[c] = fmaxf(acc, 0.f) * W2[c];
    __syncthreads();
    for (int s = 64; s > 0; s >>= 1) {
        if (c < s) hs[c] += hs[c + s];
        __syncthreads();
    }
    if (c == 0) {
        float xv = hs[0] + b2[0];
        out[g] = (xv > 0.f) ? (xv + log1pf(expf(-xv))) : log1pf(expf(xv));
    }
}

// ---------------- launch ------------------------------------------------------
extern "C" void kernel_launch(void* const* d_in, const int* in_sizes, int n_in,
                              void* d_out, int out_size) {
    const float* x     = (const float*)d_in[0];
    const int*   ei    = (const int*)d_in[1];
    const int*   batch = (const int*)d_in[2];
    const float* W_emb = (const float*)d_in[3];
    const float* W_msg = (const float*)d_in[4];
    const float* W_ih  = (const float*)d_in[5];
    const float* W_hh  = (const float*)d_in[6];
    const float* b_ih  = (const float*)d_in[7];
    const float* b_hh  = (const float*)d_in[8];
    const float* W1    = (const float*)d_in[9];
    const float* b1    = (const float*)d_in[10];
    const float* W2    = (const float*)d_in[11];
    const float* b2    = (const float*)d_in[12];
    float* out = (float*)d_out;

    float *h_p, *agg_p, *gx_p, *gh_p, *pool_p, *cnt_p;
    int* deg_p;
    cudaGetSymbolAddress((void**)&h_p,   g_h);
    cudaGetSymbolAddress((void**)&agg_p, g_agg);
    cudaGetSymbolAddress((void**)&gx_p,  g_gx);
    cudaGetSymbolAddress((void**)&gh_p,  g_gh);
    cudaGetSymbolAddress((void**)&pool_p, g_pool);
    cudaGetSymbolAddress((void**)&cnt_p,  g_cnt);
    cudaGetSymbolAddress((void**)&deg_p,  g_deg);

    __nv_bfloat16 *wcomb_h, *wcomb_l, *whh_h, *whh_l;
    cudaGetSymbolAddress((void**)&wcomb_h, g_wcomb_h);
    cudaGetSymbolAddress((void**)&wcomb_l, g_wcomb_l);
    cudaGetSymbolAddress((void**)&whh_h,   g_whh_h);
    cudaGetSymbolAddress((void**)&whh_l,   g_whh_l);

    const int embed_smem = (FEAT * H + 32 * FEAT) * 4;  // 57600 B
    cudaFuncSetAttribute(embed_kernel,
                         cudaFuncAttributeMaxDynamicSharedMemorySize, embed_smem);
    cudaFuncSetAttribute(gemm_mma,
                         cudaFuncAttributeMaxDynamicSharedMemorySize, GEMM_SMEM);

    // side stream + events for capture-safe fork/join
    cudaStream_t s2;
    cudaStreamCreateWithFlags(&s2, cudaStreamNonBlocking);
    cudaEvent_t evF, evJ;
    cudaEventCreateWithFlags(&evF, cudaEventDisableTiming);
    cudaEventCreateWithFlags(&evJ, cudaEventDisableTiming);

    // ---- setup phase: CSR build (stream 0)  ||  weight prep + embed (s2) ----
    cudaEventRecord(evF, 0);
    cudaStreamWaitEvent(s2, evF, 0);
    prep_whh<<<(3 * H * H + 255) / 256, 256, 0, s2>>>(W_hh);
    prep_wcomb<<<(STEPS * 3 * H * H + 255) / 256, 256, 0, s2>>>(W_msg, W_ih);
    embed_kernel<<<M_PAD / 32, 128, embed_smem, s2>>>(x, W_emb);
    cudaEventRecord(evJ, s2);

    cudaMemsetAsync(deg_p, 0, N_NODES * sizeof(int));
    hist_kernel<<<(N_EDGES + 255) / 256, 256>>>(ei);
    scan_kernel<<<1, 1024>>>();
    fill_kernel<<<(N_EDGES + 255) / 256, 256>>>(ei);
    cudaStreamWaitEvent(0, evJ, 0);

    // ---- steps: gather (0) ∥ gh-GEMM (s2); join; gx-GEMM; gru (R7 schedule) ----
    for (int s = 0; s < STEPS; s++) {
        cudaEventRecord(evF, 0);
        cudaStreamWaitEvent(s2, evF, 0);
        gemm_mma<<<GEMM_TILES, 256, GEMM_SMEM, s2>>>(h_p, whh_h, whh_l, b_hh, gh_p);
        cudaEventRecord(evJ, s2);

        gather_kernel<<<(N_NODES * 32) / 256, 256>>>();
        gemm_mma<<<GEMM_TILES, 256, GEMM_SMEM>>>(
            agg_p, wcomb_h + (size_t)s * 3 * H * H, wcomb_l + (size_t)s * 3 * H * H,
            b_ih, gx_p);

        cudaStreamWaitEvent(0, evJ, 0);
        gru_kernel<<<(M_PAD * 32) / 256, 256>>>();
    }

    // ---- pooling + head ----
    cudaMemsetAsync(pool_p, 0, N_GRAPHS * H * sizeof(float));
    cudaMemsetAsync(cnt_p, 0, N_GRAPHS * sizeof(float));
    pool_kernel<<<(N_NODES + 255) / 256, 128>>>(batch);
    head_kernel<<<N_GRAPHS, H>>>(W1, b1, W2, b2, out);

    cudaEventDestroy(evF);
    cudaEventDestroy(evJ);
    cudaStreamDestroy(s2);
}

// round 12
// speedup vs baseline: 1.0813x; 1.0412x over previous
#include <cuda_runtime.h>
#include <cuda_bf16.h>
#include <math.h>
#include <stdint.h>

#define N_NODES  50000
#define N_EDGES  800000
#define FEAT     90
#define H        128
#define STEPS    4
#define N_GRAPHS 100
#define M_PAD    50048   // 128 * 391
#define M_TILES  (M_PAD / 128)
#define NOUT     384
#define SCAN_BLOCKS 196  // 196 * 256 = 50176 >= N_NODES

typedef unsigned long long u64;

// ---------------- device scratch ----------------
__device__ float g_h  [(size_t)M_PAD * H];
__device__ float g_agg[(size_t)M_PAD * H];
__device__ float g_gx [(size_t)M_PAD * 3 * H];
__device__ float g_gh [(size_t)M_PAD * 3 * H];
__device__ float g_pool[N_GRAPHS * H];
__device__ float g_cnt [N_GRAPHS];

// CSR for gather aggregation
__device__ int g_deg[N_NODES];
__device__ int g_off[N_NODES + 1];
__device__ int g_cur[N_NODES];
__device__ int g_eid[N_EDGES];
__device__ int g_bsum[SCAN_BLOCKS];

// bf16-split, transposed weights, layout [n][k]
__device__ __nv_bfloat16 g_wcomb_h[STEPS * 3 * H * H];  // W_msg[s] @ W_ih
__device__ __nv_bfloat16 g_wcomb_l[STEPS * 3 * H * H];
__device__ __nv_bfloat16 g_whh_h[3 * H * H];
__device__ __nv_bfloat16 g_whh_l[3 * H * H];

// ---------------- PTX helpers ----------------
__device__ __forceinline__ uint32_t smem_u32(const void* p) {
    uint32_t a;
    asm("{ .reg .u64 t; cvta.to.shared.u64 t, %1; cvt.u32.u64 %0, t; }" : "=r"(a) : "l"(p));
    return a;
}

__device__ __forceinline__ void ldsm_x4(uint32_t& r0, uint32_t& r1, uint32_t& r2, uint32_t& r3,
                                        uint32_t addr) {
    asm volatile("ldmatrix.sync.aligned.m8n8.x4.shared.b16 {%0,%1,%2,%3}, [%4];"
                 : "=r"(r0), "=r"(r1), "=r"(r2), "=r"(r3) : "r"(addr));
}

__device__ __forceinline__ void mma_bf16(float* c, const uint32_t* a, const uint32_t* b) {
    asm volatile(
        "mma.sync.aligned.m16n8k16.row.col.f32.bf16.bf16.f32 "
        "{%0,%1,%2,%3}, {%4,%5,%6,%7}, {%8,%9}, {%0,%1,%2,%3};"
        : "+f"(c[0]), "+f"(c[1]), "+f"(c[2]), "+f"(c[3])
        : "r"(a[0]), "r"(a[1]), "r"(a[2]), "r"(a[3]), "r"(b[0]), "r"(b[1]));
}

// swizzled tile offset: row r (0..127), 16B-chunk c (0..15); 256B rows
__device__ __forceinline__ uint32_t swz(int r, int c) {
    return (uint32_t)r * 256 + (uint32_t)((c ^ (r & 7)) << 4);
}

__device__ __forceinline__ float sigmoidf_(float x) { return 1.f / (1.f + expf(-x)); }

// ---------------- CSR build ----------------
__global__ void hist_kernel(const int* __restrict__ ei) {
    int e = blockIdx.x * 256 + threadIdx.x;
    if (e < N_EDGES) atomicAdd(&g_deg[ei[N_EDGES + e]], 1);
}

// pass 1: per-block exclusive scan of deg; write local prefix + block sum
__global__ void scan_local() {
    __shared__ int wsum[8];
    const int tid = threadIdx.x, lane = tid & 31, w = tid >> 5;
    const int i = blockIdx.x * 256 + tid;
    int v = (i < N_NODES) ? g_deg[i] : 0;
    int x = v;
    #pragma unroll
    for (int d = 1; d < 32; d <<= 1) {
        int t = __shfl_up_sync(0xFFFFFFFFu, x, d);
        if (lane >= d) x += t;
    }
    if (lane == 31) wsum[w] = x;
    __syncthreads();
    if (w == 0 && lane < 8) {
        int y = wsum[lane];
        #pragma unroll
        for (int d = 1; d < 8; d <<= 1) {
            int t = __shfl_up_sync(0xFFu, y, d);
            if (lane >= d) y += t;
        }
        wsum[lane] = y;
    }
    __syncthreads();
    int woff = (w == 0) ? 0 : wsum[w - 1];
    if (i < N_NODES) g_off[i] = woff + x - v;       // local exclusive prefix
    if (tid == 255) g_bsum[blockIdx.x] = woff + x;  // block total
}

// pass 2: one block scans the 196 block sums (exclusive, in place)
__global__ void scan_bsum() {
    __shared__ int ws[8];
    const int tid = threadIdx.x, lane = tid & 31, w = tid >> 5;
    int v = (tid < SCAN_BLOCKS) ? g_bsum[tid] : 0;
    int x = v;
    #pragma unroll
    for (int d = 1; d < 32; d <<= 1) {
        int t = __shfl_up_sync(0xFFFFFFFFu, x, d);
        if (lane >= d) x += t;
    }
    if (lane == 31) ws[w] = x;
    __syncthreads();
    if (w == 0 && lane < 8) {
        int y = ws[lane];
        #pragma unroll
        for (int d = 1; d < 8; d <<= 1) {
            int t = __shfl_up_sync(0xFFu, y, d);
            if (lane >= d) y += t;
        }
        ws[lane] = y;
    }
    __syncthreads();
    int woff = (w == 0) ? 0 : ws[w - 1];
    if (tid < SCAN_BLOCKS) g_bsum[tid] = woff + x - v;   // exclusive
    if (tid == 0) g_off[N_NODES] = N_EDGES;
}

// pass 3: add block offsets, init cursor
__global__ void scan_add() {
    const int i = blockIdx.x * 256 + threadIdx.x;
    if (i >= N_NODES) return;
    int o = g_off[i] + g_bsum[blockIdx.x];
    g_off[i] = o;
    g_cur[i] = o;
}

__global__ void fill_kernel(const int* __restrict__ ei) {
    int e = blockIdx.x * 256 + threadIdx.x;
    if (e < N_EDGES) {
        int dst = ei[N_EDGES + e];
        int pos = atomicAdd(&g_cur[dst], 1);
        g_eid[pos] = ei[e];
    }
}

// ---------------- gather: agg[n] = sum_{e: dst=n} h[src[e]] ----------------
__global__ void gather_kernel() {
    const int node = (blockIdx.x * blockDim.x + threadIdx.x) >> 5;
    if (node >= N_NODES) return;
    const int lane = threadIdx.x & 31;
    const int beg = g_off[node], end = g_off[node + 1];
    float4 acc = make_float4(0.f, 0.f, 0.f, 0.f);
    #pragma unroll 4
    for (int e = beg; e < end; e++) {
        int src = __ldg(&g_eid[e]);
        float4 v = *(const float4*)(g_h + (size_t)src * H + lane * 4);
        acc.x += v.x; acc.y += v.y; acc.z += v.z; acc.w += v.w;
    }
    *(float4*)(g_agg + (size_t)node * H + lane * 4) = acc;
}

// ---------------- weight prep ----------------
__global__ void prep_whh(const float* __restrict__ Whh) {
    int j = blockIdx.x * 256 + threadIdx.x;
    if (j >= 3 * H * H) return;
    int n = j >> 7, k = j & 127;
    float v = Whh[k * 384 + n];
    __nv_bfloat16 hi = __float2bfloat16(v);
    __nv_bfloat16 lo = __float2bfloat16(v - __bfloat162float(hi));
    g_whh_h[j] = hi; g_whh_l[j] = lo;
}

__global__ void prep_wcomb(const float* __restrict__ Wmsg,
                           const float* __restrict__ Wih) {
    int i = blockIdx.x * 256 + threadIdx.x;
    if (i >= STEPS * 3 * H * H) return;
    int s = i / (3 * H * H);
    int r = i % (3 * H * H);
    int k = r / 384;
    int n = r % 384;
    const float* wm = Wmsg + (s << 14) + k * H;
    float acc = 0.f;
    #pragma unroll 8
    for (int j = 0; j < H; j++) acc = fmaf(wm[j], Wih[j * 384 + n], acc);
    __nv_bfloat16 hi = __float2bfloat16(acc);
    __nv_bfloat16 lo = __float2bfloat16(acc - __bfloat162float(hi));
    size_t o = (size_t)s * 3 * H * H + (size_t)n * H + k;
    g_wcomb_h[o] = hi; g_wcomb_l[o] = lo;
}

// ---------------- mma.sync GEMM: C[M_PAD,384] = A[M_PAD,128] @ W[128,384] + b --
// bf16x3: C = Ah*Bh + Ah*Bl + Al*Bh (fp32 accum). 512 thr, warp tile m32 x n32.
// (R7-proven configuration: BM=128, 1 CTA/SM, synchronous B loads.)
#define SM_A_H 0
#define SM_A_L 32768
#define SM_B_H 65536
#define SM_B_L 98304
#define SM_BIAS 131072
#define GEMM_SMEM (131072 + 1536)

__global__ void __launch_bounds__(512, 1) gemm_mma(
        const float* __restrict__ A,
        const __nv_bfloat16* __restrict__ Bh, const __nv_bfloat16* __restrict__ Bl,
        const float* __restrict__ bias, float* __restrict__ C) {
    extern __shared__ char smem[];
    const uint32_t sbase = smem_u32(smem);
    const int tid = threadIdx.x;
    const int wid = tid >> 5;
    const int lane = tid & 31;
    const int m0 = blockIdx.x * 128;

    // ---- load A tile (128x128 fp32), split to bf16 hi/lo, swizzled store ----
    {
        const float* Ab = A + (size_t)m0 * 128;
        #pragma unroll
        for (int it = 0; it < 8; it++) {
            int idx = it * 512 + tid;          // 0..4095
            int row = idx >> 5;
            int q = idx & 31;                  // float4 index; k0 = q*4
            float4 v = *(const float4*)(Ab + row * 128 + q * 4);
            __nv_bfloat16 h0 = __float2bfloat16(v.x);
            __nv_bfloat16 h1 = __float2bfloat16(v.y);
            __nv_bfloat16 h2 = __float2bfloat16(v.z);
            __nv_bfloat16 h3 = __float2bfloat16(v.w);
            __nv_bfloat16 l0 = __float2bfloat16(v.x - __bfloat162float(h0));
            __nv_bfloat16 l1 = __float2bfloat16(v.y - __bfloat162float(h1));
            __nv_bfloat16 l2 = __float2bfloat16(v.z - __bfloat162float(h2));
            __nv_bfloat16 l3 = __float2bfloat16(v.w - __bfloat162float(h3));
            uint32_t off = swz(row, q >> 1) + (q & 1) * 8;
            uint2 hw, lw;
            hw.x = (uint32_t)__bfloat16_as_ushort(h0) | ((uint32_t)__bfloat16_as_ushort(h1) << 16);
            hw.y = (uint32_t)__bfloat16_as_ushort(h2) | ((uint32_t)__bfloat16_as_ushort(h3) << 16);
            lw.x = (uint32_t)__bfloat16_as_ushort(l0) | ((uint32_t)__bfloat16_as_ushort(l1) << 16);
            lw.y = (uint32_t)__bfloat16_as_ushort(l2) | ((uint32_t)__bfloat16_as_ushort(l3) << 16);
            *(uint2*)(smem + SM_A_H + off) = hw;
            *(uint2*)(smem + SM_A_L + off) = lw;
        }
    }
    // ---- bias -> smem ----
    for (int i = tid; i < NOUT; i += 512)
        *(float*)(smem + SM_BIAS + i * 4) = bias[i];

    const int wm = (wid & 3) * 32;          // warp row offset
    const int wn = (wid >> 2) * 32;         // warp col offset within tile

    #pragma unroll
    for (int nt = 0; nt < 3; nt++) {
        __syncthreads();
        // ---- load B sub-tile 128n x 128k hi+lo, swizzled ----
        {
            const __nv_bfloat16* bh = Bh + (size_t)nt * 128 * 128;
            const __nv_bfloat16* bl = Bl + (size_t)nt * 128 * 128;
            #pragma unroll
            for (int it = 0; it < 4; it++) {
                int idx = it * 512 + tid;       // 0..2047
                int row = idx >> 4;
                int c = idx & 15;
                uint32_t off = swz(row, c);
                *(uint4*)(smem + SM_B_H + off) = *(const uint4*)(bh + row * 128 + c * 8);
                *(uint4*)(smem + SM_B_L + off) = *(const uint4*)(bl + row * 128 + c * 8);
            }
        }
        __syncthreads();

        // ---- compute: 8 k-steps, warp tile m32 x n32 ----
        float acc[2][4][4];
        #pragma unroll
        for (int mi = 0; mi < 2; mi++)
            #pragma unroll
            for (int ni = 0; ni < 4; ni++)
                #pragma unroll
                for (int j = 0; j < 4; j++) acc[mi][ni][j] = 0.f;

        #pragma unroll
        for (int ks = 0; ks < 8; ks++) {
            const int c0 = ks * 2;
            uint32_t ah[2][4], al[2][4], bh[4][2], bl[4][2];
            {
                int arow = (lane & 15);
                int ac = c0 + (lane >> 4);
                #pragma unroll
                for (int mi = 0; mi < 2; mi++) {
                    uint32_t o = swz(wm + mi * 16 + arow, ac);
                    ldsm_x4(ah[mi][0], ah[mi][1], ah[mi][2], ah[mi][3], sbase + SM_A_H + o);
                    ldsm_x4(al[mi][0], al[mi][1], al[mi][2], al[mi][3], sbase + SM_A_L + o);
                }
            }
            {
                int brow = ((lane >> 4) << 3) + (lane & 7);
                int bc = c0 + ((lane >> 3) & 1);
                #pragma unroll
                for (int nj = 0; nj < 2; nj++) {
                    uint32_t o = swz(wn + nj * 16 + brow, bc);
                    uint32_t t0, t1, t2, t3;
                    ldsm_x4(t0, t1, t2, t3, sbase + SM_B_H + o);
                    bh[nj * 2][0] = t0; bh[nj * 2][1] = t1;
                    bh[nj * 2 + 1][0] = t2; bh[nj * 2 + 1][1] = t3;
                    ldsm_x4(t0, t1, t2, t3, sbase + SM_B_L + o);
                    bl[nj * 2][0] = t0; bl[nj * 2][1] = t1;
                    bl[nj * 2 + 1][0] = t2; bl[nj * 2 + 1][1] = t3;
                }
            }
            #pragma unroll
            for (int mi = 0; mi < 2; mi++)
                #pragma unroll
                for (int ni = 0; ni < 4; ni++) {
                    mma_bf16(acc[mi][ni], ah[mi], bh[ni]);
                    mma_bf16(acc[mi][ni], ah[mi], bl[ni]);
                    mma_bf16(acc[mi][ni], al[mi], bh[ni]);
                }
        }

        // ---- epilogue ----
        {
            const int r0 = m0 + wm + (lane >> 2);
            const int cb = nt * 128 + wn + (lane & 3) * 2;
            #pragma unroll
            for (int mi = 0; mi < 2; mi++) {
                #pragma unroll
                for (int ni = 0; ni < 4; ni++) {
                    int col = cb + ni * 8;
                    float2 bb = *(const float2*)(smem + SM_BIAS + col * 4);
                    float* c0p = C + (size_t)(r0 + mi * 16) * NOUT + col;
                    float* c1p = C + (size_t)(r0 + mi * 16 + 8) * NOUT + col;
                    *(float2*)c0p = make_float2(acc[mi][ni][0] + bb.x, acc[mi][ni][1] + bb.y);
                    *(float2*)c1p = make_float2(acc[mi][ni][2] + bb.x, acc[mi][ni][3] + bb.y);
                }
            }
        }
    }
}

// ---------------- embedding: h = relu(x @ W_emb), K=90 ----------------
__global__ void embed_kernel(const float* __restrict__ x,
                             const float* __restrict__ Wemb) {
    extern __shared__ float sm[];
    float* Ws = sm;               // FEAT*H
    float* xs = sm + FEAT * H;    // 32*FEAT
    const int tid = threadIdx.x;
    for (int i = tid; i < FEAT * H; i += 128) Ws[i] = Wemb[i];
    const int n0 = blockIdx.x * 32;
    for (int i = tid; i < 32 * FEAT; i += 128) {
        int r = i / FEAT, cc = i - r * FEAT;
        int n = n0 + r;
        xs[i] = (n < N_NODES) ? x[(size_t)n * FEAT + cc] : 0.f;
    }
    __syncthreads();
    const int c = tid;
    for (int r = 0; r < 32; r++) {
        float acc = 0.f;
        const float* xr = xs + r * FEAT;
        #pragma unroll 6
        for (int k = 0; k < FEAT; k++) acc = fmaf(xr[k], Ws[k * H + c], acc);
        g_h[(size_t)(n0 + r) * H + c] = fmaxf(acc, 0.f);
    }
}

// ---------------- GRU elementwise (float4 vectorized) ------------------------
__global__ void gru_kernel() {
    const int v = blockIdx.x * blockDim.x + threadIdx.x;  // vec4 index, < M_PAD*32
    const int node = v >> 5;
    const int c4 = (v & 31) * 4;
    const size_t gb = (size_t)node * 384 + c4;
    const size_t hb = (size_t)node * 128 + c4;
    float4 xr = *(const float4*)&g_gx[gb];
    float4 xz = *(const float4*)&g_gx[gb + 128];
    float4 xn = *(const float4*)&g_gx[gb + 256];
    float4 hr = *(const float4*)&g_gh[gb];
    float4 hz = *(const float4*)&g_gh[gb + 128];
    float4 hn = *(const float4*)&g_gh[gb + 256];
    float4 hv = *(const float4*)&g_h[hb];
    float4 o;
    {
        float r = sigmoidf_(xr.x + hr.x), z = sigmoidf_(xz.x + hz.x);
        float nn = tanhf(xn.x + r * hn.x);
        o.x = (1.f - z) * nn + z * hv.x;
    }
    {
        float r = sigmoidf_(xr.y + hr.y), z = sigmoidf_(xz.y + hz.y);
        float nn = tanhf(xn.y + r * hn.y);
        o.y = (1.f - z) * nn + z * hv.y;
    }
    {
        float r = sigmoidf_(xr.z + hr.z), z = sigmoidf_(xz.z + hz.z);
        float nn = tanhf(xn.z + r * hn.z);
        o.z = (1.f - z) * nn + z * hv.z;
    }
    {
        float r = sigmoidf_(xr.w + hr.w), z = sigmoidf_(xz.w + hz.w);
        float nn = tanhf(xn.w + r * hn.w);
        o.w = (1.f - z) * nn + z * hv.w;
    }
    *(float4*)&g_h[hb] = o;
}

// ---------------- pooling: sum relu(h) per graph (batch sorted) --------------
__global__ void pool_kernel(const int* __restrict__ batch) {
    __shared__ int bs[256];
    const int tid = threadIdx.x;        // 128 threads, one column each
    const int n0 = blockIdx.x * 256;
    const int cnt = min(256, N_NODES - n0);
    for (int i = tid; i < cnt; i += 128) bs[i] = batch[n0 + i];
    __syncthreads();
    const int c = tid;
    float sum = 0.f;
    int cur = bs[0];
    int run = 0;
    for (int i = 0; i < cnt; i++) {
        int b = bs[i];
        if (b != cur) {
            atomicAdd(&g_pool[cur * H + c], sum);
            if (c == 0) atomicAdd(&g_cnt[cur], (float)run);
            sum = 0.f; run = 0; cur = b;
        }
        sum += fmaxf(g_h[(size_t)(n0 + i) * H + c], 0.f);
        run++;
    }
    atomicAdd(&g_pool[cur * H + c], sum);
    if (c == 0) atomicAdd(&g_cnt[cur], (float)run);
}

// ---------------- head: mean -> Linear+ReLU -> Linear -> softplus ------------
__global__ void head_kernel(const float* __restrict__ W1, const float* __restrict__ b1,
                            const float* __restrict__ W2, const float* __restrict__ b2,
                            float* __restrict__ out) {
    __shared__ float ps[H];
    __shared__ float hs[H];
    const int g = blockIdx.x, c = threadIdx.x;
    float cnt = fmaxf(g_cnt[g], 1.f);
    ps[c] = g_pool[g * H + c] / cnt;
    __syncthreads();
    float acc = b1[c];
    #pragma unroll 8
    for (int k = 0; k < H; k++) acc = fmaf(ps[k], W1[k * H + c], acc);
    hs[c] = fmaxf(acc, 0.f) * W2[c];
    __syncthreads();
    for (int s = 64; s > 0; s >>= 1) {
        if (c < s) hs[c] += hs[c + s];
        __syncthreads();
    }
    if (c == 0) {
        float xv = hs[0] + b2[0];
        out[g] = (xv > 0.f) ? (xv + log1pf(expf(-xv))) : log1pf(expf(xv));
    }
}

// ---------------- launch ------------------------------------------------------
extern "C" void kernel_launch(void* const* d_in, const int* in_sizes, int n_in,
                              void* d_out, int out_size) {
    const float* x     = (const float*)d_in[0];
    const int*   ei    = (const int*)d_in[1];
    const int*   batch = (const int*)d_in[2];
    const float* W_emb = (const float*)d_in[3];
    const float* W_msg = (const float*)d_in[4];
    const float* W_ih  = (const float*)d_in[5];
    const float* W_hh  = (const float*)d_in[6];
    const float* b_ih  = (const float*)d_in[7];
    const float* b_hh  = (const float*)d_in[8];
    const float* W1    = (const float*)d_in[9];
    const float* b1    = (const float*)d_in[10];
    const float* W2    = (const float*)d_in[11];
    const float* b2    = (const float*)d_in[12];
    float* out = (float*)d_out;

    float *h_p, *agg_p, *gx_p, *gh_p, *pool_p, *cnt_p;
    int* deg_p;
    cudaGetSymbolAddress((void**)&h_p,   g_h);
    cudaGetSymbolAddress((void**)&agg_p, g_agg);
    cudaGetSymbolAddress((void**)&gx_p,  g_gx);
    cudaGetSymbolAddress((void**)&gh_p,  g_gh);
    cudaGetSymbolAddress((void**)&pool_p, g_pool);
    cudaGetSymbolAddress((void**)&cnt_p,  g_cnt);
    cudaGetSymbolAddress((void**)&deg_p,  g_deg);

    __nv_bfloat16 *wcomb_h, *wcomb_l, *whh_h, *whh_l;
    cudaGetSymbolAddress((void**)&wcomb_h, g_wcomb_h);
    cudaGetSymbolAddress((void**)&wcomb_l, g_wcomb_l);
    cudaGetSymbolAddress((void**)&whh_h,   g_whh_h);
    cudaGetSymbolAddress((void**)&whh_l,   g_whh_l);

    const int embed_smem = (FEAT * H + 32 * FEAT) * 4;  // 57600 B
    cudaFuncSetAttribute(embed_kernel,
                         cudaFuncAttributeMaxDynamicSharedMemorySize, embed_smem);
    cudaFuncSetAttribute(gemm_mma,
                         cudaFuncAttributeMaxDynamicSharedMemorySize, GEMM_SMEM);

    // side stream + events for capture-safe fork/join
    cudaStream_t s2;
    cudaStreamCreateWithFlags(&s2, cudaStreamNonBlocking);
    cudaEvent_t evF, evJ;
    cudaEventCreateWithFlags(&evF, cudaEventDisableTiming);
    cudaEventCreateWithFlags(&evJ, cudaEventDisableTiming);

    // ---- setup phase: CSR build (stream 0)  ||  weight prep + embed (s2) ----
    cudaEventRecord(evF, 0);
    cudaStreamWaitEvent(s2, evF, 0);
    prep_whh<<<(3 * H * H + 255) / 256, 256, 0, s2>>>(W_hh);
    prep_wcomb<<<(STEPS * 3 * H * H + 255) / 256, 256, 0, s2>>>(W_msg, W_ih);
    embed_kernel<<<M_PAD / 32, 128, embed_smem, s2>>>(x, W_emb);
    cudaEventRecord(evJ, s2);

    cudaMemsetAsync(deg_p, 0, N_NODES * sizeof(int));
    hist_kernel<<<(N_EDGES + 255) / 256, 256>>>(ei);
    scan_local<<<SCAN_BLOCKS, 256>>>();
    scan_bsum<<<1, 256>>>();
    scan_add<<<SCAN_BLOCKS, 256>>>();
    fill_kernel<<<(N_EDGES + 255) / 256, 256>>>(ei);
    cudaStreamWaitEvent(0, evJ, 0);

    // ---- steps: gather (0) ∥ gh-GEMM (s2); join; gx-GEMM; gru (R7 schedule) ----
    for (int s = 0; s < STEPS; s++) {
        cudaEventRecord(evF, 0);
        cudaStreamWaitEvent(s2, evF, 0);
        gemm_mma<<<M_TILES, 512, GEMM_SMEM, s2>>>(h_p, whh_h, whh_l, b_hh, gh_p);
        cudaEventRecord(evJ, s2);

        gather_kernel<<<(N_NODES * 32) / 256, 256>>>();
        gemm_mma<<<M_TILES, 512, GEMM_SMEM>>>(
            agg_p, wcomb_h + (size_t)s * 3 * H * H, wcomb_l + (size_t)s * 3 * H * H,
            b_ih, gx_p);

        cudaStreamWaitEvent(0, evJ, 0);
        gru_kernel<<<(M_PAD * 32) / 256, 256>>>();
    }

    // ---- pooling + head ----
    cudaMemsetAsync(pool_p, 0, N_GRAPHS * H * sizeof(float));
    cudaMemsetAsync(cnt_p, 0, N_GRAPHS * sizeof(float));
    pool_kernel<<<(N_NODES + 255) / 256, 128>>>(batch);
    head_kernel<<<N_GRAPHS, H>>>(W1, b1, W2, b2, out);

    cudaEventDestroy(evF);
    cudaEventDestroy(evJ);
    cudaStreamDestroy(s2);
}

// round 13
// speedup vs baseline: 1.1055x; 1.0224x over previous
#include <cuda_runtime.h>
#include <cuda_bf16.h>
#include <math.h>
#include <stdint.h>

#define N_NODES  50000
#define N_EDGES  800000
#define FEAT     90
#define H        128
#define STEPS    4
#define N_GRAPHS 100
#define M_PAD    50048   // 128 * 391
#define M_TILES  (M_PAD / 128)
#define NOUT     384
#define SCAN_BLOCKS 196  // 196 * 256 = 50176 >= N_NODES

typedef unsigned long long u64;

// ---------------- device scratch ----------------
__device__ float g_h  [(size_t)M_PAD * H];
__device__ float g_agg[(size_t)M_PAD * H];
__device__ float g_gx [(size_t)M_PAD * 3 * H];
__device__ float g_gh [(size_t)M_PAD * 3 * H];
__device__ float g_pool[N_GRAPHS * H];
__device__ float g_cnt [N_GRAPHS];

// CSR for gather aggregation
__device__ int g_deg[N_NODES];
__device__ int g_off[N_NODES + 1];
__device__ int g_cur[N_NODES];
__device__ int g_eid[N_EDGES];
__device__ int g_bsum[SCAN_BLOCKS];

// bf16-split, transposed weights, layout [n][k]
__device__ __nv_bfloat16 g_wcomb_h[STEPS * 3 * H * H];  // W_msg[s] @ W_ih
__device__ __nv_bfloat16 g_wcomb_l[STEPS * 3 * H * H];
__device__ __nv_bfloat16 g_whh_h[3 * H * H];
__device__ __nv_bfloat16 g_whh_l[3 * H * H];

// ---------------- PTX helpers ----------------
__device__ __forceinline__ uint32_t smem_u32(const void* p) {
    uint32_t a;
    asm("{ .reg .u64 t; cvta.to.shared.u64 t, %1; cvt.u32.u64 %0, t; }" : "=r"(a) : "l"(p));
    return a;
}

__device__ __forceinline__ void ldsm_x4(uint32_t& r0, uint32_t& r1, uint32_t& r2, uint32_t& r3,
                                        uint32_t addr) {
    asm volatile("ldmatrix.sync.aligned.m8n8.x4.shared.b16 {%0,%1,%2,%3}, [%4];"
                 : "=r"(r0), "=r"(r1), "=r"(r2), "=r"(r3) : "r"(addr));
}

__device__ __forceinline__ void mma_bf16(float* c, const uint32_t* a, const uint32_t* b) {
    asm volatile(
        "mma.sync.aligned.m16n8k16.row.col.f32.bf16.bf16.f32 "
        "{%0,%1,%2,%3}, {%4,%5,%6,%7}, {%8,%9}, {%0,%1,%2,%3};"
        : "+f"(c[0]), "+f"(c[1]), "+f"(c[2]), "+f"(c[3])
        : "r"(a[0]), "r"(a[1]), "r"(a[2]), "r"(a[3]), "r"(b[0]), "r"(b[1]));
}

// swizzled tile offset: row r (0..127), 16B-chunk c (0..15); 256B rows
__device__ __forceinline__ uint32_t swz(int r, int c) {
    return (uint32_t)r * 256 + (uint32_t)((c ^ (r & 7)) << 4);
}

__device__ __forceinline__ float sigmoidf_(float x) { return 1.f / (1.f + expf(-x)); }

// ---------------- CSR build ----------------
__global__ void hist_kernel(const int* __restrict__ ei) {
    int e = blockIdx.x * 256 + threadIdx.x;
    if (e < N_EDGES) atomicAdd(&g_deg[ei[N_EDGES + e]], 1);
}

// pass 1: per-block exclusive scan of deg; write local prefix + block sum
__global__ void scan_local() {
    __shared__ int wsum[8];
    const int tid = threadIdx.x, lane = tid & 31, w = tid >> 5;
    const int i = blockIdx.x * 256 + tid;
    int v = (i < N_NODES) ? g_deg[i] : 0;
    int x = v;
    #pragma unroll
    for (int d = 1; d < 32; d <<= 1) {
        int t = __shfl_up_sync(0xFFFFFFFFu, x, d);
        if (lane >= d) x += t;
    }
    if (lane == 31) wsum[w] = x;
    __syncthreads();
    if (w == 0 && lane < 8) {
        int y = wsum[lane];
        #pragma unroll
        for (int d = 1; d < 8; d <<= 1) {
            int t = __shfl_up_sync(0xFFu, y, d);
            if (lane >= d) y += t;
        }
        wsum[lane] = y;
    }
    __syncthreads();
    int woff = (w == 0) ? 0 : wsum[w - 1];
    if (i < N_NODES) g_off[i] = woff + x - v;       // local exclusive prefix
    if (tid == 255) g_bsum[blockIdx.x] = woff + x;  // block total
}

// pass 2: one block scans the 196 block sums (exclusive, in place)
__global__ void scan_bsum() {
    __shared__ int ws[8];
    const int tid = threadIdx.x, lane = tid & 31, w = tid >> 5;
    int v = (tid < SCAN_BLOCKS) ? g_bsum[tid] : 0;
    int x = v;
    #pragma unroll
    for (int d = 1; d < 32; d <<= 1) {
        int t = __shfl_up_sync(0xFFFFFFFFu, x, d);
        if (lane >= d) x += t;
    }
    if (lane == 31) ws[w] = x;
    __syncthreads();
    if (w == 0 && lane < 8) {
        int y = ws[lane];
        #pragma unroll
        for (int d = 1; d < 8; d <<= 1) {
            int t = __shfl_up_sync(0xFFu, y, d);
            if (lane >= d) y += t;
        }
        ws[lane] = y;
    }
    __syncthreads();
    int woff = (w == 0) ? 0 : ws[w - 1];
    if (tid < SCAN_BLOCKS) g_bsum[tid] = woff + x - v;   // exclusive
    if (tid == 0) g_off[N_NODES] = N_EDGES;
}

// pass 3: add block offsets, init cursor
__global__ void scan_add() {
    const int i = blockIdx.x * 256 + threadIdx.x;
    if (i >= N_NODES) return;
    int o = g_off[i] + g_bsum[blockIdx.x];
    g_off[i] = o;
    g_cur[i] = o;
}

__global__ void fill_kernel(const int* __restrict__ ei) {
    int e = blockIdx.x * 256 + threadIdx.x;
    if (e < N_EDGES) {
        int dst = ei[N_EDGES + e];
        int pos = atomicAdd(&g_cur[dst], 1);
        g_eid[pos] = ei[e];
    }
}

// ---------------- gather: agg[n] = sum_{e: dst=n} h[src[e]] ----------------
// 64-thread blocks (2 warps) for finer load balancing across skewed degrees.
__global__ void gather_kernel() {
    const int node = (blockIdx.x * 64 + threadIdx.x) >> 5;
    if (node >= N_NODES) return;
    const int lane = threadIdx.x & 31;
    const int beg = g_off[node], end = g_off[node + 1];
    float4 acc = make_float4(0.f, 0.f, 0.f, 0.f);
    #pragma unroll 4
    for (int e = beg; e < end; e++) {
        int src = __ldg(&g_eid[e]);
        float4 v = *(const float4*)(g_h + (size_t)src * H + lane * 4);
        acc.x += v.x; acc.y += v.y; acc.z += v.z; acc.w += v.w;
    }
    *(float4*)(g_agg + (size_t)node * H + lane * 4) = acc;
}

// ---------------- weight prep ----------------
__global__ void prep_whh(const float* __restrict__ Whh) {
    int j = blockIdx.x * 256 + threadIdx.x;
    if (j >= 3 * H * H) return;
    int n = j >> 7, k = j & 127;
    float v = Whh[k * 384 + n];
    __nv_bfloat16 hi = __float2bfloat16(v);
    __nv_bfloat16 lo = __float2bfloat16(v - __bfloat162float(hi));
    g_whh_h[j] = hi; g_whh_l[j] = lo;
}

__global__ void prep_wcomb(const float* __restrict__ Wmsg,
                           const float* __restrict__ Wih) {
    int i = blockIdx.x * 256 + threadIdx.x;
    if (i >= STEPS * 3 * H * H) return;
    int s = i / (3 * H * H);
    int r = i % (3 * H * H);
    int k = r / 384;
    int n = r % 384;
    const float* wm = Wmsg + (s << 14) + k * H;
    float acc = 0.f;
    #pragma unroll 8
    for (int j = 0; j < H; j++) acc = fmaf(wm[j], Wih[j * 384 + n], acc);
    __nv_bfloat16 hi = __float2bfloat16(acc);
    __nv_bfloat16 lo = __float2bfloat16(acc - __bfloat162float(hi));
    size_t o = (size_t)s * 3 * H * H + (size_t)n * H + k;
    g_wcomb_h[o] = hi; g_wcomb_l[o] = lo;
}

// ---------------- mma.sync GEMM: C[M_PAD,384] = A[M_PAD,128] @ W[128,384] + b --
// bf16x3: C = Ah*Bh + Ah*Bl + Al*Bh (fp32 accum). 512 thr, warp tile m32 x n32.
// Prologue merges A + B-tile-0 loads (one sync covers both); term-outer mma
// ordering maximizes accumulator ILP.
#define SM_A_H 0
#define SM_A_L 32768
#define SM_B_H 65536
#define SM_B_L 98304
#define SM_BIAS 131072
#define GEMM_SMEM (131072 + 1536)

__global__ void __launch_bounds__(512, 1) gemm_mma(
        const float* __restrict__ A,
        const __nv_bfloat16* __restrict__ Bh, const __nv_bfloat16* __restrict__ Bl,
        const float* __restrict__ bias, float* __restrict__ C) {
    extern __shared__ char smem[];
    const uint32_t sbase = smem_u32(smem);
    const int tid = threadIdx.x;
    const int wid = tid >> 5;
    const int lane = tid & 31;
    const int m0 = blockIdx.x * 128;

    // ---- load A tile (128x128 fp32), split to bf16 hi/lo, swizzled store ----
    {
        const float* Ab = A + (size_t)m0 * 128;
        #pragma unroll
        for (int it = 0; it < 8; it++) {
            int idx = it * 512 + tid;          // 0..4095
            int row = idx >> 5;
            int q = idx & 31;                  // float4 index; k0 = q*4
            float4 v = *(const float4*)(Ab + row * 128 + q * 4);
            __nv_bfloat16 h0 = __float2bfloat16(v.x);
            __nv_bfloat16 h1 = __float2bfloat16(v.y);
            __nv_bfloat16 h2 = __float2bfloat16(v.z);
            __nv_bfloat16 h3 = __float2bfloat16(v.w);
            __nv_bfloat16 l0 = __float2bfloat16(v.x - __bfloat162float(h0));
            __nv_bfloat16 l1 = __float2bfloat16(v.y - __bfloat162float(h1));
            __nv_bfloat16 l2 = __float2bfloat16(v.z - __bfloat162float(h2));
            __nv_bfloat16 l3 = __float2bfloat16(v.w - __bfloat162float(h3));
            uint32_t off = swz(row, q >> 1) + (q & 1) * 8;
            uint2 hw, lw;
            hw.x = (uint32_t)__bfloat16_as_ushort(h0) | ((uint32_t)__bfloat16_as_ushort(h1) << 16);
            hw.y = (uint32_t)__bfloat16_as_ushort(h2) | ((uint32_t)__bfloat16_as_ushort(h3) << 16);
            lw.x = (uint32_t)__bfloat16_as_ushort(l0) | ((uint32_t)__bfloat16_as_ushort(l1) << 16);
            lw.y = (uint32_t)__bfloat16_as_ushort(l2) | ((uint32_t)__bfloat16_as_ushort(l3) << 16);
            *(uint2*)(smem + SM_A_H + off) = hw;
            *(uint2*)(smem + SM_A_L + off) = lw;
        }
    }
    // ---- bias -> smem ----
    for (int i = tid; i < NOUT; i += 512)
        *(float*)(smem + SM_BIAS + i * 4) = bias[i];
    // ---- B tile 0 -> smem (merged with A prologue; one sync covers both) ----
    {
        #pragma unroll
        for (int it = 0; it < 4; it++) {
            int idx = it * 512 + tid;
            int row = idx >> 4;
            int c = idx & 15;
            uint32_t off = swz(row, c);
            *(uint4*)(smem + SM_B_H + off) = *(const uint4*)(Bh + row * 128 + c * 8);
            *(uint4*)(smem + SM_B_L + off) = *(const uint4*)(Bl + row * 128 + c * 8);
        }
    }

    const int wm = (wid & 3) * 32;          // warp row offset
    const int wn = (wid >> 2) * 32;         // warp col offset within tile

    #pragma unroll
    for (int nt = 0; nt < 3; nt++) {
        __syncthreads();   // A/bias/B(nt) visible

        // ---- compute: 8 k-steps, warp tile m32 x n32 ----
        float acc[2][4][4];
        #pragma unroll
        for (int mi = 0; mi < 2; mi++)
            #pragma unroll
            for (int ni = 0; ni < 4; ni++)
                #pragma unroll
                for (int j = 0; j < 4; j++) acc[mi][ni][j] = 0.f;

        #pragma unroll
        for (int ks = 0; ks < 8; ks++) {
            const int c0 = ks * 2;
            uint32_t ah[2][4], al[2][4], bh[4][2], bl[4][2];
            {
                int arow = (lane & 15);
                int ac = c0 + (lane >> 4);
                #pragma unroll
                for (int mi = 0; mi < 2; mi++) {
                    uint32_t o = swz(wm + mi * 16 + arow, ac);
                    ldsm_x4(ah[mi][0], ah[mi][1], ah[mi][2], ah[mi][3], sbase + SM_A_H + o);
                    ldsm_x4(al[mi][0], al[mi][1], al[mi][2], al[mi][3], sbase + SM_A_L + o);
                }
            }
            {
                int brow = ((lane >> 4) << 3) + (lane & 7);
                int bc = c0 + ((lane >> 3) & 1);
                #pragma unroll
                for (int nj = 0; nj < 2; nj++) {
                    uint32_t o = swz(wn + nj * 16 + brow, bc);
                    uint32_t t0, t1, t2, t3;
                    ldsm_x4(t0, t1, t2, t3, sbase + SM_B_H + o);
                    bh[nj * 2][0] = t0; bh[nj * 2][1] = t1;
                    bh[nj * 2 + 1][0] = t2; bh[nj * 2 + 1][1] = t3;
                    ldsm_x4(t0, t1, t2, t3, sbase + SM_B_L + o);
                    bl[nj * 2][0] = t0; bl[nj * 2][1] = t1;
                    bl[nj * 2 + 1][0] = t2; bl[nj * 2 + 1][1] = t3;
                }
            }
            // term-outer ordering: consecutive mmas hit different accumulators
            #pragma unroll
            for (int mi = 0; mi < 2; mi++)
                #pragma unroll
                for (int ni = 0; ni < 4; ni++)
                    mma_bf16(acc[mi][ni], ah[mi], bh[ni]);
            #pragma unroll
            for (int mi = 0; mi < 2; mi++)
                #pragma unroll
                for (int ni = 0; ni < 4; ni++)
                    mma_bf16(acc[mi][ni], ah[mi], bl[ni]);
            #pragma unroll
            for (int mi = 0; mi < 2; mi++)
                #pragma unroll
                for (int ni = 0; ni < 4; ni++)
                    mma_bf16(acc[mi][ni], al[mi], bh[ni]);
        }

        // ---- epilogue ----
        {
            const int r0 = m0 + wm + (lane >> 2);
            const int cb = nt * 128 + wn + (lane & 3) * 2;
            #pragma unroll
            for (int mi = 0; mi < 2; mi++) {
                #pragma unroll
                for (int ni = 0; ni < 4; ni++) {
                    int col = cb + ni * 8;
                    float2 bb = *(const float2*)(smem + SM_BIAS + col * 4);
                    float* c0p = C + (size_t)(r0 + mi * 16) * NOUT + col;
                    float* c1p = C + (size_t)(r0 + mi * 16 + 8) * NOUT + col;
                    *(float2*)c0p = make_float2(acc[mi][ni][0] + bb.x, acc[mi][ni][1] + bb.y);
                    *(float2*)c1p = make_float2(acc[mi][ni][2] + bb.x, acc[mi][ni][3] + bb.y);
                }
            }
        }

        // ---- load next B tile (sync: all warps done reading B(nt)) ----
        if (nt < 2) {
            __syncthreads();
            const __nv_bfloat16* bh = Bh + (size_t)(nt + 1) * 128 * 128;
            const __nv_bfloat16* bl = Bl + (size_t)(nt + 1) * 128 * 128;
            #pragma unroll
            for (int it = 0; it < 4; it++) {
                int idx = it * 512 + tid;
                int row = idx >> 4;
                int c = idx & 15;
                uint32_t off = swz(row, c);
                *(uint4*)(smem + SM_B_H + off) = *(const uint4*)(bh + row * 128 + c * 8);
                *(uint4*)(smem + SM_B_L + off) = *(const uint4*)(bl + row * 128 + c * 8);
            }
        }
    }
}

// ---------------- embedding: h = relu(x @ W_emb), K=90, 64 nodes per block ----
__global__ void embed_kernel(const float* __restrict__ x,
                             const float* __restrict__ Wemb) {
    extern __shared__ float sm[];
    float* Ws = sm;               // FEAT*H
    float* xs = sm + FEAT * H;    // 64*FEAT
    const int tid = threadIdx.x;
    for (int i = tid; i < FEAT * H; i += 128) Ws[i] = Wemb[i];
    const int n0 = blockIdx.x * 64;
    for (int i = tid; i < 64 * FEAT; i += 128) {
        int r = i / FEAT, cc = i - r * FEAT;
        int n = n0 + r;
        xs[i] = (n < N_NODES) ? x[(size_t)n * FEAT + cc] : 0.f;
    }
    __syncthreads();
    const int c = tid;
    for (int r = 0; r < 64; r++) {
        float acc = 0.f;
        const float* xr = xs + r * FEAT;
        #pragma unroll 6
        for (int k = 0; k < FEAT; k++) acc = fmaf(xr[k], Ws[k * H + c], acc);
        g_h[(size_t)(n0 + r) * H + c] = fmaxf(acc, 0.f);
    }
}

// ---------------- GRU elementwise (float4 vectorized) ------------------------
__global__ void gru_kernel() {
    const int v = blockIdx.x * blockDim.x + threadIdx.x;  // vec4 index, < M_PAD*32
    const int node = v >> 5;
    const int c4 = (v & 31) * 4;
    const size_t gb = (size_t)node * 384 + c4;
    const size_t hb = (size_t)node * 128 + c4;
    float4 xr = *(const float4*)&g_gx[gb];
    float4 xz = *(const float4*)&g_gx[gb + 128];
    float4 xn = *(const float4*)&g_gx[gb + 256];
    float4 hr = *(const float4*)&g_gh[gb];
    float4 hz = *(const float4*)&g_gh[gb + 128];
    float4 hn = *(const float4*)&g_gh[gb + 256];
    float4 hv = *(const float4*)&g_h[hb];
    float4 o;
    {
        float r = sigmoidf_(xr.x + hr.x), z = sigmoidf_(xz.x + hz.x);
        float nn = tanhf(xn.x + r * hn.x);
        o.x = (1.f - z) * nn + z * hv.x;
    }
    {
        float r = sigmoidf_(xr.y + hr.y), z = sigmoidf_(xz.y + hz.y);
        float nn = tanhf(xn.y + r * hn.y);
        o.y = (1.f - z) * nn + z * hv.y;
    }
    {
        float r = sigmoidf_(xr.z + hr.z), z = sigmoidf_(xz.z + hz.z);
        float nn = tanhf(xn.z + r * hn.z);
        o.z = (1.f - z) * nn + z * hv.z;
    }
    {
        float r = sigmoidf_(xr.w + hr.w), z = sigmoidf_(xz.w + hz.w);
        float nn = tanhf(xn.w + r * hn.w);
        o.w = (1.f - z) * nn + z * hv.w;
    }
    *(float4*)&g_h[hb] = o;
}

// ---------------- pooling: sum relu(h) per graph (batch sorted) --------------
__global__ void pool_kernel(const int* __restrict__ batch) {
    __shared__ int bs[256];
    const int tid = threadIdx.x;        // 128 threads, one column each
    const int n0 = blockIdx.x * 256;
    const int cnt = min(256, N_NODES - n0);
    for (int i = tid; i < cnt; i += 128) bs[i] = batch[n0 + i];
    __syncthreads();
    const int c = tid;
    float sum = 0.f;
    int cur = bs[0];
    int run = 0;
    for (int i = 0; i < cnt; i++) {
        int b = bs[i];
        if (b != cur) {
            atomicAdd(&g_pool[cur * H + c], sum);
            if (c == 0) atomicAdd(&g_cnt[cur], (float)run);
            sum = 0.f; run = 0; cur = b;
        }
        sum += fmaxf(g_h[(size_t)(n0 + i) * H + c], 0.f);
        run++;
    }
    atomicAdd(&g_pool[cur * H + c], sum);
    if (c == 0) atomicAdd(&g_cnt[cur], (float)run);
}

// ---------------- head: mean -> Linear+ReLU -> Linear -> softplus ------------
__global__ void head_kernel(const float* __restrict__ W1, const float* __restrict__ b1,
                            const float* __restrict__ W2, const float* __restrict__ b2,
                            float* __restrict__ out) {
    __shared__ float ps[H];
    __shared__ float hs[H];
    const int g = blockIdx.x, c = threadIdx.x;
    float cnt = fmaxf(g_cnt[g], 1.f);
    ps[c] = g_pool[g * H + c] / cnt;
    __syncthreads();
    float acc = b1[c];
    #pragma unroll 8
    for (int k = 0; k < H; k++) acc = fmaf(ps[k], W1[k * H + c], acc);
    hs[c] = fmaxf(acc, 0.f) * W2[c];
    __syncthreads();
    for (int s = 64; s > 0; s >>= 1) {
        if (c < s) hs[c] += hs[c + s];
        __syncthreads();
    }
    if (c == 0) {
        float xv = hs[0] + b2[0];
        out[g] = (xv > 0.f) ? (xv + log1pf(expf(-xv))) : log1pf(expf(xv));
    }
}

// ---------------- launch ------------------------------------------------------
extern "C" void kernel_launch(void* const* d_in, const int* in_sizes, int n_in,
                              void* d_out, int out_size) {
    const float* x     = (const float*)d_in[0];
    const int*   ei    = (const int*)d_in[1];
    const int*   batch = (const int*)d_in[2];
    const float* W_emb = (const float*)d_in[3];
    const float* W_msg = (const float*)d_in[4];
    const float* W_ih  = (const float*)d_in[5];
    const float* W_hh  = (const float*)d_in[6];
    const float* b_ih  = (const float*)d_in[7];
    const float* b_hh  = (const float*)d_in[8];
    const float* W1    = (const float*)d_in[9];
    const float* b1    = (const float*)d_in[10];
    const float* W2    = (const float*)d_in[11];
    const float* b2    = (const float*)d_in[12];
    float* out = (float*)d_out;

    float *h_p, *agg_p, *gx_p, *gh_p, *pool_p, *cnt_p;
    int* deg_p;
    cudaGetSymbolAddress((void**)&h_p,   g_h);
    cudaGetSymbolAddress((void**)&agg_p, g_agg);
    cudaGetSymbolAddress((void**)&gx_p,  g_gx);
    cudaGetSymbolAddress((void**)&gh_p,  g_gh);
    cudaGetSymbolAddress((void**)&pool_p, g_pool);
    cudaGetSymbolAddress((void**)&cnt_p,  g_cnt);
    cudaGetSymbolAddress((void**)&deg_p,  g_deg);

    __nv_bfloat16 *wcomb_h, *wcomb_l, *whh_h, *whh_l;
    cudaGetSymbolAddress((void**)&wcomb_h, g_wcomb_h);
    cudaGetSymbolAddress((void**)&wcomb_l, g_wcomb_l);
    cudaGetSymbolAddress((void**)&whh_h,   g_whh_h);
    cudaGetSymbolAddress((void**)&whh_l,   g_whh_l);

    const int embed_smem = (FEAT * H + 64 * FEAT) * 4;  // 69120 B
    cudaFuncSetAttribute(embed_kernel,
                         cudaFuncAttributeMaxDynamicSharedMemorySize, embed_smem);
    cudaFuncSetAttribute(gemm_mma,
                         cudaFuncAttributeMaxDynamicSharedMemorySize, GEMM_SMEM);

    // side stream + events for capture-safe fork/join
    cudaStream_t s2;
    cudaStreamCreateWithFlags(&s2, cudaStreamNonBlocking);
    cudaEvent_t evF, evJ;
    cudaEventCreateWithFlags(&evF, cudaEventDisableTiming);
    cudaEventCreateWithFlags(&evJ, cudaEventDisableTiming);

    // ---- setup phase: CSR build (stream 0)  ||  weight prep + embed (s2) ----
    cudaEventRecord(evF, 0);
    cudaStreamWaitEvent(s2, evF, 0);
    prep_whh<<<(3 * H * H + 255) / 256, 256, 0, s2>>>(W_hh);
    prep_wcomb<<<(STEPS * 3 * H * H + 255) / 256, 256, 0, s2>>>(W_msg, W_ih);
    embed_kernel<<<M_PAD / 64, 128, embed_smem, s2>>>(x, W_emb);
    cudaEventRecord(evJ, s2);

    cudaMemsetAsync(deg_p, 0, N_NODES * sizeof(int));
    hist_kernel<<<(N_EDGES + 255) / 256, 256>>>(ei);
    scan_local<<<SCAN_BLOCKS, 256>>>();
    scan_bsum<<<1, 256>>>();
    scan_add<<<SCAN_BLOCKS, 256>>>();
    fill_kernel<<<(N_EDGES + 255) / 256, 256>>>(ei);
    cudaStreamWaitEvent(0, evJ, 0);

    // ---- steps: gather (0) ∥ gh-GEMM (s2); join; gx-GEMM; gru (R7 schedule) ----
    for (int s = 0; s < STEPS; s++) {
        cudaEventRecord(evF, 0);
        cudaStreamWaitEvent(s2, evF, 0);
        gemm_mma<<<M_TILES, 512, GEMM_SMEM, s2>>>(h_p, whh_h, whh_l, b_hh, gh_p);
        cudaEventRecord(evJ, s2);

        gather_kernel<<<(N_NODES * 32 + 63) / 64, 64>>>();
        gemm_mma<<<M_TILES, 512, GEMM_SMEM>>>(
            agg_p, wcomb_h + (size_t)s * 3 * H * H, wcomb_l + (size_t)s * 3 * H * H,
            b_ih, gx_p);

        cudaStreamWaitEvent(0, evJ, 0);
        gru_kernel<<<(M_PAD * 32) / 256, 256>>>();
    }

    // ---- pooling + head ----
    cudaMemsetAsync(pool_p, 0, N_GRAPHS * H * sizeof(float));
    cudaMemsetAsync(cnt_p, 0, N_GRAPHS * sizeof(float));
    pool_kernel<<<(N_NODES + 255) / 256, 128>>>(batch);
    head_kernel<<<N_GRAPHS, H>>>(W1, b1, W2, b2, out);

    cudaEventDestroy(evF);
    cudaEventDestroy(evJ);
    cudaStreamDestroy(s2);
}

// round 14
// speedup vs baseline: 1.1557x; 1.0454x over previous
#include <cuda_runtime.h>
#include <cuda_bf16.h>
#include <math.h>
#include <stdint.h>

#define N_NODES  50000
#define N_EDGES  800000
#define FEAT     90
#define H        128
#define STEPS    4
#define N_GRAPHS 100
#define M_PAD    50048   // 128 * 391
#define M_TILES  (M_PAD / 128)
#define NOUT     384
#define SCAN_BLOCKS 196  // 196 * 256 = 50176 >= N_NODES

typedef unsigned long long u64;

// ---------------- device scratch ----------------
__device__ float g_h  [(size_t)M_PAD * H];
__device__ float g_agg[(size_t)M_PAD * H];
__device__ float g_gx [(size_t)M_PAD * 3 * H];
__device__ float g_gh [(size_t)M_PAD * 3 * H];
__device__ float g_pool[N_GRAPHS * H];
__device__ float g_cnt [N_GRAPHS];

// CSR for gather aggregation
__device__ int g_deg[N_NODES];
__device__ int g_off[N_NODES + 1];
__device__ int g_cur[N_NODES];
__device__ int g_eid[N_EDGES];
__device__ int g_bsum[SCAN_BLOCKS];

// bf16-split, transposed weights, layout [n][k]
__device__ __nv_bfloat16 g_wcomb_h[STEPS * 3 * H * H];  // W_msg[s] @ W_ih
__device__ __nv_bfloat16 g_wcomb_l[STEPS * 3 * H * H];
__device__ __nv_bfloat16 g_whh_h[3 * H * H];
__device__ __nv_bfloat16 g_whh_l[3 * H * H];

// ---------------- PTX helpers ----------------
__device__ __forceinline__ uint32_t smem_u32(const void* p) {
    uint32_t a;
    asm("{ .reg .u64 t; cvta.to.shared.u64 t, %1; cvt.u32.u64 %0, t; }" : "=r"(a) : "l"(p));
    return a;
}

__device__ __forceinline__ void ldsm_x4(uint32_t& r0, uint32_t& r1, uint32_t& r2, uint32_t& r3,
                                        uint32_t addr) {
    asm volatile("ldmatrix.sync.aligned.m8n8.x4.shared.b16 {%0,%1,%2,%3}, [%4];"
                 : "=r"(r0), "=r"(r1), "=r"(r2), "=r"(r3) : "r"(addr));
}

__device__ __forceinline__ void mma_bf16(float* c, const uint32_t* a, const uint32_t* b) {
    asm volatile(
        "mma.sync.aligned.m16n8k16.row.col.f32.bf16.bf16.f32 "
        "{%0,%1,%2,%3}, {%4,%5,%6,%7}, {%8,%9}, {%0,%1,%2,%3};"
        : "+f"(c[0]), "+f"(c[1]), "+f"(c[2]), "+f"(c[3])
        : "r"(a[0]), "r"(a[1]), "r"(a[2]), "r"(a[3]), "r"(b[0]), "r"(b[1]));
}

// swizzled tile offset: row r (0..127), 16B-chunk c (0..15); 256B rows
__device__ __forceinline__ uint32_t swz(int r, int c) {
    return (uint32_t)r * 256 + (uint32_t)((c ^ (r & 7)) << 4);
}

__device__ __forceinline__ float sigmoidf_(float x) { return 1.f / (1.f + expf(-x)); }

// ---------------- CSR build ----------------
__global__ void hist_kernel(const int* __restrict__ ei) {
    int e = blockIdx.x * 256 + threadIdx.x;
    if (e < N_EDGES) atomicAdd(&g_deg[ei[N_EDGES + e]], 1);
}

// pass 1: per-block exclusive scan of deg; write local prefix + block sum
__global__ void scan_local() {
    __shared__ int wsum[8];
    const int tid = threadIdx.x, lane = tid & 31, w = tid >> 5;
    const int i = blockIdx.x * 256 + tid;
    int v = (i < N_NODES) ? g_deg[i] : 0;
    int x = v;
    #pragma unroll
    for (int d = 1; d < 32; d <<= 1) {
        int t = __shfl_up_sync(0xFFFFFFFFu, x, d);
        if (lane >= d) x += t;
    }
    if (lane == 31) wsum[w] = x;
    __syncthreads();
    if (w == 0 && lane < 8) {
        int y = wsum[lane];
        #pragma unroll
        for (int d = 1; d < 8; d <<= 1) {
            int t = __shfl_up_sync(0xFFu, y, d);
            if (lane >= d) y += t;
        }
        wsum[lane] = y;
    }
    __syncthreads();
    int woff = (w == 0) ? 0 : wsum[w - 1];
    if (i < N_NODES) g_off[i] = woff + x - v;       // local exclusive prefix
    if (tid == 255) g_bsum[blockIdx.x] = woff + x;  // block total
}

// pass 2: one block scans the 196 block sums (exclusive, in place)
__global__ void scan_bsum() {
    __shared__ int ws[8];
    const int tid = threadIdx.x, lane = tid & 31, w = tid >> 5;
    int v = (tid < SCAN_BLOCKS) ? g_bsum[tid] : 0;
    int x = v;
    #pragma unroll
    for (int d = 1; d < 32; d <<= 1) {
        int t = __shfl_up_sync(0xFFFFFFFFu, x, d);
        if (lane >= d) x += t;
    }
    if (lane == 31) ws[w] = x;
    __syncthreads();
    if (w == 0 && lane < 8) {
        int y = ws[lane];
        #pragma unroll
        for (int d = 1; d < 8; d <<= 1) {
            int t = __shfl_up_sync(0xFFu, y, d);
            if (lane >= d) y += t;
        }
        ws[lane] = y;
    }
    __syncthreads();
    int woff = (w == 0) ? 0 : ws[w - 1];
    if (tid < SCAN_BLOCKS) g_bsum[tid] = woff + x - v;   // exclusive
    if (tid == 0) g_off[N_NODES] = N_EDGES;
}

// pass 3: add block offsets, init cursor
__global__ void scan_add() {
    const int i = blockIdx.x * 256 + threadIdx.x;
    if (i >= N_NODES) return;
    int o = g_off[i] + g_bsum[blockIdx.x];
    g_off[i] = o;
    g_cur[i] = o;
}

__global__ void fill_kernel(const int* __restrict__ ei) {
    int e = blockIdx.x * 256 + threadIdx.x;
    if (e < N_EDGES) {
        int dst = ei[N_EDGES + e];
        int pos = atomicAdd(&g_cur[dst], 1);
        g_eid[pos] = ei[e];
    }
}

// ---------------- gather: agg[n] = sum_{e: dst=n} h[src[e]] ----------------
// 64-thread blocks (2 warps) for finer load balancing across skewed degrees.
__global__ void gather_kernel() {
    const int node = (blockIdx.x * 64 + threadIdx.x) >> 5;
    if (node >= N_NODES) return;
    const int lane = threadIdx.x & 31;
    const int beg = g_off[node], end = g_off[node + 1];
    float4 acc = make_float4(0.f, 0.f, 0.f, 0.f);
    #pragma unroll 4
    for (int e = beg; e < end; e++) {
        int src = __ldg(&g_eid[e]);
        float4 v = *(const float4*)(g_h + (size_t)src * H + lane * 4);
        acc.x += v.x; acc.y += v.y; acc.z += v.z; acc.w += v.w;
    }
    *(float4*)(g_agg + (size_t)node * H + lane * 4) = acc;
}

// ---------------- weight prep ----------------
__global__ void prep_whh(const float* __restrict__ Whh) {
    int j = blockIdx.x * 256 + threadIdx.x;
    if (j >= 3 * H * H) return;
    int n = j >> 7, k = j & 127;
    float v = Whh[k * 384 + n];
    __nv_bfloat16 hi = __float2bfloat16(v);
    __nv_bfloat16 lo = __float2bfloat16(v - __bfloat162float(hi));
    g_whh_h[j] = hi; g_whh_l[j] = lo;
}

__global__ void prep_wcomb(const float* __restrict__ Wmsg,
                           const float* __restrict__ Wih) {
    int i = blockIdx.x * 256 + threadIdx.x;
    if (i >= STEPS * 3 * H * H) return;
    int s = i / (3 * H * H);
    int r = i % (3 * H * H);
    int k = r / 384;
    int n = r % 384;
    const float* wm = Wmsg + (s << 14) + k * H;
    float acc = 0.f;
    #pragma unroll 8
    for (int j = 0; j < H; j++) acc = fmaf(wm[j], Wih[j * 384 + n], acc);
    __nv_bfloat16 hi = __float2bfloat16(acc);
    __nv_bfloat16 lo = __float2bfloat16(acc - __bfloat162float(hi));
    size_t o = (size_t)s * 3 * H * H + (size_t)n * H + k;
    g_wcomb_h[o] = hi; g_wcomb_l[o] = lo;
}

// ---------------- mma.sync GEMM: C[M_PAD,384] = A[M_PAD,128] @ W[128,384] + b --
// bf16x3: C = Ah*Bh + Ah*Bl + Al*Bh (fp32 accum). 512 thr, warp tile m32 x n32.
// Prologue merges A + B-tile-0 loads; term-outer mma ordering for accumulator ILP.
#define SM_A_H 0
#define SM_A_L 32768
#define SM_B_H 65536
#define SM_B_L 98304
#define SM_BIAS 131072
#define GEMM_SMEM (131072 + 1536)

__global__ void __launch_bounds__(512, 1) gemm_mma(
        const float* __restrict__ A,
        const __nv_bfloat16* __restrict__ Bh, const __nv_bfloat16* __restrict__ Bl,
        const float* __restrict__ bias, float* __restrict__ C) {
    extern __shared__ char smem[];
    const uint32_t sbase = smem_u32(smem);
    const int tid = threadIdx.x;
    const int wid = tid >> 5;
    const int lane = tid & 31;
    const int m0 = blockIdx.x * 128;

    // ---- load A tile (128x128 fp32), split to bf16 hi/lo, swizzled store ----
    {
        const float* Ab = A + (size_t)m0 * 128;
        #pragma unroll
        for (int it = 0; it < 8; it++) {
            int idx = it * 512 + tid;          // 0..4095
            int row = idx >> 5;
            int q = idx & 31;                  // float4 index; k0 = q*4
            float4 v = *(const float4*)(Ab + row * 128 + q * 4);
            __nv_bfloat16 h0 = __float2bfloat16(v.x);
            __nv_bfloat16 h1 = __float2bfloat16(v.y);
            __nv_bfloat16 h2 = __float2bfloat16(v.z);
            __nv_bfloat16 h3 = __float2bfloat16(v.w);
            __nv_bfloat16 l0 = __float2bfloat16(v.x - __bfloat162float(h0));
            __nv_bfloat16 l1 = __float2bfloat16(v.y - __bfloat162float(h1));
            __nv_bfloat16 l2 = __float2bfloat16(v.z - __bfloat162float(h2));
            __nv_bfloat16 l3 = __float2bfloat16(v.w - __bfloat162float(h3));
            uint32_t off = swz(row, q >> 1) + (q & 1) * 8;
            uint2 hw, lw;
            hw.x = (uint32_t)__bfloat16_as_ushort(h0) | ((uint32_t)__bfloat16_as_ushort(h1) << 16);
            hw.y = (uint32_t)__bfloat16_as_ushort(h2) | ((uint32_t)__bfloat16_as_ushort(h3) << 16);
            lw.x = (uint32_t)__bfloat16_as_ushort(l0) | ((uint32_t)__bfloat16_as_ushort(l1) << 16);
            lw.y = (uint32_t)__bfloat16_as_ushort(l2) | ((uint32_t)__bfloat16_as_ushort(l3) << 16);
            *(uint2*)(smem + SM_A_H + off) = hw;
            *(uint2*)(smem + SM_A_L + off) = lw;
        }
    }
    // ---- bias -> smem ----
    for (int i = tid; i < NOUT; i += 512)
        *(float*)(smem + SM_BIAS + i * 4) = bias[i];
    // ---- B tile 0 -> smem (merged with A prologue; one sync covers both) ----
    {
        #pragma unroll
        for (int it = 0; it < 4; it++) {
            int idx = it * 512 + tid;
            int row = idx >> 4;
            int c = idx & 15;
            uint32_t off = swz(row, c);
            *(uint4*)(smem + SM_B_H + off) = *(const uint4*)(Bh + row * 128 + c * 8);
            *(uint4*)(smem + SM_B_L + off) = *(const uint4*)(Bl + row * 128 + c * 8);
        }
    }

    const int wm = (wid & 3) * 32;          // warp row offset
    const int wn = (wid >> 2) * 32;         // warp col offset within tile

    #pragma unroll
    for (int nt = 0; nt < 3; nt++) {
        __syncthreads();   // A/bias/B(nt) visible

        // ---- compute: 8 k-steps, warp tile m32 x n32 ----
        float acc[2][4][4];
        #pragma unroll
        for (int mi = 0; mi < 2; mi++)
            #pragma unroll
            for (int ni = 0; ni < 4; ni++)
                #pragma unroll
                for (int j = 0; j < 4; j++) acc[mi][ni][j] = 0.f;

        #pragma unroll
        for (int ks = 0; ks < 8; ks++) {
            const int c0 = ks * 2;
            uint32_t ah[2][4], al[2][4], bh[4][2], bl[4][2];
            {
                int arow = (lane & 15);
                int ac = c0 + (lane >> 4);
                #pragma unroll
                for (int mi = 0; mi < 2; mi++) {
                    uint32_t o = swz(wm + mi * 16 + arow, ac);
                    ldsm_x4(ah[mi][0], ah[mi][1], ah[mi][2], ah[mi][3], sbase + SM_A_H + o);
                    ldsm_x4(al[mi][0], al[mi][1], al[mi][2], al[mi][3], sbase + SM_A_L + o);
                }
            }
            {
                int brow = ((lane >> 4) << 3) + (lane & 7);
                int bc = c0 + ((lane >> 3) & 1);
                #pragma unroll
                for (int nj = 0; nj < 2; nj++) {
                    uint32_t o = swz(wn + nj * 16 + brow, bc);
                    uint32_t t0, t1, t2, t3;
                    ldsm_x4(t0, t1, t2, t3, sbase + SM_B_H + o);
                    bh[nj * 2][0] = t0; bh[nj * 2][1] = t1;
                    bh[nj * 2 + 1][0] = t2; bh[nj * 2 + 1][1] = t3;
                    ldsm_x4(t0, t1, t2, t3, sbase + SM_B_L + o);
                    bl[nj * 2][0] = t0; bl[nj * 2][1] = t1;
                    bl[nj * 2 + 1][0] = t2; bl[nj * 2 + 1][1] = t3;
                }
            }
            // term-outer ordering: consecutive mmas hit different accumulators
            #pragma unroll
            for (int mi = 0; mi < 2; mi++)
                #pragma unroll
                for (int ni = 0; ni < 4; ni++)
                    mma_bf16(acc[mi][ni], ah[mi], bh[ni]);
            #pragma unroll
            for (int mi = 0; mi < 2; mi++)
                #pragma unroll
                for (int ni = 0; ni < 4; ni++)
                    mma_bf16(acc[mi][ni], ah[mi], bl[ni]);
            #pragma unroll
            for (int mi = 0; mi < 2; mi++)
                #pragma unroll
                for (int ni = 0; ni < 4; ni++)
                    mma_bf16(acc[mi][ni], al[mi], bh[ni]);
        }

        // ---- epilogue ----
        {
            const int r0 = m0 + wm + (lane >> 2);
            const int cb = nt * 128 + wn + (lane & 3) * 2;
            #pragma unroll
            for (int mi = 0; mi < 2; mi++) {
                #pragma unroll
                for (int ni = 0; ni < 4; ni++) {
                    int col = cb + ni * 8;
                    float2 bb = *(const float2*)(smem + SM_BIAS + col * 4);
                    float* c0p = C + (size_t)(r0 + mi * 16) * NOUT + col;
                    float* c1p = C + (size_t)(r0 + mi * 16 + 8) * NOUT + col;
                    *(float2*)c0p = make_float2(acc[mi][ni][0] + bb.x, acc[mi][ni][1] + bb.y);
                    *(float2*)c1p = make_float2(acc[mi][ni][2] + bb.x, acc[mi][ni][3] + bb.y);
                }
            }
        }

        // ---- load next B tile (sync: all warps done reading B(nt)) ----
        if (nt < 2) {
            __syncthreads();
            const __nv_bfloat16* bh = Bh + (size_t)(nt + 1) * 128 * 128;
            const __nv_bfloat16* bl = Bl + (size_t)(nt + 1) * 128 * 128;
            #pragma unroll
            for (int it = 0; it < 4; it++) {
                int idx = it * 512 + tid;
                int row = idx >> 4;
                int c = idx & 15;
                uint32_t off = swz(row, c);
                *(uint4*)(smem + SM_B_H + off) = *(const uint4*)(bh + row * 128 + c * 8);
                *(uint4*)(smem + SM_B_L + off) = *(const uint4*)(bl + row * 128 + c * 8);
            }
        }
    }
}

// ---------------- embedding: h = relu(x @ W_emb), K=90, 64 nodes per block ----
__global__ void embed_kernel(const float* __restrict__ x,
                             const float* __restrict__ Wemb) {
    extern __shared__ float sm[];
    float* Ws = sm;               // FEAT*H
    float* xs = sm + FEAT * H;    // 64*FEAT
    const int tid = threadIdx.x;
    for (int i = tid; i < FEAT * H; i += 128) Ws[i] = Wemb[i];
    const int n0 = blockIdx.x * 64;
    for (int i = tid; i < 64 * FEAT; i += 128) {
        int r = i / FEAT, cc = i - r * FEAT;
        int n = n0 + r;
        xs[i] = (n < N_NODES) ? x[(size_t)n * FEAT + cc] : 0.f;
    }
    __syncthreads();
    const int c = tid;
    for (int r = 0; r < 64; r++) {
        float acc = 0.f;
        const float* xr = xs + r * FEAT;
        #pragma unroll 6
        for (int k = 0; k < FEAT; k++) acc = fmaf(xr[k], Ws[k * H + c], acc);
        g_h[(size_t)(n0 + r) * H + c] = fmaxf(acc, 0.f);
    }
}

// ---------------- GRU elementwise (float4 vectorized) ------------------------
__global__ void gru_kernel() {
    const int v = blockIdx.x * blockDim.x + threadIdx.x;  // vec4 index, < M_PAD*32
    const int node = v >> 5;
    const int c4 = (v & 31) * 4;
    const size_t gb = (size_t)node * 384 + c4;
    const size_t hb = (size_t)node * 128 + c4;
    float4 xr = *(const float4*)&g_gx[gb];
    float4 xz = *(const float4*)&g_gx[gb + 128];
    float4 xn = *(const float4*)&g_gx[gb + 256];
    float4 hr = *(const float4*)&g_gh[gb];
    float4 hz = *(const float4*)&g_gh[gb + 128];
    float4 hn = *(const float4*)&g_gh[gb + 256];
    float4 hv = *(const float4*)&g_h[hb];
    float4 o;
    {
        float r = sigmoidf_(xr.x + hr.x), z = sigmoidf_(xz.x + hz.x);
        float nn = tanhf(xn.x + r * hn.x);
        o.x = (1.f - z) * nn + z * hv.x;
    }
    {
        float r = sigmoidf_(xr.y + hr.y), z = sigmoidf_(xz.y + hz.y);
        float nn = tanhf(xn.y + r * hn.y);
        o.y = (1.f - z) * nn + z * hv.y;
    }
    {
        float r = sigmoidf_(xr.z + hr.z), z = sigmoidf_(xz.z + hz.z);
        float nn = tanhf(xn.z + r * hn.z);
        o.z = (1.f - z) * nn + z * hv.z;
    }
    {
        float r = sigmoidf_(xr.w + hr.w), z = sigmoidf_(xz.w + hz.w);
        float nn = tanhf(xn.w + r * hn.w);
        o.w = (1.f - z) * nn + z * hv.w;
    }
    *(float4*)&g_h[hb] = o;
}

// ---------------- pooling: sum relu(h) per graph (batch sorted) --------------
// 128 nodes per block (391 blocks) for shorter serial runs + better waves.
__global__ void pool_kernel(const int* __restrict__ batch) {
    __shared__ int bs[128];
    const int tid = threadIdx.x;        // 128 threads, one column each
    const int n0 = blockIdx.x * 128;
    const int cnt = min(128, N_NODES - n0);
    if (cnt <= 0) return;
    if (tid < cnt) bs[tid] = batch[n0 + tid];
    __syncthreads();
    const int c = tid;
    float sum = 0.f;
    int cur = bs[0];
    int run = 0;
    for (int i = 0; i < cnt; i++) {
        int b = bs[i];
        if (b != cur) {
            atomicAdd(&g_pool[cur * H + c], sum);
            if (c == 0) atomicAdd(&g_cnt[cur], (float)run);
            sum = 0.f; run = 0; cur = b;
        }
        sum += fmaxf(g_h[(size_t)(n0 + i) * H + c], 0.f);
        run++;
    }
    atomicAdd(&g_pool[cur * H + c], sum);
    if (c == 0) atomicAdd(&g_cnt[cur], (float)run);
}

// ---------------- head: mean -> Linear+ReLU -> Linear -> softplus ------------
__global__ void head_kernel(const float* __restrict__ W1, const float* __restrict__ b1,
                            const float* __restrict__ W2, const float* __restrict__ b2,
                            float* __restrict__ out) {
    __shared__ float ps[H];
    __shared__ float hs[H];
    const int g = blockIdx.x, c = threadIdx.x;
    float cnt = fmaxf(g_cnt[g], 1.f);
    ps[c] = g_pool[g * H + c] / cnt;
    __syncthreads();
    float acc = b1[c];
    #pragma unroll 8
    for (int k = 0; k < H; k++) acc = fmaf(ps[k], W1[k * H + c], acc);
    hs[c] = fmaxf(acc, 0.f) * W2[c];
    __syncthreads();
    for (int s = 64; s > 0; s >>= 1) {
        if (c < s) hs[c] += hs[c + s];
        __syncthreads();
    }
    if (c == 0) {
        float xv = hs[0] + b2[0];
        out[g] = (xv > 0.f) ? (xv + log1pf(expf(-xv))) : log1pf(expf(xv));
    }
}

// ---------------- launch ------------------------------------------------------
extern "C" void kernel_launch(void* const* d_in, const int* in_sizes, int n_in,
                              void* d_out, int out_size) {
    const float* x     = (const float*)d_in[0];
    const int*   ei    = (const int*)d_in[1];
    const int*   batch = (const int*)d_in[2];
    const float* W_emb = (const float*)d_in[3];
    const float* W_msg = (const float*)d_in[4];
    const float* W_ih  = (const float*)d_in[5];
    const float* W_hh  = (const float*)d_in[6];
    const float* b_ih  = (const float*)d_in[7];
    const float* b_hh  = (const float*)d_in[8];
    const float* W1    = (const float*)d_in[9];
    const float* b1    = (const float*)d_in[10];
    const float* W2    = (const float*)d_in[11];
    const float* b2    = (const float*)d_in[12];
    float* out = (float*)d_out;

    float *h_p, *agg_p, *gx_p, *gh_p, *pool_p, *cnt_p;
    int* deg_p;
    cudaGetSymbolAddress((void**)&h_p,   g_h);
    cudaGetSymbolAddress((void**)&agg_p, g_agg);
    cudaGetSymbolAddress((void**)&gx_p,  g_gx);
    cudaGetSymbolAddress((void**)&gh_p,  g_gh);
    cudaGetSymbolAddress((void**)&pool_p, g_pool);
    cudaGetSymbolAddress((void**)&cnt_p,  g_cnt);
    cudaGetSymbolAddress((void**)&deg_p,  g_deg);

    __nv_bfloat16 *wcomb_h, *wcomb_l, *whh_h, *whh_l;
    cudaGetSymbolAddress((void**)&wcomb_h, g_wcomb_h);
    cudaGetSymbolAddress((void**)&wcomb_l, g_wcomb_l);
    cudaGetSymbolAddress((void**)&whh_h,   g_whh_h);
    cudaGetSymbolAddress((void**)&whh_l,   g_whh_l);

    const int embed_smem = (FEAT * H + 64 * FEAT) * 4;  // 69120 B
    cudaFuncSetAttribute(embed_kernel,
                         cudaFuncAttributeMaxDynamicSharedMemorySize, embed_smem);
    cudaFuncSetAttribute(gemm_mma,
                         cudaFuncAttributeMaxDynamicSharedMemorySize, GEMM_SMEM);

    // side streams + events for capture-safe fork/join
    cudaStream_t s2, s3;
    cudaStreamCreateWithFlags(&s2, cudaStreamNonBlocking);
    cudaStreamCreateWithFlags(&s3, cudaStreamNonBlocking);
    cudaEvent_t evF, evJ, evK;
    cudaEventCreateWithFlags(&evF, cudaEventDisableTiming);
    cudaEventCreateWithFlags(&evJ, cudaEventDisableTiming);
    cudaEventCreateWithFlags(&evK, cudaEventDisableTiming);

    // ---- setup: CSR (stream 0) || weight prep (s2) || embed + pool memsets (s3)
    cudaEventRecord(evF, 0);
    cudaStreamWaitEvent(s2, evF, 0);
    cudaStreamWaitEvent(s3, evF, 0);

    prep_whh<<<(3 * H * H + 255) / 256, 256, 0, s2>>>(W_hh);
    prep_wcomb<<<(STEPS * 3 * H * H + 255) / 256, 256, 0, s2>>>(W_msg, W_ih);
    cudaEventRecord(evJ, s2);

    embed_kernel<<<M_PAD / 64, 128, embed_smem, s3>>>(x, W_emb);
    cudaMemsetAsync(pool_p, 0, N_GRAPHS * H * sizeof(float), s3);
    cudaMemsetAsync(cnt_p, 0, N_GRAPHS * sizeof(float), s3);
    cudaEventRecord(evK, s3);

    cudaMemsetAsync(deg_p, 0, N_NODES * sizeof(int));
    hist_kernel<<<(N_EDGES + 255) / 256, 256>>>(ei);
    scan_local<<<SCAN_BLOCKS, 256>>>();
    scan_bsum<<<1, 256>>>();
    scan_add<<<SCAN_BLOCKS, 256>>>();
    fill_kernel<<<(N_EDGES + 255) / 256, 256>>>(ei);
    cudaStreamWaitEvent(0, evJ, 0);
    cudaStreamWaitEvent(0, evK, 0);

    // ---- steps: gather (0) ∥ gh-GEMM (s2); join; gx-GEMM; gru (R7 schedule) ----
    for (int s = 0; s < STEPS; s++) {
        cudaEventRecord(evF, 0);
        cudaStreamWaitEvent(s2, evF, 0);
        gemm_mma<<<M_TILES, 512, GEMM_SMEM, s2>>>(h_p, whh_h, whh_l, b_hh, gh_p);
        cudaEventRecord(evJ, s2);

        gather_kernel<<<(N_NODES * 32 + 63) / 64, 64>>>();
        gemm_mma<<<M_TILES, 512, GEMM_SMEM>>>(
            agg_p, wcomb_h + (size_t)s * 3 * H * H, wcomb_l + (size_t)s * 3 * H * H,
            b_ih, gx_p);

        cudaStreamWaitEvent(0, evJ, 0);
        gru_kernel<<<(M_PAD * 32) / 256, 256>>>();
    }

    // ---- pooling + head ----
    pool_kernel<<<(N_NODES + 127) / 128, 128>>>(batch);
    head_kernel<<<N_GRAPHS, H>>>(W1, b1, W2, b2, out);

    cudaEventDestroy(evF);
    cudaEventDestroy(evJ);
    cudaEventDestroy(evK);
    cudaStreamDestroy(s2);
    cudaStreamDestroy(s3);
}

// round 15
// speedup vs baseline: 1.1639x; 1.0071x over previous
#include <cuda_runtime.h>
#include <cuda_bf16.h>
#include <math.h>
#include <stdint.h>

#define N_NODES  50000
#define N_EDGES  800000
#define FEAT     90
#define H        128
#define STEPS    4
#define N_GRAPHS 100
#define M_PAD    50048   // 128 * 391
#define M_TILES  (M_PAD / 128)
#define NOUT     384
#define SCAN_BLOCKS 196  // 196 * 256 = 50176 >= N_NODES

typedef unsigned long long u64;

// ---------------- device scratch ----------------
__device__ float g_h  [(size_t)M_PAD * H];
__device__ float g_agg[(size_t)M_PAD * H];
__device__ float g_gx [(size_t)M_PAD * 3 * H];
__device__ float g_gh [(size_t)M_PAD * 3 * H];
__device__ float g_pool[N_GRAPHS * H];
__device__ float g_cnt [N_GRAPHS];

// CSR for gather aggregation
__device__ int g_deg[N_NODES];
__device__ int g_off[N_NODES + 1];
__device__ int g_cur[N_NODES];
__device__ int g_eid[N_EDGES];
__device__ int g_bsum[SCAN_BLOCKS];

// bf16-split, transposed weights, layout [n][k]
__device__ __nv_bfloat16 g_wcomb_h[STEPS * 3 * H * H];  // W_msg[s] @ W_ih
__device__ __nv_bfloat16 g_wcomb_l[STEPS * 3 * H * H];
__device__ __nv_bfloat16 g_whh_h[3 * H * H];
__device__ __nv_bfloat16 g_whh_l[3 * H * H];

// ---------------- PTX helpers ----------------
__device__ __forceinline__ uint32_t smem_u32(const void* p) {
    uint32_t a;
    asm("{ .reg .u64 t; cvta.to.shared.u64 t, %1; cvt.u32.u64 %0, t; }" : "=r"(a) : "l"(p));
    return a;
}

__device__ __forceinline__ void ldsm_x4(uint32_t& r0, uint32_t& r1, uint32_t& r2, uint32_t& r3,
                                        uint32_t addr) {
    asm volatile("ldmatrix.sync.aligned.m8n8.x4.shared.b16 {%0,%1,%2,%3}, [%4];"
                 : "=r"(r0), "=r"(r1), "=r"(r2), "=r"(r3) : "r"(addr));
}

__device__ __forceinline__ void mma_bf16(float* c, const uint32_t* a, const uint32_t* b) {
    asm volatile(
        "mma.sync.aligned.m16n8k16.row.col.f32.bf16.bf16.f32 "
        "{%0,%1,%2,%3}, {%4,%5,%6,%7}, {%8,%9}, {%0,%1,%2,%3};"
        : "+f"(c[0]), "+f"(c[1]), "+f"(c[2]), "+f"(c[3])
        : "r"(a[0]), "r"(a[1]), "r"(a[2]), "r"(a[3]), "r"(b[0]), "r"(b[1]));
}

// swizzled tile offset: row r (0..127), 16B-chunk c (0..15); 256B rows
__device__ __forceinline__ uint32_t swz(int r, int c) {
    return (uint32_t)r * 256 + (uint32_t)((c ^ (r & 7)) << 4);
}

// fast activations (MUFU.EX2-based, rel err ~2^-21 — well within budget)
__device__ __forceinline__ float fsigmoid(float x) {
    return __fdividef(1.f, 1.f + __expf(-x));
}
__device__ __forceinline__ float ftanh(float x) {
    float e = __expf(2.f * x);
    return __fdividef(e - 1.f, e + 1.f);
}

// ---------------- CSR build ----------------
__global__ void hist_kernel(const int* __restrict__ ei) {
    int e = blockIdx.x * 256 + threadIdx.x;
    if (e < N_EDGES) atomicAdd(&g_deg[ei[N_EDGES + e]], 1);
}

// pass 1: per-block exclusive scan of deg; write local prefix + block sum
__global__ void scan_local() {
    __shared__ int wsum[8];
    const int tid = threadIdx.x, lane = tid & 31, w = tid >> 5;
    const int i = blockIdx.x * 256 + tid;
    int v = (i < N_NODES) ? g_deg[i] : 0;
    int x = v;
    #pragma unroll
    for (int d = 1; d < 32; d <<= 1) {
        int t = __shfl_up_sync(0xFFFFFFFFu, x, d);
        if (lane >= d) x += t;
    }
    if (lane == 31) wsum[w] = x;
    __syncthreads();
    if (w == 0 && lane < 8) {
        int y = wsum[lane];
        #pragma unroll
        for (int d = 1; d < 8; d <<= 1) {
            int t = __shfl_up_sync(0xFFu, y, d);
            if (lane >= d) y += t;
        }
        wsum[lane] = y;
    }
    __syncthreads();
    int woff = (w == 0) ? 0 : wsum[w - 1];
    if (i < N_NODES) g_off[i] = woff + x - v;       // local exclusive prefix
    if (tid == 255) g_bsum[blockIdx.x] = woff + x;  // block total
}

// pass 2: one block scans the 196 block sums (exclusive, in place)
__global__ void scan_bsum() {
    __shared__ int ws[8];
    const int tid = threadIdx.x, lane = tid & 31, w = tid >> 5;
    int v = (tid < SCAN_BLOCKS) ? g_bsum[tid] : 0;
    int x = v;
    #pragma unroll
    for (int d = 1; d < 32; d <<= 1) {
        int t = __shfl_up_sync(0xFFFFFFFFu, x, d);
        if (lane >= d) x += t;
    }
    if (lane == 31) ws[w] = x;
    __syncthreads();
    if (w == 0 && lane < 8) {
        int y = ws[lane];
        #pragma unroll
        for (int d = 1; d < 8; d <<= 1) {
            int t = __shfl_up_sync(0xFFu, y, d);
            if (lane >= d) y += t;
        }
        ws[lane] = y;
    }
    __syncthreads();
    int woff = (w == 0) ? 0 : ws[w - 1];
    if (tid < SCAN_BLOCKS) g_bsum[tid] = woff + x - v;   // exclusive
    if (tid == 0) g_off[N_NODES] = N_EDGES;
}

// pass 3: add block offsets, init cursor
__global__ void scan_add() {
    const int i = blockIdx.x * 256 + threadIdx.x;
    if (i >= N_NODES) return;
    int o = g_off[i] + g_bsum[blockIdx.x];
    g_off[i] = o;
    g_cur[i] = o;
}

__global__ void fill_kernel(const int* __restrict__ ei) {
    int e = blockIdx.x * 256 + threadIdx.x;
    if (e < N_EDGES) {
        int dst = ei[N_EDGES + e];
        int pos = atomicAdd(&g_cur[dst], 1);
        g_eid[pos] = ei[e];
    }
}

// ---------------- gather: agg[n] = sum_{e: dst=n} h[src[e]] ----------------
// 64-thread blocks (2 warps) for finer load balancing across skewed degrees.
__global__ void gather_kernel() {
    const int node = (blockIdx.x * 64 + threadIdx.x) >> 5;
    if (node >= N_NODES) return;
    const int lane = threadIdx.x & 31;
    const int beg = g_off[node], end = g_off[node + 1];
    float4 acc = make_float4(0.f, 0.f, 0.f, 0.f);
    #pragma unroll 4
    for (int e = beg; e < end; e++) {
        int src = __ldg(&g_eid[e]);
        float4 v = *(const float4*)(g_h + (size_t)src * H + lane * 4);
        acc.x += v.x; acc.y += v.y; acc.z += v.z; acc.w += v.w;
    }
    *(float4*)(g_agg + (size_t)node * H + lane * 4) = acc;
}

// ---------------- weight prep ----------------
__global__ void prep_whh(const float* __restrict__ Whh) {
    int j = blockIdx.x * 256 + threadIdx.x;
    if (j >= 3 * H * H) return;
    int n = j >> 7, k = j & 127;
    float v = Whh[k * 384 + n];
    __nv_bfloat16 hi = __float2bfloat16(v);
    __nv_bfloat16 lo = __float2bfloat16(v - __bfloat162float(hi));
    g_whh_h[j] = hi; g_whh_l[j] = lo;
}

__global__ void prep_wcomb(const float* __restrict__ Wmsg,
                           const float* __restrict__ Wih) {
    int i = blockIdx.x * 256 + threadIdx.x;
    if (i >= STEPS * 3 * H * H) return;
    int s = i / (3 * H * H);
    int r = i % (3 * H * H);
    int k = r / 384;
    int n = r % 384;
    const float* wm = Wmsg + (s << 14) + k * H;
    float acc = 0.f;
    #pragma unroll 8
    for (int j = 0; j < H; j++) acc = fmaf(wm[j], Wih[j * 384 + n], acc);
    __nv_bfloat16 hi = __float2bfloat16(acc);
    __nv_bfloat16 lo = __float2bfloat16(acc - __bfloat162float(hi));
    size_t o = (size_t)s * 3 * H * H + (size_t)n * H + k;
    g_wcomb_h[o] = hi; g_wcomb_l[o] = lo;
}

// ---------------- mma.sync GEMM: C[M_PAD,384] = A[M_PAD,128] @ W[128,384] + b --
// bf16x3: C = Ah*Bh + Ah*Bl + Al*Bh (fp32 accum). 512 thr, warp tile m32 x n32.
// Prologue merges A + B-tile-0 loads; term-outer mma ordering for accumulator ILP.
#define SM_A_H 0
#define SM_A_L 32768
#define SM_B_H 65536
#define SM_B_L 98304
#define SM_BIAS 131072
#define GEMM_SMEM (131072 + 1536)

__global__ void __launch_bounds__(512, 1) gemm_mma(
        const float* __restrict__ A,
        const __nv_bfloat16* __restrict__ Bh, const __nv_bfloat16* __restrict__ Bl,
        const float* __restrict__ bias, float* __restrict__ C) {
    extern __shared__ char smem[];
    const uint32_t sbase = smem_u32(smem);
    const int tid = threadIdx.x;
    const int wid = tid >> 5;
    const int lane = tid & 31;
    const int m0 = blockIdx.x * 128;

    // ---- load A tile (128x128 fp32), split to bf16 hi/lo, swizzled store ----
    {
        const float* Ab = A + (size_t)m0 * 128;
        #pragma unroll
        for (int it = 0; it < 8; it++) {
            int idx = it * 512 + tid;          // 0..4095
            int row = idx >> 5;
            int q = idx & 31;                  // float4 index; k0 = q*4
            float4 v = *(const float4*)(Ab + row * 128 + q * 4);
            __nv_bfloat16 h0 = __float2bfloat16(v.x);
            __nv_bfloat16 h1 = __float2bfloat16(v.y);
            __nv_bfloat16 h2 = __float2bfloat16(v.z);
            __nv_bfloat16 h3 = __float2bfloat16(v.w);
            __nv_bfloat16 l0 = __float2bfloat16(v.x - __bfloat162float(h0));
            __nv_bfloat16 l1 = __float2bfloat16(v.y - __bfloat162float(h1));
            __nv_bfloat16 l2 = __float2bfloat16(v.z - __bfloat162float(h2));
            __nv_bfloat16 l3 = __float2bfloat16(v.w - __bfloat162float(h3));
            uint32_t off = swz(row, q >> 1) + (q & 1) * 8;
            uint2 hw, lw;
            hw.x = (uint32_t)__bfloat16_as_ushort(h0) | ((uint32_t)__bfloat16_as_ushort(h1) << 16);
            hw.y = (uint32_t)__bfloat16_as_ushort(h2) | ((uint32_t)__bfloat16_as_ushort(h3) << 16);
            lw.x = (uint32_t)__bfloat16_as_ushort(l0) | ((uint32_t)__bfloat16_as_ushort(l1) << 16);
            lw.y = (uint32_t)__bfloat16_as_ushort(l2) | ((uint32_t)__bfloat16_as_ushort(l3) << 16);
            *(uint2*)(smem + SM_A_H + off) = hw;
            *(uint2*)(smem + SM_A_L + off) = lw;
        }
    }
    // ---- bias -> smem ----
    for (int i = tid; i < NOUT; i += 512)
        *(float*)(smem + SM_BIAS + i * 4) = bias[i];
    // ---- B tile 0 -> smem (merged with A prologue; one sync covers both) ----
    {
        #pragma unroll
        for (int it = 0; it < 4; it++) {
            int idx = it * 512 + tid;
            int row = idx >> 4;
            int c = idx & 15;
            uint32_t off = swz(row, c);
            *(uint4*)(smem + SM_B_H + off) = *(const uint4*)(Bh + row * 128 + c * 8);
            *(uint4*)(smem + SM_B_L + off) = *(const uint4*)(Bl + row * 128 + c * 8);
        }
    }

    const int wm = (wid & 3) * 32;          // warp row offset
    const int wn = (wid >> 2) * 32;         // warp col offset within tile

    #pragma unroll
    for (int nt = 0; nt < 3; nt++) {
        __syncthreads();   // A/bias/B(nt) visible

        // ---- compute: 8 k-steps, warp tile m32 x n32 ----
        float acc[2][4][4];
        #pragma unroll
        for (int mi = 0; mi < 2; mi++)
            #pragma unroll
            for (int ni = 0; ni < 4; ni++)
                #pragma unroll
                for (int j = 0; j < 4; j++) acc[mi][ni][j] = 0.f;

        #pragma unroll
        for (int ks = 0; ks < 8; ks++) {
            const int c0 = ks * 2;
            uint32_t ah[2][4], al[2][4], bh[4][2], bl[4][2];
            {
                int arow = (lane & 15);
                int ac = c0 + (lane >> 4);
                #pragma unroll
                for (int mi = 0; mi < 2; mi++) {
                    uint32_t o = swz(wm + mi * 16 + arow, ac);
                    ldsm_x4(ah[mi][0], ah[mi][1], ah[mi][2], ah[mi][3], sbase + SM_A_H + o);
                    ldsm_x4(al[mi][0], al[mi][1], al[mi][2], al[mi][3], sbase + SM_A_L + o);
                }
            }
            {
                int brow = ((lane >> 4) << 3) + (lane & 7);
                int bc = c0 + ((lane >> 3) & 1);
                #pragma unroll
                for (int nj = 0; nj < 2; nj++) {
                    uint32_t o = swz(wn + nj * 16 + brow, bc);
                    uint32_t t0, t1, t2, t3;
                    ldsm_x4(t0, t1, t2, t3, sbase + SM_B_H + o);
                    bh[nj * 2][0] = t0; bh[nj * 2][1] = t1;
                    bh[nj * 2 + 1][0] = t2; bh[nj * 2 + 1][1] = t3;
                    ldsm_x4(t0, t1, t2, t3, sbase + SM_B_L + o);
                    bl[nj * 2][0] = t0; bl[nj * 2][1] = t1;
                    bl[nj * 2 + 1][0] = t2; bl[nj * 2 + 1][1] = t3;
                }
            }
            // term-outer ordering: consecutive mmas hit different accumulators
            #pragma unroll
            for (int mi = 0; mi < 2; mi++)
                #pragma unroll
                for (int ni = 0; ni < 4; ni++)
                    mma_bf16(acc[mi][ni], ah[mi], bh[ni]);
            #pragma unroll
            for (int mi = 0; mi < 2; mi++)
                #pragma unroll
                for (int ni = 0; ni < 4; ni++)
                    mma_bf16(acc[mi][ni], ah[mi], bl[ni]);
            #pragma unroll
            for (int mi = 0; mi < 2; mi++)
                #pragma unroll
                for (int ni = 0; ni < 4; ni++)
                    mma_bf16(acc[mi][ni], al[mi], bh[ni]);
        }

        // ---- epilogue ----
        {
            const int r0 = m0 + wm + (lane >> 2);
            const int cb = nt * 128 + wn + (lane & 3) * 2;
            #pragma unroll
            for (int mi = 0; mi < 2; mi++) {
                #pragma unroll
                for (int ni = 0; ni < 4; ni++) {
                    int col = cb + ni * 8;
                    float2 bb = *(const float2*)(smem + SM_BIAS + col * 4);
                    float* c0p = C + (size_t)(r0 + mi * 16) * NOUT + col;
                    float* c1p = C + (size_t)(r0 + mi * 16 + 8) * NOUT + col;
                    *(float2*)c0p = make_float2(acc[mi][ni][0] + bb.x, acc[mi][ni][1] + bb.y);
                    *(float2*)c1p = make_float2(acc[mi][ni][2] + bb.x, acc[mi][ni][3] + bb.y);
                }
            }
        }

        // ---- load next B tile (sync: all warps done reading B(nt)) ----
        if (nt < 2) {
            __syncthreads();
            const __nv_bfloat16* bh = Bh + (size_t)(nt + 1) * 128 * 128;
            const __nv_bfloat16* bl = Bl + (size_t)(nt + 1) * 128 * 128;
            #pragma unroll
            for (int it = 0; it < 4; it++) {
                int idx = it * 512 + tid;
                int row = idx >> 4;
                int c = idx & 15;
                uint32_t off = swz(row, c);
                *(uint4*)(smem + SM_B_H + off) = *(const uint4*)(bh + row * 128 + c * 8);
                *(uint4*)(smem + SM_B_L + off) = *(const uint4*)(bl + row * 128 + c * 8);
            }
        }
    }
}

// ---------------- embedding: h = relu(x @ W_emb), K=90, 64 nodes per block ----
__global__ void embed_kernel(const float* __restrict__ x,
                             const float* __restrict__ Wemb) {
    extern __shared__ float sm[];
    float* Ws = sm;               // FEAT*H
    float* xs = sm + FEAT * H;    // 64*FEAT
    const int tid = threadIdx.x;
    for (int i = tid; i < FEAT * H; i += 128) Ws[i] = Wemb[i];
    const int n0 = blockIdx.x * 64;
    for (int i = tid; i < 64 * FEAT; i += 128) {
        int r = i / FEAT, cc = i - r * FEAT;
        int n = n0 + r;
        xs[i] = (n < N_NODES) ? x[(size_t)n * FEAT + cc] : 0.f;
    }
    __syncthreads();
    const int c = tid;
    for (int r = 0; r < 64; r++) {
        float acc = 0.f;
        const float* xr = xs + r * FEAT;
        #pragma unroll 6
        for (int k = 0; k < FEAT; k++) acc = fmaf(xr[k], Ws[k * H + c], acc);
        g_h[(size_t)(n0 + r) * H + c] = fmaxf(acc, 0.f);
    }
}

// ---------------- GRU elementwise (float4 vectorized, fast activations) ------
__global__ void gru_kernel() {
    const int v = blockIdx.x * blockDim.x + threadIdx.x;  // vec4 index, < M_PAD*32
    const int node = v >> 5;
    const int c4 = (v & 31) * 4;
    const size_t gb = (size_t)node * 384 + c4;
    const size_t hb = (size_t)node * 128 + c4;
    float4 xr = *(const float4*)&g_gx[gb];
    float4 xz = *(const float4*)&g_gx[gb + 128];
    float4 xn = *(const float4*)&g_gx[gb + 256];
    float4 hr = *(const float4*)&g_gh[gb];
    float4 hz = *(const float4*)&g_gh[gb + 128];
    float4 hn = *(const float4*)&g_gh[gb + 256];
    float4 hv = *(const float4*)&g_h[hb];
    float4 o;
    {
        float r = fsigmoid(xr.x + hr.x), z = fsigmoid(xz.x + hz.x);
        float nn = ftanh(xn.x + r * hn.x);
        o.x = (1.f - z) * nn + z * hv.x;
    }
    {
        float r = fsigmoid(xr.y + hr.y), z = fsigmoid(xz.y + hz.y);
        float nn = ftanh(xn.y + r * hn.y);
        o.y = (1.f - z) * nn + z * hv.y;
    }
    {
        float r = fsigmoid(xr.z + hr.z), z = fsigmoid(xz.z + hz.z);
        float nn = ftanh(xn.z + r * hn.z);
        o.z = (1.f - z) * nn + z * hv.z;
    }
    {
        float r = fsigmoid(xr.w + hr.w), z = fsigmoid(xz.w + hz.w);
        float nn = ftanh(xn.w + r * hn.w);
        o.w = (1.f - z) * nn + z * hv.w;
    }
    *(float4*)&g_h[hb] = o;
}

// ---------------- pooling: sum relu(h) per graph (batch sorted) --------------
// 128 nodes per block (391 blocks) for shorter serial runs + better waves.
__global__ void pool_kernel(const int* __restrict__ batch) {
    __shared__ int bs[128];
    const int tid = threadIdx.x;        // 128 threads, one column each
    const int n0 = blockIdx.x * 128;
    const int cnt = min(128, N_NODES - n0);
    if (cnt <= 0) return;
    if (tid < cnt) bs[tid] = batch[n0 + tid];
    __syncthreads();
    const int c = tid;
    float sum = 0.f;
    int cur = bs[0];
    int run = 0;
    for (int i = 0; i < cnt; i++) {
        int b = bs[i];
        if (b != cur) {
            atomicAdd(&g_pool[cur * H + c], sum);
            if (c == 0) atomicAdd(&g_cnt[cur], (float)run);
            sum = 0.f; run = 0; cur = b;
        }
        sum += fmaxf(g_h[(size_t)(n0 + i) * H + c], 0.f);
        run++;
    }
    atomicAdd(&g_pool[cur * H + c], sum);
    if (c == 0) atomicAdd(&g_cnt[cur], (float)run);
}

// ---------------- head: mean -> Linear+ReLU -> Linear -> softplus ------------
__global__ void head_kernel(const float* __restrict__ W1, const float* __restrict__ b1,
                            const float* __restrict__ W2, const float* __restrict__ b2,
                            float* __restrict__ out) {
    __shared__ float ps[H];
    __shared__ float hs[H];
    const int g = blockIdx.x, c = threadIdx.x;
    float cnt = fmaxf(g_cnt[g], 1.f);
    ps[c] = g_pool[g * H + c] / cnt;
    __syncthreads();
    float acc = b1[c];
    #pragma unroll 8
    for (int k = 0; k < H; k++) acc = fmaf(ps[k], W1[k * H + c], acc);
    hs[c] = fmaxf(acc, 0.f) * W2[c];
    __syncthreads();
    for (int s = 64; s > 0; s >>= 1) {
        if (c < s) hs[c] += hs[c + s];
        __syncthreads();
    }
    if (c == 0) {
        float xv = hs[0] + b2[0];
        out[g] = (xv > 0.f) ? (xv + log1pf(expf(-xv))) : log1pf(expf(xv));
    }
}

// ---------------- launch ------------------------------------------------------
extern "C" void kernel_launch(void* const* d_in, const int* in_sizes, int n_in,
                              void* d_out, int out_size) {
    const float* x     = (const float*)d_in[0];
    const int*   ei    = (const int*)d_in[1];
    const int*   batch = (const int*)d_in[2];
    const float* W_emb = (const float*)d_in[3];
    const float* W_msg = (const float*)d_in[4];
    const float* W_ih  = (const float*)d_in[5];
    const float* W_hh  = (const float*)d_in[6];
    const float* b_ih  = (const float*)d_in[7];
    const float* b_hh  = (const float*)d_in[8];
    const float* W1    = (const float*)d_in[9];
    const float* b1    = (const float*)d_in[10];
    const float* W2    = (const float*)d_in[11];
    const float* b2    = (const float*)d_in[12];
    float* out = (float*)d_out;

    float *h_p, *agg_p, *gx_p, *gh_p, *pool_p, *cnt_p;
    int* deg_p;
    cudaGetSymbolAddress((void**)&h_p,   g_h);
    cudaGetSymbolAddress((void**)&agg_p, g_agg);
    cudaGetSymbolAddress((void**)&gx_p,  g_gx);
    cudaGetSymbolAddress((void**)&gh_p,  g_gh);
    cudaGetSymbolAddress((void**)&pool_p, g_pool);
    cudaGetSymbolAddress((void**)&cnt_p,  g_cnt);
    cudaGetSymbolAddress((void**)&deg_p,  g_deg);

    __nv_bfloat16 *wcomb_h, *wcomb_l, *whh_h, *whh_l;
    cudaGetSymbolAddress((void**)&wcomb_h, g_wcomb_h);
    cudaGetSymbolAddress((void**)&wcomb_l, g_wcomb_l);
    cudaGetSymbolAddress((void**)&whh_h,   g_whh_h);
    cudaGetSymbolAddress((void**)&whh_l,   g_whh_l);

    const int embed_smem = (FEAT * H + 64 * FEAT) * 4;  // 69120 B
    cudaFuncSetAttribute(embed_kernel,
                         cudaFuncAttributeMaxDynamicSharedMemorySize, embed_smem);
    cudaFuncSetAttribute(gemm_mma,
                         cudaFuncAttributeMaxDynamicSharedMemorySize, GEMM_SMEM);

    // side streams + events for capture-safe fork/join
    cudaStream_t s2, s3;
    cudaStreamCreateWithFlags(&s2, cudaStreamNonBlocking);
    cudaStreamCreateWithFlags(&s3, cudaStreamNonBlocking);
    cudaEvent_t evF, evJ, evK;
    cudaEventCreateWithFlags(&evF, cudaEventDisableTiming);
    cudaEventCreateWithFlags(&evJ, cudaEventDisableTiming);
    cudaEventCreateWithFlags(&evK, cudaEventDisableTiming);

    // ---- setup: CSR (stream 0) || weight prep (s2) || embed + pool memsets (s3)
    cudaEventRecord(evF, 0);
    cudaStreamWaitEvent(s2, evF, 0);
    cudaStreamWaitEvent(s3, evF, 0);

    prep_whh<<<(3 * H * H + 255) / 256, 256, 0, s2>>>(W_hh);
    prep_wcomb<<<(STEPS * 3 * H * H + 255) / 256, 256, 0, s2>>>(W_msg, W_ih);
    cudaEventRecord(evJ, s2);

    embed_kernel<<<M_PAD / 64, 128, embed_smem, s3>>>(x, W_emb);
    cudaMemsetAsync(pool_p, 0, N_GRAPHS * H * sizeof(float), s3);
    cudaMemsetAsync(cnt_p, 0, N_GRAPHS * sizeof(float), s3);
    cudaEventRecord(evK, s3);

    cudaMemsetAsync(deg_p, 0, N_NODES * sizeof(int));
    hist_kernel<<<(N_EDGES + 255) / 256, 256>>>(ei);
    scan_local<<<SCAN_BLOCKS, 256>>>();
    scan_bsum<<<1, 256>>>();
    scan_add<<<SCAN_BLOCKS, 256>>>();
    fill_kernel<<<(N_EDGES + 255) / 256, 256>>>(ei);
    cudaStreamWaitEvent(0, evJ, 0);
    cudaStreamWaitEvent(0, evK, 0);

    // ---- steps: gather (0) ∥ gh-GEMM (s2); join; gx-GEMM; gru (R7 schedule) ----
    for (int s = 0; s < STEPS; s++) {
        cudaEventRecord(evF, 0);
        cudaStreamWaitEvent(s2, evF, 0);
        gemm_mma<<<M_TILES, 512, GEMM_SMEM, s2>>>(h_p, whh_h, whh_l, b_hh, gh_p);
        cudaEventRecord(evJ, s2);

        gather_kernel<<<(N_NODES * 32 + 63) / 64, 64>>>();
        gemm_mma<<<M_TILES, 512, GEMM_SMEM>>>(
            agg_p, wcomb_h + (size_t)s * 3 * H * H, wcomb_l + (size_t)s * 3 * H * H,
            b_ih, gx_p);

        cudaStreamWaitEvent(0, evJ, 0);
        gru_kernel<<<(M_PAD * 32) / 256, 256>>>();
    }

    // ---- pooling + head ----
    pool_kernel<<<(N_NODES + 127) / 128, 128>>>(batch);
    head_kernel<<<N_GRAPHS, H>>>(W1, b1, W2, b2, out);

    cudaEventDestroy(evF);
    cudaEventDestroy(evJ);
    cudaEventDestroy(evK);
    cudaStreamDestroy(s2);
    cudaStreamDestroy(s3);
}

// round 16
// speedup vs baseline: 1.2312x; 1.0578x over previous
#include <cuda_runtime.h>
#include <cuda_bf16.h>
#include <cuda_fp16.h>
#include <math.h>
#include <stdint.h>

#define N_NODES  50000
#define N_EDGES  800000
#define FEAT     90
#define H        128
#define STEPS    4
#define N_GRAPHS 100
#define M_PAD    50048   // 128 * 391
#define M_TILES  (M_PAD / 128)
#define NOUT     384
#define SCAN_BLOCKS 196  // 196 * 256 = 50176 >= N_NODES

typedef unsigned long long u64;

// ---------------- device scratch ----------------
__device__ float  g_h  [(size_t)M_PAD * H];
__device__ float  g_agg[(size_t)M_PAD * H];
__device__ __half g_gx [(size_t)M_PAD * 3 * H];   // fp16 gate pre-activations
__device__ __half g_gh [(size_t)M_PAD * 3 * H];
__device__ float  g_pool[N_GRAPHS * H];
__device__ float  g_cnt [N_GRAPHS];

// CSR for gather aggregation
__device__ int g_deg[N_NODES];
__device__ int g_off[N_NODES + 1];
__device__ int g_cur[N_NODES];
__device__ int g_eid[N_EDGES];
__device__ int g_bsum[SCAN_BLOCKS];

// bf16-split, transposed weights, layout [n][k]
__device__ __nv_bfloat16 g_wcomb_h[STEPS * 3 * H * H];  // W_msg[s] @ W_ih
__device__ __nv_bfloat16 g_wcomb_l[STEPS * 3 * H * H];
__device__ __nv_bfloat16 g_whh_h[3 * H * H];
__device__ __nv_bfloat16 g_whh_l[3 * H * H];

// ---------------- PTX helpers ----------------
__device__ __forceinline__ uint32_t smem_u32(const void* p) {
    uint32_t a;
    asm("{ .reg .u64 t; cvta.to.shared.u64 t, %1; cvt.u32.u64 %0, t; }" : "=r"(a) : "l"(p));
    return a;
}

__device__ __forceinline__ void ldsm_x4(uint32_t& r0, uint32_t& r1, uint32_t& r2, uint32_t& r3,
                                        uint32_t addr) {
    asm volatile("ldmatrix.sync.aligned.m8n8.x4.shared.b16 {%0,%1,%2,%3}, [%4];"
                 : "=r"(r0), "=r"(r1), "=r"(r2), "=r"(r3) : "r"(addr));
}

__device__ __forceinline__ void mma_bf16(float* c, const uint32_t* a, const uint32_t* b) {
    asm volatile(
        "mma.sync.aligned.m16n8k16.row.col.f32.bf16.bf16.f32 "
        "{%0,%1,%2,%3}, {%4,%5,%6,%7}, {%8,%9}, {%0,%1,%2,%3};"
        : "+f"(c[0]), "+f"(c[1]), "+f"(c[2]), "+f"(c[3])
        : "r"(a[0]), "r"(a[1]), "r"(a[2]), "r"(a[3]), "r"(b[0]), "r"(b[1]));
}

// swizzled tile offset: row r (0..127), 16B-chunk c (0..15); 256B rows
__device__ __forceinline__ uint32_t swz(int r, int c) {
    return (uint32_t)r * 256 + (uint32_t)((c ^ (r & 7)) << 4);
}

// fast activations (MUFU.EX2-based, rel err ~2^-21 — well within budget)
__device__ __forceinline__ float fsigmoid(float x) {
    return __fdividef(1.f, 1.f + __expf(-x));
}
__device__ __forceinline__ float ftanh(float x) {
    float e = __expf(2.f * x);
    return __fdividef(e - 1.f, e + 1.f);
}

// ---------------- CSR build ----------------
__global__ void hist_kernel(const int* __restrict__ ei) {
    int e = blockIdx.x * 256 + threadIdx.x;
    if (e < N_EDGES) atomicAdd(&g_deg[ei[N_EDGES + e]], 1);
}

// pass 1: per-block exclusive scan of deg; write local prefix + block sum
__global__ void scan_local() {
    __shared__ int wsum[8];
    const int tid = threadIdx.x, lane = tid & 31, w = tid >> 5;
    const int i = blockIdx.x * 256 + tid;
    int v = (i < N_NODES) ? g_deg[i] : 0;
    int x = v;
    #pragma unroll
    for (int d = 1; d < 32; d <<= 1) {
        int t = __shfl_up_sync(0xFFFFFFFFu, x, d);
        if (lane >= d) x += t;
    }
    if (lane == 31) wsum[w] = x;
    __syncthreads();
    if (w == 0 && lane < 8) {
        int y = wsum[lane];
        #pragma unroll
        for (int d = 1; d < 8; d <<= 1) {
            int t = __shfl_up_sync(0xFFu, y, d);
            if (lane >= d) y += t;
        }
        wsum[lane] = y;
    }
    __syncthreads();
    int woff = (w == 0) ? 0 : wsum[w - 1];
    if (i < N_NODES) g_off[i] = woff + x - v;       // local exclusive prefix
    if (tid == 255) g_bsum[blockIdx.x] = woff + x;  // block total
}

// pass 2: one block scans the 196 block sums (exclusive, in place)
__global__ void scan_bsum() {
    __shared__ int ws[8];
    const int tid = threadIdx.x, lane = tid & 31, w = tid >> 5;
    int v = (tid < SCAN_BLOCKS) ? g_bsum[tid] : 0;
    int x = v;
    #pragma unroll
    for (int d = 1; d < 32; d <<= 1) {
        int t = __shfl_up_sync(0xFFFFFFFFu, x, d);
        if (lane >= d) x += t;
    }
    if (lane == 31) ws[w] = x;
    __syncthreads();
    if (w == 0 && lane < 8) {
        int y = ws[lane];
        #pragma unroll
        for (int d = 1; d < 8; d <<= 1) {
            int t = __shfl_up_sync(0xFFu, y, d);
            if (lane >= d) y += t;
        }
        ws[lane] = y;
    }
    __syncthreads();
    int woff = (w == 0) ? 0 : ws[w - 1];
    if (tid < SCAN_BLOCKS) g_bsum[tid] = woff + x - v;   // exclusive
    if (tid == 0) g_off[N_NODES] = N_EDGES;
}

// pass 3: add block offsets, init cursor
__global__ void scan_add() {
    const int i = blockIdx.x * 256 + threadIdx.x;
    if (i >= N_NODES) return;
    int o = g_off[i] + g_bsum[blockIdx.x];
    g_off[i] = o;
    g_cur[i] = o;
}

__global__ void fill_kernel(const int* __restrict__ ei) {
    int e = blockIdx.x * 256 + threadIdx.x;
    if (e < N_EDGES) {
        int dst = ei[N_EDGES + e];
        int pos = atomicAdd(&g_cur[dst], 1);
        g_eid[pos] = ei[e];
    }
}

// ---------------- gather: agg[n] = sum_{e: dst=n} h[src[e]] ----------------
// 64-thread blocks (2 warps) for finer load balancing across skewed degrees.
__global__ void gather_kernel() {
    const int node = (blockIdx.x * 64 + threadIdx.x) >> 5;
    if (node >= N_NODES) return;
    const int lane = threadIdx.x & 31;
    const int beg = g_off[node], end = g_off[node + 1];
    float4 acc = make_float4(0.f, 0.f, 0.f, 0.f);
    #pragma unroll 4
    for (int e = beg; e < end; e++) {
        int src = __ldg(&g_eid[e]);
        float4 v = *(const float4*)(g_h + (size_t)src * H + lane * 4);
        acc.x += v.x; acc.y += v.y; acc.z += v.z; acc.w += v.w;
    }
    *(float4*)(g_agg + (size_t)node * H + lane * 4) = acc;
}

// ---------------- weight prep ----------------
__global__ void prep_whh(const float* __restrict__ Whh) {
    int j = blockIdx.x * 256 + threadIdx.x;
    if (j >= 3 * H * H) return;
    int n = j >> 7, k = j & 127;
    float v = Whh[k * 384 + n];
    __nv_bfloat16 hi = __float2bfloat16(v);
    __nv_bfloat16 lo = __float2bfloat16(v - __bfloat162float(hi));
    g_whh_h[j] = hi; g_whh_l[j] = lo;
}

__global__ void prep_wcomb(const float* __restrict__ Wmsg,
                           const float* __restrict__ Wih) {
    int i = blockIdx.x * 256 + threadIdx.x;
    if (i >= STEPS * 3 * H * H) return;
    int s = i / (3 * H * H);
    int r = i % (3 * H * H);
    int k = r / 384;
    int n = r % 384;
    const float* wm = Wmsg + (s << 14) + k * H;
    float acc = 0.f;
    #pragma unroll 8
    for (int j = 0; j < H; j++) acc = fmaf(wm[j], Wih[j * 384 + n], acc);
    __nv_bfloat16 hi = __float2bfloat16(acc);
    __nv_bfloat16 lo = __float2bfloat16(acc - __bfloat162float(hi));
    size_t o = (size_t)s * 3 * H * H + (size_t)n * H + k;
    g_wcomb_h[o] = hi; g_wcomb_l[o] = lo;
}

// ---------------- mma.sync GEMM: C[M_PAD,384] = A[M_PAD,128] @ W[128,384] + b --
// bf16x3: C = Ah*Bh + Ah*Bl + Al*Bh (fp32 accum), fp16 output (gate pre-acts).
// 512 thr, warp tile m32 x n32. Prologue merges A + B-tile-0 loads.
#define SM_A_H 0
#define SM_A_L 32768
#define SM_B_H 65536
#define SM_B_L 98304
#define SM_BIAS 131072
#define GEMM_SMEM (131072 + 1536)

__global__ void __launch_bounds__(512, 1) gemm_mma(
        const float* __restrict__ A,
        const __nv_bfloat16* __restrict__ Bh, const __nv_bfloat16* __restrict__ Bl,
        const float* __restrict__ bias, __half* __restrict__ C) {
    extern __shared__ char smem[];
    const uint32_t sbase = smem_u32(smem);
    const int tid = threadIdx.x;
    const int wid = tid >> 5;
    const int lane = tid & 31;
    const int m0 = blockIdx.x * 128;

    // ---- load A tile (128x128 fp32), split to bf16 hi/lo, swizzled store ----
    {
        const float* Ab = A + (size_t)m0 * 128;
        #pragma unroll
        for (int it = 0; it < 8; it++) {
            int idx = it * 512 + tid;          // 0..4095
            int row = idx >> 5;
            int q = idx & 31;                  // float4 index; k0 = q*4
            float4 v = *(const float4*)(Ab + row * 128 + q * 4);
            __nv_bfloat16 h0 = __float2bfloat16(v.x);
            __nv_bfloat16 h1 = __float2bfloat16(v.y);
            __nv_bfloat16 h2 = __float2bfloat16(v.z);
            __nv_bfloat16 h3 = __float2bfloat16(v.w);
            __nv_bfloat16 l0 = __float2bfloat16(v.x - __bfloat162float(h0));
            __nv_bfloat16 l1 = __float2bfloat16(v.y - __bfloat162float(h1));
            __nv_bfloat16 l2 = __float2bfloat16(v.z - __bfloat162float(h2));
            __nv_bfloat16 l3 = __float2bfloat16(v.w - __bfloat162float(h3));
            uint32_t off = swz(row, q >> 1) + (q & 1) * 8;
            uint2 hw, lw;
            hw.x = (uint32_t)__bfloat16_as_ushort(h0) | ((uint32_t)__bfloat16_as_ushort(h1) << 16);
            hw.y = (uint32_t)__bfloat16_as_ushort(h2) | ((uint32_t)__bfloat16_as_ushort(h3) << 16);
            lw.x = (uint32_t)__bfloat16_as_ushort(l0) | ((uint32_t)__bfloat16_as_ushort(l1) << 16);
            lw.y = (uint32_t)__bfloat16_as_ushort(l2) | ((uint32_t)__bfloat16_as_ushort(l3) << 16);
            *(uint2*)(smem + SM_A_H + off) = hw;
            *(uint2*)(smem + SM_A_L + off) = lw;
        }
    }
    // ---- bias -> smem ----
    for (int i = tid; i < NOUT; i += 512)
        *(float*)(smem + SM_BIAS + i * 4) = bias[i];
    // ---- B tile 0 -> smem (merged with A prologue; one sync covers both) ----
    {
        #pragma unroll
        for (int it = 0; it < 4; it++) {
            int idx = it * 512 + tid;
            int row = idx >> 4;
            int c = idx & 15;
            uint32_t off = swz(row, c);
            *(uint4*)(smem + SM_B_H + off) = *(const uint4*)(Bh + row * 128 + c * 8);
            *(uint4*)(smem + SM_B_L + off) = *(const uint4*)(Bl + row * 128 + c * 8);
        }
    }

    const int wm = (wid & 3) * 32;          // warp row offset
    const int wn = (wid >> 2) * 32;         // warp col offset within tile

    #pragma unroll
    for (int nt = 0; nt < 3; nt++) {
        __syncthreads();   // A/bias/B(nt) visible

        // ---- compute: 8 k-steps, warp tile m32 x n32 ----
        float acc[2][4][4];
        #pragma unroll
        for (int mi = 0; mi < 2; mi++)
            #pragma unroll
            for (int ni = 0; ni < 4; ni++)
                #pragma unroll
                for (int j = 0; j < 4; j++) acc[mi][ni][j] = 0.f;

        #pragma unroll
        for (int ks = 0; ks < 8; ks++) {
            const int c0 = ks * 2;
            uint32_t ah[2][4], al[2][4], bh[4][2], bl[4][2];
            {
                int arow = (lane & 15);
                int ac = c0 + (lane >> 4);
                #pragma unroll
                for (int mi = 0; mi < 2; mi++) {
                    uint32_t o = swz(wm + mi * 16 + arow, ac);
                    ldsm_x4(ah[mi][0], ah[mi][1], ah[mi][2], ah[mi][3], sbase + SM_A_H + o);
                    ldsm_x4(al[mi][0], al[mi][1], al[mi][2], al[mi][3], sbase + SM_A_L + o);
                }
            }
            {
                int brow = ((lane >> 4) << 3) + (lane & 7);
                int bc = c0 + ((lane >> 3) & 1);
                #pragma unroll
                for (int nj = 0; nj < 2; nj++) {
                    uint32_t o = swz(wn + nj * 16 + brow, bc);
                    uint32_t t0, t1, t2, t3;
                    ldsm_x4(t0, t1, t2, t3, sbase + SM_B_H + o);
                    bh[nj * 2][0] = t0; bh[nj * 2][1] = t1;
                    bh[nj * 2 + 1][0] = t2; bh[nj * 2 + 1][1] = t3;
                    ldsm_x4(t0, t1, t2, t3, sbase + SM_B_L + o);
                    bl[nj * 2][0] = t0; bl[nj * 2][1] = t1;
                    bl[nj * 2 + 1][0] = t2; bl[nj * 2 + 1][1] = t3;
                }
            }
            // term-outer ordering: consecutive mmas hit different accumulators
            #pragma unroll
            for (int mi = 0; mi < 2; mi++)
                #pragma unroll
                for (int ni = 0; ni < 4; ni++)
                    mma_bf16(acc[mi][ni], ah[mi], bh[ni]);
            #pragma unroll
            for (int mi = 0; mi < 2; mi++)
                #pragma unroll
                for (int ni = 0; ni < 4; ni++)
                    mma_bf16(acc[mi][ni], ah[mi], bl[ni]);
            #pragma unroll
            for (int mi = 0; mi < 2; mi++)
                #pragma unroll
                for (int ni = 0; ni < 4; ni++)
                    mma_bf16(acc[mi][ni], al[mi], bh[ni]);
        }

        // ---- epilogue: fp32 acc + bias -> fp16 gate store ----
        {
            const int r0 = m0 + wm + (lane >> 2);
            const int cb = nt * 128 + wn + (lane & 3) * 2;
            #pragma unroll
            for (int mi = 0; mi < 2; mi++) {
                #pragma unroll
                for (int ni = 0; ni < 4; ni++) {
                    int col = cb + ni * 8;
                    float2 bb = *(const float2*)(smem + SM_BIAS + col * 4);
                    __half2 o0 = __floats2half2_rn(acc[mi][ni][0] + bb.x,
                                                   acc[mi][ni][1] + bb.y);
                    __half2 o1 = __floats2half2_rn(acc[mi][ni][2] + bb.x,
                                                   acc[mi][ni][3] + bb.y);
                    *(__half2*)(C + (size_t)(r0 + mi * 16) * NOUT + col)     = o0;
                    *(__half2*)(C + (size_t)(r0 + mi * 16 + 8) * NOUT + col) = o1;
                }
            }
        }

        // ---- load next B tile (sync: all warps done reading B(nt)) ----
        if (nt < 2) {
            __syncthreads();
            const __nv_bfloat16* bh = Bh + (size_t)(nt + 1) * 128 * 128;
            const __nv_bfloat16* bl = Bl + (size_t)(nt + 1) * 128 * 128;
            #pragma unroll
            for (int it = 0; it < 4; it++) {
                int idx = it * 512 + tid;
                int row = idx >> 4;
                int c = idx & 15;
                uint32_t off = swz(row, c);
                *(uint4*)(smem + SM_B_H + off) = *(const uint4*)(bh + row * 128 + c * 8);
                *(uint4*)(smem + SM_B_L + off) = *(const uint4*)(bl + row * 128 + c * 8);
            }
        }
    }
}

// ---------------- embedding: h = relu(x @ W_emb), K=90, 64 nodes per block ----
__global__ void embed_kernel(const float* __restrict__ x,
                             const float* __restrict__ Wemb) {
    extern __shared__ float sm[];
    float* Ws = sm;               // FEAT*H
    float* xs = sm + FEAT * H;    // 64*FEAT
    const int tid = threadIdx.x;
    for (int i = tid; i < FEAT * H; i += 128) Ws[i] = Wemb[i];
    const int n0 = blockIdx.x * 64;
    for (int i = tid; i < 64 * FEAT; i += 128) {
        int r = i / FEAT, cc = i - r * FEAT;
        int n = n0 + r;
        xs[i] = (n < N_NODES) ? x[(size_t)n * FEAT + cc] : 0.f;
    }
    __syncthreads();
    const int c = tid;
    for (int r = 0; r < 64; r++) {
        float acc = 0.f;
        const float* xr = xs + r * FEAT;
        #pragma unroll 6
        for (int k = 0; k < FEAT; k++) acc = fmaf(xr[k], Ws[k * H + c], acc);
        g_h[(size_t)(n0 + r) * H + c] = fmaxf(acc, 0.f);
    }
}

// ---------------- GRU elementwise (fp16 gates, fast activations) -------------
__global__ void gru_kernel() {
    const int v = blockIdx.x * blockDim.x + threadIdx.x;  // vec4 index, < M_PAD*32
    const int node = v >> 5;
    const int c4 = (v & 31) * 4;
    const size_t gb = (size_t)node * 384 + c4;
    const size_t hb = (size_t)node * 128 + c4;
    const __half2* gx = (const __half2*)(g_gx + gb);
    const __half2* gh = (const __half2*)(g_gh + gb);
    float2 xr0 = __half22float2(gx[0]),      xr1 = __half22float2(gx[1]);
    float2 xz0 = __half22float2(gx[64]),     xz1 = __half22float2(gx[65]);
    float2 xn0 = __half22float2(gx[128]),    xn1 = __half22float2(gx[129]);
    float2 hr0 = __half22float2(gh[0]),      hr1 = __half22float2(gh[1]);
    float2 hz0 = __half22float2(gh[64]),     hz1 = __half22float2(gh[65]);
    float2 hn0 = __half22float2(gh[128]),    hn1 = __half22float2(gh[129]);
    float4 hv = *(const float4*)&g_h[hb];
    float4 o;
    {
        float r = fsigmoid(xr0.x + hr0.x), z = fsigmoid(xz0.x + hz0.x);
        float nn = ftanh(xn0.x + r * hn0.x);
        o.x = (1.f - z) * nn + z * hv.x;
    }
    {
        float r = fsigmoid(xr0.y + hr0.y), z = fsigmoid(xz0.y + hz0.y);
        float nn = ftanh(xn0.y + r * hn0.y);
        o.y = (1.f - z) * nn + z * hv.y;
    }
    {
        float r = fsigmoid(xr1.x + hr1.x), z = fsigmoid(xz1.x + hz1.x);
        float nn = ftanh(xn1.x + r * hn1.x);
        o.z = (1.f - z) * nn + z * hv.z;
    }
    {
        float r = fsigmoid(xr1.y + hr1.y), z = fsigmoid(xz1.y + hz1.y);
        float nn = ftanh(xn1.y + r * hn1.y);
        o.w = (1.f - z) * nn + z * hv.w;
    }
    *(float4*)&g_h[hb] = o;
}

// ---------------- pooling: sum relu(h) per graph (batch sorted) --------------
// 128 nodes per block (391 blocks) for shorter serial runs + better waves.
__global__ void pool_kernel(const int* __restrict__ batch) {
    __shared__ int bs[128];
    const int tid = threadIdx.x;        // 128 threads, one column each
    const int n0 = blockIdx.x * 128;
    const int cnt = min(128, N_NODES - n0);
    if (cnt <= 0) return;
    if (tid < cnt) bs[tid] = batch[n0 + tid];
    __syncthreads();
    const int c = tid;
    float sum = 0.f;
    int cur = bs[0];
    int run = 0;
    for (int i = 0; i < cnt; i++) {
        int b = bs[i];
        if (b != cur) {
            atomicAdd(&g_pool[cur * H + c], sum);
            if (c == 0) atomicAdd(&g_cnt[cur], (float)run);
            sum = 0.f; run = 0; cur = b;
        }
        sum += fmaxf(g_h[(size_t)(n0 + i) * H + c], 0.f);
        run++;
    }
    atomicAdd(&g_pool[cur * H + c], sum);
    if (c == 0) atomicAdd(&g_cnt[cur], (float)run);
}

// ---------------- head: mean -> Linear+ReLU -> Linear -> softplus ------------
__global__ void head_kernel(const float* __restrict__ W1, const float* __restrict__ b1,
                            const float* __restrict__ W2, const float* __restrict__ b2,
                            float* __restrict__ out) {
    __shared__ float ps[H];
    __shared__ float hs[H];
    const int g = blockIdx.x, c = threadIdx.x;
    float cnt = fmaxf(g_cnt[g], 1.f);
    ps[c] = g_pool[g * H + c] / cnt;
    __syncthreads();
    float acc = b1[c];
    #pragma unroll 8
    for (int k = 0; k < H; k++) acc = fmaf(ps[k], W1[k * H + c], acc);
    hs[c] = fmaxf(acc, 0.f) * W2[c];
    __syncthreads();
    for (int s = 64; s > 0; s >>= 1) {
        if (c < s) hs[c] += hs[c + s];
        __syncthreads();
    }
    if (c == 0) {
        float xv = hs[0] + b2[0];
        out[g] = (xv > 0.f) ? (xv + log1pf(expf(-xv))) : log1pf(expf(xv));
    }
}

// ---------------- launch ------------------------------------------------------
extern "C" void kernel_launch(void* const* d_in, const int* in_sizes, int n_in,
                              void* d_out, int out_size) {
    const float* x     = (const float*)d_in[0];
    const int*   ei    = (const int*)d_in[1];
    const int*   batch = (const int*)d_in[2];
    const float* W_emb = (const float*)d_in[3];
    const float* W_msg = (const float*)d_in[4];
    const float* W_ih  = (const float*)d_in[5];
    const float* W_hh  = (const float*)d_in[6];
    const float* b_ih  = (const float*)d_in[7];
    const float* b_hh  = (const float*)d_in[8];
    const float* W1    = (const float*)d_in[9];
    const float* b1    = (const float*)d_in[10];
    const float* W2    = (const float*)d_in[11];
    const float* b2    = (const float*)d_in[12];
    float* out = (float*)d_out;

    float *h_p, *agg_p, *pool_p, *cnt_p;
    __half *gx_p, *gh_p;
    int* deg_p;
    cudaGetSymbolAddress((void**)&h_p,   g_h);
    cudaGetSymbolAddress((void**)&agg_p, g_agg);
    cudaGetSymbolAddress((void**)&gx_p,  g_gx);
    cudaGetSymbolAddress((void**)&gh_p,  g_gh);
    cudaGetSymbolAddress((void**)&pool_p, g_pool);
    cudaGetSymbolAddress((void**)&cnt_p,  g_cnt);
    cudaGetSymbolAddress((void**)&deg_p,  g_deg);

    __nv_bfloat16 *wcomb_h, *wcomb_l, *whh_h, *whh_l;
    cudaGetSymbolAddress((void**)&wcomb_h, g_wcomb_h);
    cudaGetSymbolAddress((void**)&wcomb_l, g_wcomb_l);
    cudaGetSymbolAddress((void**)&whh_h,   g_whh_h);
    cudaGetSymbolAddress((void**)&whh_l,   g_whh_l);

    const int embed_smem = (FEAT * H + 64 * FEAT) * 4;  // 69120 B
    cudaFuncSetAttribute(embed_kernel,
                         cudaFuncAttributeMaxDynamicSharedMemorySize, embed_smem);
    cudaFuncSetAttribute(gemm_mma,
                         cudaFuncAttributeMaxDynamicSharedMemorySize, GEMM_SMEM);

    // side streams + events for capture-safe fork/join
    cudaStream_t s2, s3;
    cudaStreamCreateWithFlags(&s2, cudaStreamNonBlocking);
    cudaStreamCreateWithFlags(&s3, cudaStreamNonBlocking);
    cudaEvent_t evF, evJ, evK;
    cudaEventCreateWithFlags(&evF, cudaEventDisableTiming);
    cudaEventCreateWithFlags(&evJ, cudaEventDisableTiming);
    cudaEventCreateWithFlags(&evK, cudaEventDisableTiming);

    // ---- setup: CSR (stream 0) || weight prep (s2) || embed + pool memsets (s3)
    cudaEventRecord(evF, 0);
    cudaStreamWaitEvent(s2, evF, 0);
    cudaStreamWaitEvent(s3, evF, 0);

    prep_whh<<<(3 * H * H + 255) / 256, 256, 0, s2>>>(W_hh);
    prep_wcomb<<<(STEPS * 3 * H * H + 255) / 256, 256, 0, s2>>>(W_msg, W_ih);
    cudaEventRecord(evJ, s2);

    embed_kernel<<<M_PAD / 64, 128, embed_smem, s3>>>(x, W_emb);
    cudaMemsetAsync(pool_p, 0, N_GRAPHS * H * sizeof(float), s3);
    cudaMemsetAsync(cnt_p, 0, N_GRAPHS * sizeof(float), s3);
    cudaEventRecord(evK, s3);

    cudaMemsetAsync(deg_p, 0, N_NODES * sizeof(int));
    hist_kernel<<<(N_EDGES + 255) / 256, 256>>>(ei);
    scan_local<<<SCAN_BLOCKS, 256>>>();
    scan_bsum<<<1, 256>>>();
    scan_add<<<SCAN_BLOCKS, 256>>>();
    fill_kernel<<<(N_EDGES + 255) / 256, 256>>>(ei);
    cudaStreamWaitEvent(0, evJ, 0);
    cudaStreamWaitEvent(0, evK, 0);

    // ---- steps: gather (0) ∥ gh-GEMM (s2); join; gx-GEMM; gru (R7 schedule) ----
    for (int s = 0; s < STEPS; s++) {
        cudaEventRecord(evF, 0);
        cudaStreamWaitEvent(s2, evF, 0);
        gemm_mma<<<M_TILES, 512, GEMM_SMEM, s2>>>(h_p, whh_h, whh_l, b_hh, gh_p);
        cudaEventRecord(evJ, s2);

        gather_kernel<<<(N_NODES * 32 + 63) / 64, 64>>>();
        gemm_mma<<<M_TILES, 512, GEMM_SMEM>>>(
            agg_p, wcomb_h + (size_t)s * 3 * H * H, wcomb_l + (size_t)s * 3 * H * H,
            b_ih, gx_p);

        cudaStreamWaitEvent(0, evJ, 0);
        gru_kernel<<<(M_PAD * 32) / 256, 256>>>();
    }

    // ---- pooling + head ----
    pool_kernel<<<(N_NODES + 127) / 128, 128>>>(batch);
    head_kernel<<<N_GRAPHS, H>>>(W1, b1, W2, b2, out);

    cudaEventDestroy(evF);
    cudaEventDestroy(evJ);
    cudaEventDestroy(evK);
    cudaStreamDestroy(s2);
    cudaStreamDestroy(s3);
}

// round 17
// speedup vs baseline: 1.3943x; 1.1324x over previous
#include <cuda_runtime.h>
#include <cuda_bf16.h>
#include <cuda_fp16.h>
#include <math.h>
#include <stdint.h>

#define N_NODES  50000
#define N_EDGES  800000
#define FEAT     90
#define H        128
#define STEPS    4
#define N_GRAPHS 100
#define M_PAD    50048   // 128 * 391
#define M_TILES  (M_PAD / 128)
#define NOUT     384
#define SCAN_BLOCKS 196  // 196 * 256 = 50176 >= N_NODES

typedef unsigned long long u64;

// ---------------- device scratch ----------------
__device__ float  g_h  [(size_t)M_PAD * H];
__device__ float  g_agg[(size_t)M_PAD * H];
__device__ __half g_gx [(size_t)M_PAD * 3 * H];   // fp16 gate pre-activations
__device__ __half g_gh [(size_t)M_PAD * 3 * H];
__device__ float  g_pool[N_GRAPHS * H];
__device__ float  g_cnt [N_GRAPHS];

// CSR for gather aggregation
__device__ int g_deg[N_NODES];
__device__ int g_off[N_NODES + 1];
__device__ int g_cur[N_NODES];
__device__ int g_eid[N_EDGES];
__device__ int g_bsum[SCAN_BLOCKS];

// bf16-split, transposed weights, layout [n][k]
__device__ __nv_bfloat16 g_wcomb_h[STEPS * 3 * H * H];  // W_msg[s] @ W_ih
__device__ __nv_bfloat16 g_wcomb_l[STEPS * 3 * H * H];
__device__ __nv_bfloat16 g_whh_h[3 * H * H];
__device__ __nv_bfloat16 g_whh_l[3 * H * H];

// ---------------- PTX helpers ----------------
__device__ __forceinline__ uint32_t smem_u32(const void* p) {
    uint32_t a;
    asm("{ .reg .u64 t; cvta.to.shared.u64 t, %1; cvt.u32.u64 %0, t; }" : "=r"(a) : "l"(p));
    return a;
}

__device__ __forceinline__ void ldsm_x4(uint32_t& r0, uint32_t& r1, uint32_t& r2, uint32_t& r3,
                                        uint32_t addr) {
    asm volatile("ldmatrix.sync.aligned.m8n8.x4.shared.b16 {%0,%1,%2,%3}, [%4];"
                 : "=r"(r0), "=r"(r1), "=r"(r2), "=r"(r3) : "r"(addr));
}

__device__ __forceinline__ void mma_bf16(float* c, const uint32_t* a, const uint32_t* b) {
    asm volatile(
        "mma.sync.aligned.m16n8k16.row.col.f32.bf16.bf16.f32 "
        "{%0,%1,%2,%3}, {%4,%5,%6,%7}, {%8,%9}, {%0,%1,%2,%3};"
        : "+f"(c[0]), "+f"(c[1]), "+f"(c[2]), "+f"(c[3])
        : "r"(a[0]), "r"(a[1]), "r"(a[2]), "r"(a[3]), "r"(b[0]), "r"(b[1]));
}

// swizzled tile offset: row r (0..127), 16B-chunk c (0..15); 256B rows
__device__ __forceinline__ uint32_t swz(int r, int c) {
    return (uint32_t)r * 256 + (uint32_t)((c ^ (r & 7)) << 4);
}

// fast activations (MUFU.EX2-based)
__device__ __forceinline__ float fsigmoid(float x) {
    return __fdividef(1.f, 1.f + __expf(-x));
}
__device__ __forceinline__ float ftanh(float x) {
    float e = __expf(2.f * x);
    return __fdividef(e - 1.f, e + 1.f);
}

// ---------------- CSR build ----------------
__global__ void hist_kernel(const int* __restrict__ ei) {
    int e = blockIdx.x * 256 + threadIdx.x;
    if (e < N_EDGES) atomicAdd(&g_deg[ei[N_EDGES + e]], 1);
}

// pass 1: per-block exclusive scan of deg; write local prefix + block sum
__global__ void scan_local() {
    __shared__ int wsum[8];
    const int tid = threadIdx.x, lane = tid & 31, w = tid >> 5;
    const int i = blockIdx.x * 256 + tid;
    int v = (i < N_NODES) ? g_deg[i] : 0;
    int x = v;
    #pragma unroll
    for (int d = 1; d < 32; d <<= 1) {
        int t = __shfl_up_sync(0xFFFFFFFFu, x, d);
        if (lane >= d) x += t;
    }
    if (lane == 31) wsum[w] = x;
    __syncthreads();
    if (w == 0 && lane < 8) {
        int y = wsum[lane];
        #pragma unroll
        for (int d = 1; d < 8; d <<= 1) {
            int t = __shfl_up_sync(0xFFu, y, d);
            if (lane >= d) y += t;
        }
        wsum[lane] = y;
    }
    __syncthreads();
    int woff = (w == 0) ? 0 : wsum[w - 1];
    if (i < N_NODES) g_off[i] = woff + x - v;       // local exclusive prefix
    if (tid == 255) g_bsum[blockIdx.x] = woff + x;  // block total
}

// pass 2: one block scans the 196 block sums (exclusive, in place)
__global__ void scan_bsum() {
    __shared__ int ws[8];
    const int tid = threadIdx.x, lane = tid & 31, w = tid >> 5;
    int v = (tid < SCAN_BLOCKS) ? g_bsum[tid] : 0;
    int x = v;
    #pragma unroll
    for (int d = 1; d < 32; d <<= 1) {
        int t = __shfl_up_sync(0xFFFFFFFFu, x, d);
        if (lane >= d) x += t;
    }
    if (lane == 31) ws[w] = x;
    __syncthreads();
    if (w == 0 && lane < 8) {
        int y = ws[lane];
        #pragma unroll
        for (int d = 1; d < 8; d <<= 1) {
            int t = __shfl_up_sync(0xFFu, y, d);
            if (lane >= d) y += t;
        }
        ws[lane] = y;
    }
    __syncthreads();
    int woff = (w == 0) ? 0 : ws[w - 1];
    if (tid < SCAN_BLOCKS) g_bsum[tid] = woff + x - v;   // exclusive
    if (tid == 0) g_off[N_NODES] = N_EDGES;
}

// pass 3: add block offsets, init cursor
__global__ void scan_add() {
    const int i = blockIdx.x * 256 + threadIdx.x;
    if (i >= N_NODES) return;
    int o = g_off[i] + g_bsum[blockIdx.x];
    g_off[i] = o;
    g_cur[i] = o;
}

__global__ void fill_kernel(const int* __restrict__ ei) {
    int e = blockIdx.x * 256 + threadIdx.x;
    if (e < N_EDGES) {
        int dst = ei[N_EDGES + e];
        int pos = atomicAdd(&g_cur[dst], 1);
        g_eid[pos] = ei[e];
    }
}

// ---------------- gather: agg[n] = sum_{e: dst=n} h[src[e]] ----------------
// 64-thread blocks (2 warps) for finer load balancing across skewed degrees.
__global__ void gather_kernel() {
    const int node = (blockIdx.x * 64 + threadIdx.x) >> 5;
    if (node >= N_NODES) return;
    const int lane = threadIdx.x & 31;
    const int beg = g_off[node], end = g_off[node + 1];
    float4 acc = make_float4(0.f, 0.f, 0.f, 0.f);
    #pragma unroll 4
    for (int e = beg; e < end; e++) {
        int src = __ldg(&g_eid[e]);
        float4 v = *(const float4*)(g_h + (size_t)src * H + lane * 4);
        acc.x += v.x; acc.y += v.y; acc.z += v.z; acc.w += v.w;
    }
    *(float4*)(g_agg + (size_t)node * H + lane * 4) = acc;
}

// ---------------- weight prep ----------------
__global__ void prep_whh(const float* __restrict__ Whh) {
    int j = blockIdx.x * 256 + threadIdx.x;
    if (j >= 3 * H * H) return;
    int n = j >> 7, k = j & 127;
    float v = Whh[k * 384 + n];
    __nv_bfloat16 hi = __float2bfloat16(v);
    __nv_bfloat16 lo = __float2bfloat16(v - __bfloat162float(hi));
    g_whh_h[j] = hi; g_whh_l[j] = lo;
}

__global__ void prep_wcomb(const float* __restrict__ Wmsg,
                           const float* __restrict__ Wih) {
    int i = blockIdx.x * 256 + threadIdx.x;
    if (i >= STEPS * 3 * H * H) return;
    int s = i / (3 * H * H);
    int r = i % (3 * H * H);
    int k = r / 384;
    int n = r % 384;
    const float* wm = Wmsg + (s << 14) + k * H;
    float acc = 0.f;
    #pragma unroll 8
    for (int j = 0; j < H; j++) acc = fmaf(wm[j], Wih[j * 384 + n], acc);
    __nv_bfloat16 hi = __float2bfloat16(acc);
    __nv_bfloat16 lo = __float2bfloat16(acc - __bfloat162float(hi));
    size_t o = (size_t)s * 3 * H * H + (size_t)n * H + k;
    g_wcomb_h[o] = hi; g_wcomb_l[o] = lo;
}

// ---------------- mma.sync GEMM: C[M_PAD,384] = A[M_PAD,128] @ W[128,384] + b --
// bf16x2: C = Ah*Bh + Ah*Bl (fp32 accum), fp16 output (gate pre-acts).
// A truncated to bf16 (error ~2^-9, attenuated ~1000x by pooling — validated by
// the fp16-gate experiment). 512 thr, warp tile m32 x n32.
#define SM_A    0
#define SM_B_H  32768
#define SM_B_L  65536
#define SM_BIAS 98304
#define GEMM_SMEM (98304 + 1536)

__global__ void __launch_bounds__(512, 1) gemm_mma(
        const float* __restrict__ A,
        const __nv_bfloat16* __restrict__ Bh, const __nv_bfloat16* __restrict__ Bl,
        const float* __restrict__ bias, __half* __restrict__ C) {
    extern __shared__ char smem[];
    const uint32_t sbase = smem_u32(smem);
    const int tid = threadIdx.x;
    const int wid = tid >> 5;
    const int lane = tid & 31;
    const int m0 = blockIdx.x * 128;

    // ---- load A tile (128x128 fp32) -> bf16, swizzled store ----
    {
        const float* Ab = A + (size_t)m0 * 128;
        #pragma unroll
        for (int it = 0; it < 8; it++) {
            int idx = it * 512 + tid;          // 0..4095
            int row = idx >> 5;
            int q = idx & 31;                  // float4 index; k0 = q*4
            float4 v = *(const float4*)(Ab + row * 128 + q * 4);
            __nv_bfloat16 h0 = __float2bfloat16(v.x);
            __nv_bfloat16 h1 = __float2bfloat16(v.y);
            __nv_bfloat16 h2 = __float2bfloat16(v.z);
            __nv_bfloat16 h3 = __float2bfloat16(v.w);
            uint32_t off = swz(row, q >> 1) + (q & 1) * 8;
            uint2 hw;
            hw.x = (uint32_t)__bfloat16_as_ushort(h0) | ((uint32_t)__bfloat16_as_ushort(h1) << 16);
            hw.y = (uint32_t)__bfloat16_as_ushort(h2) | ((uint32_t)__bfloat16_as_ushort(h3) << 16);
            *(uint2*)(smem + SM_A + off) = hw;
        }
    }
    // ---- bias -> smem ----
    for (int i = tid; i < NOUT; i += 512)
        *(float*)(smem + SM_BIAS + i * 4) = bias[i];
    // ---- B tile 0 -> smem (merged with A prologue; one sync covers both) ----
    {
        #pragma unroll
        for (int it = 0; it < 4; it++) {
            int idx = it * 512 + tid;
            int row = idx >> 4;
            int c = idx & 15;
            uint32_t off = swz(row, c);
            *(uint4*)(smem + SM_B_H + off) = *(const uint4*)(Bh + row * 128 + c * 8);
            *(uint4*)(smem + SM_B_L + off) = *(const uint4*)(Bl + row * 128 + c * 8);
        }
    }

    const int wm = (wid & 3) * 32;          // warp row offset
    const int wn = (wid >> 2) * 32;         // warp col offset within tile

    #pragma unroll
    for (int nt = 0; nt < 3; nt++) {
        __syncthreads();   // A/bias/B(nt) visible

        // ---- compute: 8 k-steps, warp tile m32 x n32 ----
        float acc[2][4][4];
        #pragma unroll
        for (int mi = 0; mi < 2; mi++)
            #pragma unroll
            for (int ni = 0; ni < 4; ni++)
                #pragma unroll
                for (int j = 0; j < 4; j++) acc[mi][ni][j] = 0.f;

        #pragma unroll
        for (int ks = 0; ks < 8; ks++) {
            const int c0 = ks * 2;
            uint32_t ah[2][4], bh[4][2], bl[4][2];
            {
                int arow = (lane & 15);
                int ac = c0 + (lane >> 4);
                #pragma unroll
                for (int mi = 0; mi < 2; mi++) {
                    uint32_t o = swz(wm + mi * 16 + arow, ac);
                    ldsm_x4(ah[mi][0], ah[mi][1], ah[mi][2], ah[mi][3], sbase + SM_A + o);
                }
            }
            {
                int brow = ((lane >> 4) << 3) + (lane & 7);
                int bc = c0 + ((lane >> 3) & 1);
                #pragma unroll
                for (int nj = 0; nj < 2; nj++) {
                    uint32_t o = swz(wn + nj * 16 + brow, bc);
                    uint32_t t0, t1, t2, t3;
                    ldsm_x4(t0, t1, t2, t3, sbase + SM_B_H + o);
                    bh[nj * 2][0] = t0; bh[nj * 2][1] = t1;
                    bh[nj * 2 + 1][0] = t2; bh[nj * 2 + 1][1] = t3;
                    ldsm_x4(t0, t1, t2, t3, sbase + SM_B_L + o);
                    bl[nj * 2][0] = t0; bl[nj * 2][1] = t1;
                    bl[nj * 2 + 1][0] = t2; bl[nj * 2 + 1][1] = t3;
                }
            }
            // term-outer ordering: consecutive mmas hit different accumulators
            #pragma unroll
            for (int mi = 0; mi < 2; mi++)
                #pragma unroll
                for (int ni = 0; ni < 4; ni++)
                    mma_bf16(acc[mi][ni], ah[mi], bh[ni]);
            #pragma unroll
            for (int mi = 0; mi < 2; mi++)
                #pragma unroll
                for (int ni = 0; ni < 4; ni++)
                    mma_bf16(acc[mi][ni], ah[mi], bl[ni]);
        }

        // ---- epilogue: fp32 acc + bias -> fp16 gate store ----
        {
            const int r0 = m0 + wm + (lane >> 2);
            const int cb = nt * 128 + wn + (lane & 3) * 2;
            #pragma unroll
            for (int mi = 0; mi < 2; mi++) {
                #pragma unroll
                for (int ni = 0; ni < 4; ni++) {
                    int col = cb + ni * 8;
                    float2 bb = *(const float2*)(smem + SM_BIAS + col * 4);
                    __half2 o0 = __floats2half2_rn(acc[mi][ni][0] + bb.x,
                                                   acc[mi][ni][1] + bb.y);
                    __half2 o1 = __floats2half2_rn(acc[mi][ni][2] + bb.x,
                                                   acc[mi][ni][3] + bb.y);
                    *(__half2*)(C + (size_t)(r0 + mi * 16) * NOUT + col)     = o0;
                    *(__half2*)(C + (size_t)(r0 + mi * 16 + 8) * NOUT + col) = o1;
                }
            }
        }

        // ---- load next B tile (sync: all warps done reading B(nt)) ----
        if (nt < 2) {
            __syncthreads();
            const __nv_bfloat16* bh = Bh + (size_t)(nt + 1) * 128 * 128;
            const __nv_bfloat16* bl = Bl + (size_t)(nt + 1) * 128 * 128;
            #pragma unroll
            for (int it = 0; it < 4; it++) {
                int idx = it * 512 + tid;
                int row = idx >> 4;
                int c = idx & 15;
                uint32_t off = swz(row, c);
                *(uint4*)(smem + SM_B_H + off) = *(const uint4*)(bh + row * 128 + c * 8);
                *(uint4*)(smem + SM_B_L + off) = *(const uint4*)(bl + row * 128 + c * 8);
            }
        }
    }
}

// ---------------- embedding: h = relu(x @ W_emb), K=90, 64 nodes per block ----
__global__ void embed_kernel(const float* __restrict__ x,
                             const float* __restrict__ Wemb) {
    extern __shared__ float sm[];
    float* Ws = sm;               // FEAT*H
    float* xs = sm + FEAT * H;    // 64*FEAT
    const int tid = threadIdx.x;
    for (int i = tid; i < FEAT * H; i += 128) Ws[i] = Wemb[i];
    const int n0 = blockIdx.x * 64;
    for (int i = tid; i < 64 * FEAT; i += 128) {
        int r = i / FEAT, cc = i - r * FEAT;
        int n = n0 + r;
        xs[i] = (n < N_NODES) ? x[(size_t)n * FEAT + cc] : 0.f;
    }
    __syncthreads();
    const int c = tid;
    for (int r = 0; r < 64; r++) {
        float acc = 0.f;
        const float* xr = xs + r * FEAT;
        #pragma unroll 6
        for (int k = 0; k < FEAT; k++) acc = fmaf(xr[k], Ws[k * H + c], acc);
        g_h[(size_t)(n0 + r) * H + c] = fmaxf(acc, 0.f);
    }
}

// ---------------- GRU elementwise (fp16 gates, fast activations) -------------
__global__ void gru_kernel() {
    const int v = blockIdx.x * blockDim.x + threadIdx.x;  // vec4 index, < M_PAD*32
    const int node = v >> 5;
    const int c4 = (v & 31) * 4;
    const size_t gb = (size_t)node * 384 + c4;
    const size_t hb = (size_t)node * 128 + c4;
    const __half2* gx = (const __half2*)(g_gx + gb);
    const __half2* gh = (const __half2*)(g_gh + gb);
    float2 xr0 = __half22float2(gx[0]),      xr1 = __half22float2(gx[1]);
    float2 xz0 = __half22float2(gx[64]),     xz1 = __half22float2(gx[65]);
    float2 xn0 = __half22float2(gx[128]),    xn1 = __half22float2(gx[129]);
    float2 hr0 = __half22float2(gh[0]),      hr1 = __half22float2(gh[1]);
    float2 hz0 = __half22float2(gh[64]),     hz1 = __half22float2(gh[65]);
    float2 hn0 = __half22float2(gh[128]),    hn1 = __half22float2(gh[129]);
    float4 hv = *(const float4*)&g_h[hb];
    float4 o;
    {
        float r = fsigmoid(xr0.x + hr0.x), z = fsigmoid(xz0.x + hz0.x);
        float nn = ftanh(xn0.x + r * hn0.x);
        o.x = (1.f - z) * nn + z * hv.x;
    }
    {
        float r = fsigmoid(xr0.y + hr0.y), z = fsigmoid(xz0.y + hz0.y);
        float nn = ftanh(xn0.y + r * hn0.y);
        o.y = (1.f - z) * nn + z * hv.y;
    }
    {
        float r = fsigmoid(xr1.x + hr1.x), z = fsigmoid(xz1.x + hz1.x);
        float nn = ftanh(xn1.x + r * hn1.x);
        o.z = (1.f - z) * nn + z * hv.z;
    }
    {
        float r = fsigmoid(xr1.y + hr1.y), z = fsigmoid(xz1.y + hz1.y);
        float nn = ftanh(xn1.y + r * hn1.y);
        o.w = (1.f - z) * nn + z * hv.w;
    }
    *(float4*)&g_h[hb] = o;
}

// ---------------- pooling: sum relu(h) per graph (batch sorted) --------------
// 128 nodes per block (391 blocks) for shorter serial runs + better waves.
__global__ void pool_kernel(const int* __restrict__ batch) {
    __shared__ int bs[128];
    const int tid = threadIdx.x;        // 128 threads, one column each
    const int n0 = blockIdx.x * 128;
    const int cnt = min(128, N_NODES - n0);
    if (cnt <= 0) return;
    if (tid < cnt) bs[tid] = batch[n0 + tid];
    __syncthreads();
    const int c = tid;
    float sum = 0.f;
    int cur = bs[0];
    int run = 0;
    for (int i = 0; i < cnt; i++) {
        int b = bs[i];
        if (b != cur) {
            atomicAdd(&g_pool[cur * H + c], sum);
            if (c == 0) atomicAdd(&g_cnt[cur], (float)run);
            sum = 0.f; run = 0; cur = b;
        }
        sum += fmaxf(g_h[(size_t)(n0 + i) * H + c], 0.f);
        run++;
    }
    atomicAdd(&g_pool[cur * H + c], sum);
    if (c == 0) atomicAdd(&g_cnt[cur], (float)run);
}

// ---------------- head: mean -> Linear+ReLU -> Linear -> softplus ------------
__global__ void head_kernel(const float* __restrict__ W1, const float* __restrict__ b1,
                            const float* __restrict__ W2, const float* __restrict__ b2,
                            float* __restrict__ out) {
    __shared__ float ps[H];
    __shared__ float hs[H];
    const int g = blockIdx.x, c = threadIdx.x;
    float cnt = fmaxf(g_cnt[g], 1.f);
    ps[c] = g_pool[g * H + c] / cnt;
    __syncthreads();
    float acc = b1[c];
    #pragma unroll 8
    for (int k = 0; k < H; k++) acc = fmaf(ps[k], W1[k * H + c], acc);
    hs[c] = fmaxf(acc, 0.f) * W2[c];
    __syncthreads();
    for (int s = 64; s > 0; s >>= 1) {
        if (c < s) hs[c] += hs[c + s];
        __syncthreads();
    }
    if (c == 0) {
        float xv = hs[0] + b2[0];
        out[g] = (xv > 0.f) ? (xv + log1pf(expf(-xv))) : log1pf(expf(xv));
    }
}

// ---------------- launch ------------------------------------------------------
extern "C" void kernel_launch(void* const* d_in, const int* in_sizes, int n_in,
                              void* d_out, int out_size) {
    const float* x     = (const float*)d_in[0];
    const int*   ei    = (const int*)d_in[1];
    const int*   batch = (const int*)d_in[2];
    const float* W_emb = (const float*)d_in[3];
    const float* W_msg = (const float*)d_in[4];
    const float* W_ih  = (const float*)d_in[5];
    const float* W_hh  = (const float*)d_in[6];
    const float* b_ih  = (const float*)d_in[7];
    const float* b_hh  = (const float*)d_in[8];
    const float* W1    = (const float*)d_in[9];
    const float* b1    = (const float*)d_in[10];
    const float* W2    = (const float*)d_in[11];
    const float* b2    = (const float*)d_in[12];
    float* out = (float*)d_out;

    float *h_p, *agg_p, *pool_p, *cnt_p;
    __half *gx_p, *gh_p;
    int* deg_p;
    cudaGetSymbolAddress((void**)&h_p,   g_h);
    cudaGetSymbolAddress((void**)&agg_p, g_agg);
    cudaGetSymbolAddress((void**)&gx_p,  g_gx);
    cudaGetSymbolAddress((void**)&gh_p,  g_gh);
    cudaGetSymbolAddress((void**)&pool_p, g_pool);
    cudaGetSymbolAddress((void**)&cnt_p,  g_cnt);
    cudaGetSymbolAddress((void**)&deg_p,  g_deg);

    __nv_bfloat16 *wcomb_h, *wcomb_l, *whh_h, *whh_l;
    cudaGetSymbolAddress((void**)&wcomb_h, g_wcomb_h);
    cudaGetSymbolAddress((void**)&wcomb_l, g_wcomb_l);
    cudaGetSymbolAddress((void**)&whh_h,   g_whh_h);
    cudaGetSymbolAddress((void**)&whh_l,   g_whh_l);

    const int embed_smem = (FEAT * H + 64 * FEAT) * 4;  // 69120 B
    cudaFuncSetAttribute(embed_kernel,
                         cudaFuncAttributeMaxDynamicSharedMemorySize, embed_smem);
    cudaFuncSetAttribute(gemm_mma,
                         cudaFuncAttributeMaxDynamicSharedMemorySize, GEMM_SMEM);

    // side streams + events for capture-safe fork/join
    cudaStream_t s2, s3;
    cudaStreamCreateWithFlags(&s2, cudaStreamNonBlocking);
    cudaStreamCreateWithFlags(&s3, cudaStreamNonBlocking);
    cudaEvent_t evF, evJ, evK;
    cudaEventCreateWithFlags(&evF, cudaEventDisableTiming);
    cudaEventCreateWithFlags(&evJ, cudaEventDisableTiming);
    cudaEventCreateWithFlags(&evK, cudaEventDisableTiming);

    // ---- setup: CSR (stream 0) || weight prep (s2) || embed + pool memsets (s3)
    cudaEventRecord(evF, 0);
    cudaStreamWaitEvent(s2, evF, 0);
    cudaStreamWaitEvent(s3, evF, 0);

    prep_whh<<<(3 * H * H + 255) / 256, 256, 0, s2>>>(W_hh);
    prep_wcomb<<<(STEPS * 3 * H * H + 255) / 256, 256, 0, s2>>>(W_msg, W_ih);
    cudaEventRecord(evJ, s2);

    embed_kernel<<<M_PAD / 64, 128, embed_smem, s3>>>(x, W_emb);
    cudaMemsetAsync(pool_p, 0, N_GRAPHS * H * sizeof(float), s3);
    cudaMemsetAsync(cnt_p, 0, N_GRAPHS * sizeof(float), s3);
    cudaEventRecord(evK, s3);

    cudaMemsetAsync(deg_p, 0, N_NODES * sizeof(int));
    hist_kernel<<<(N_EDGES + 255) / 256, 256>>>(ei);
    scan_local<<<SCAN_BLOCKS, 256>>>();
    scan_bsum<<<1, 256>>>();
    scan_add<<<SCAN_BLOCKS, 256>>>();
    fill_kernel<<<(N_EDGES + 255) / 256, 256>>>(ei);
    cudaStreamWaitEvent(0, evJ, 0);
    cudaStreamWaitEvent(0, evK, 0);

    // ---- steps: gather (0) ∥ gh-GEMM (s2); join; gx-GEMM; gru (R7 schedule) ----
    for (int s = 0; s < STEPS; s++) {
        cudaEventRecord(evF, 0);
        cudaStreamWaitEvent(s2, evF, 0);
        gemm_mma<<<M_TILES, 512, GEMM_SMEM, s2>>>(h_p, whh_h, whh_l, b_hh, gh_p);
        cudaEventRecord(evJ, s2);

        gather_kernel<<<(N_NODES * 32 + 63) / 64, 64>>>();
        gemm_mma<<<M_TILES, 512, GEMM_SMEM>>>(
            agg_p, wcomb_h + (size_t)s * 3 * H * H, wcomb_l + (size_t)s * 3 * H * H,
            b_ih, gx_p);

        cudaStreamWaitEvent(0, evJ, 0);
        gru_kernel<<<(M_PAD * 32) / 256, 256>>>();
    }

    // ---- pooling + head ----
    pool_kernel<<<(N_NODES + 127) / 128, 128>>>(batch);
    head_kernel<<<N_GRAPHS, H>>>(W1, b1, W2, b2, out);

    cudaEventDestroy(evF);
    cudaEventDestroy(evJ);
    cudaEventDestroy(evK);
    cudaStreamDestroy(s2);
    cudaStreamDestroy(s3);
}